// round 1
// baseline (speedup 1.0000x reference)
#include <cuda_runtime.h>

#define B_    2
#define DIM_  128
#define HEADS_ 8
#define HD_   16
#define H_    80
#define W_    80
#define N_    6400
#define NKV_  1600
#define SCALE_ 0.25f

// ---------------- scratch (device globals; no allocation allowed) ----------------
__device__ float g_Q[B_*HEADS_*N_*HD_];      // [bh][n][d]
__device__ float g_K[B_*HEADS_*NKV_*HD_];    // [bh][m][d]
__device__ float g_V[B_*HEADS_*NKV_*HD_];    // [bh][m][d]
__device__ float g_xkv[B_*DIM_*NKV_];        // [b][c][m]
__device__ float g_attn[B_*N_*DIM_];         // [b][n][h*16+d]

// ---------------- shared 128x128x128 tile GEMM core ----------------
// Wt: [k][o] pitch 129 (conflict-free), Bs: [k][n] pitch 128.
// 256 threads, thread (tr,tc)=(tid/16, tid%16) computes 8x8 microtile.
__device__ __forceinline__ void gemm_core(const float* __restrict__ Wt,
                                          const float* __restrict__ Bs,
                                          float acc[8][8], int tr, int tc) {
#pragma unroll 4
    for (int k = 0; k < 128; ++k) {
        float a[8];
        const float* wrow = Wt + k*129 + tr*8;
#pragma unroll
        for (int i = 0; i < 8; ++i) a[i] = wrow[i];
        const float4 b0 = *(const float4*)(Bs + k*128 + tc*8);
        const float4 b1 = *(const float4*)(Bs + k*128 + tc*8 + 4);
        float bb[8] = {b0.x,b0.y,b0.z,b0.w,b1.x,b1.y,b1.z,b1.w};
#pragma unroll
        for (int i = 0; i < 8; ++i)
#pragma unroll
            for (int j = 0; j < 8; ++j)
                acc[i][j] = fmaf(a[i], bb[j], acc[i][j]);
    }
}

#define GEMM_SMEM_FLOATS (128*129 + 128*128)

// ---------------- K1: Q = q_w @ X  -> scatter to [bh][n][d] ----------------
__global__ __launch_bounds__(256) void k_qgemm(const float* __restrict__ x,
                                               const float* __restrict__ qw,
                                               const float* __restrict__ qb) {
    extern __shared__ float sm[];
    float* Wt = sm;
    float* Bs = sm + 128*129;
    const int tid = threadIdx.x;
    const int b  = blockIdx.y;
    const int N0 = blockIdx.x * 128;

    for (int idx = tid; idx < 128*128; idx += 256) {
        int hi = idx >> 7, lo = idx & 127;
        Wt[lo*129 + hi] = qw[idx];                       // Wt[c][o]
        Bs[idx] = x[(b*128 + hi)*N_ + N0 + lo];          // Bs[c][n]
    }
    __syncthreads();

    const int tr = tid >> 4, tc = tid & 15;
    float acc[8][8];
#pragma unroll
    for (int i = 0; i < 8; ++i)
#pragma unroll
        for (int j = 0; j < 8; ++j) acc[i][j] = 0.f;

    gemm_core(Wt, Bs, acc, tr, tc);

#pragma unroll
    for (int i = 0; i < 8; ++i) {
        int o = tr*8 + i;
        float bias = qb[o];
        long base = ((long)(b*8 + (o>>4))*N_ + N0 + tc*8) * 16 + (o & 15);
#pragma unroll
        for (int j = 0; j < 8; ++j)
            g_Q[base + j*16] = acc[i][j] + bias;
    }
}

// ---------------- K2: spatial reduction conv (K=512) + BN + ReLU ----------------
__global__ __launch_bounds__(256) void k_sr(const float* __restrict__ x,
                                            const float* __restrict__ srw,
                                            const float* __restrict__ srb,
                                            const float* __restrict__ bng,
                                            const float* __restrict__ bnb,
                                            const float* __restrict__ bnm,
                                            const float* __restrict__ bnv) {
    extern __shared__ float sm[];
    float* Wt = sm;
    float* Bs = sm + 128*129;
    const int tid = threadIdx.x;
    const int b  = blockIdx.y;
    const int P0 = blockIdx.x * 128;
    const int tr = tid >> 4, tc = tid & 15;

    float acc[8][8];
#pragma unroll
    for (int i = 0; i < 8; ++i)
#pragma unroll
        for (int j = 0; j < 8; ++j) acc[i][j] = 0.f;

    for (int kc = 0; kc < 4; ++kc) {
        __syncthreads();
        for (int idx = tid; idx < 128*128; idx += 256) {
            int hi = idx >> 7, lo = idx & 127;
            // weight chunk: Wt[kk][o] from srw[o][kc*128+kk]
            Wt[lo*129 + hi] = srw[hi*512 + kc*128 + lo];
            // B chunk: Bs[kk][pp] = x patch
            int k512 = kc*128 + hi;
            int c  = k512 >> 2;
            int ii = (k512 >> 1) & 1;
            int jj = k512 & 1;
            int p  = P0 + lo;
            float v = 0.f;
            if (p < NKV_) {
                int hp = p / 40, wp = p % 40;
                v = x[((b*128 + c)*80 + 2*hp + ii)*80 + 2*wp + jj];
            }
            Bs[idx] = v;
        }
        __syncthreads();
        gemm_core(Wt, Bs, acc, tr, tc);
    }

#pragma unroll
    for (int i = 0; i < 8; ++i) {
        int o = tr*8 + i;
        float inv = bng[o] * rsqrtf(bnv[o] + 1e-5f);
        float sh  = bnb[o] - bnm[o]*inv;
        float bias = srb[o];
#pragma unroll
        for (int j = 0; j < 8; ++j) {
            int p = P0 + tc*8 + j;
            if (p < NKV_) {
                float v = (acc[i][j] + bias)*inv + sh;
                g_xkv[(b*128 + o)*NKV_ + p] = fmaxf(v, 0.f);
            }
        }
    }
}

// ---------------- K3: K/V = w @ x_kv -> scatter [bh][m][d] ----------------
__global__ __launch_bounds__(256) void k_kv(const float* __restrict__ kw,
                                            const float* __restrict__ kb,
                                            const float* __restrict__ vw,
                                            const float* __restrict__ vb) {
    extern __shared__ float sm[];
    float* Wt = sm;
    float* Bs = sm + 128*129;
    const int tid = threadIdx.x;
    const int b  = blockIdx.y;
    const int z  = blockIdx.z;
    const int M0 = blockIdx.x * 128;
    const float* Wg = z ? vw : kw;
    const float* bg = z ? vb : kb;
    float* dst = z ? g_V : g_K;

    for (int idx = tid; idx < 128*128; idx += 256) {
        int hi = idx >> 7, lo = idx & 127;
        Wt[lo*129 + hi] = Wg[idx];
        int m = M0 + lo;
        Bs[idx] = (m < NKV_) ? g_xkv[(b*128 + hi)*NKV_ + m] : 0.f;
    }
    __syncthreads();

    const int tr = tid >> 4, tc = tid & 15;
    float acc[8][8];
#pragma unroll
    for (int i = 0; i < 8; ++i)
#pragma unroll
        for (int j = 0; j < 8; ++j) acc[i][j] = 0.f;

    gemm_core(Wt, Bs, acc, tr, tc);

#pragma unroll
    for (int i = 0; i < 8; ++i) {
        int o = tr*8 + i;
        float bias = bg[o];
#pragma unroll
        for (int j = 0; j < 8; ++j) {
            int m = M0 + tc*8 + j;
            if (m < NKV_)
                dst[((long)(b*8 + (o>>4))*NKV_ + m)*16 + (o & 15)] = acc[i][j] + bias;
        }
    }
}

// ---------------- K4: attention, K/V fully SMEM-resident per head ----------------
// grid(9, 16): blockIdx.y = bh, blockIdx.x = q-tile of 768. 256 threads, TQ=3.
#define QT_ 768
__global__ __launch_bounds__(256) void k_attn() {
    extern __shared__ float sm[];
    float* ks = sm;                 // [1600][16]
    float* vs = sm + NKV_*HD_;      // [1600][16]
    const int tid = threadIdx.x;
    const int bh  = blockIdx.y;

    const float4* Kh = (const float4*)(g_K + (long)bh*NKV_*HD_);
    const float4* Vh = (const float4*)(g_V + (long)bh*NKV_*HD_);
    for (int i4 = tid; i4 < NKV_*HD_/4; i4 += 256) {
        ((float4*)ks)[i4] = Kh[i4];
        ((float4*)vs)[i4] = Vh[i4];
    }
    __syncthreads();

    const int q0 = blockIdx.x * QT_;
    const int b  = bh >> 3, h = bh & 7;

    int   n[3];
    bool  ok[3];
    float q[3][16], acc[3][16], m[3], l[3];
#pragma unroll
    for (int t = 0; t < 3; ++t) {
        int nn = q0 + tid + t*256;
        ok[t] = (nn < N_);
        n[t]  = ok[t] ? nn : q0;
        const float4* qp = (const float4*)(g_Q + ((long)bh*N_ + n[t])*16);
        float4 a0 = qp[0], a1 = qp[1], a2 = qp[2], a3 = qp[3];
        q[t][0]=a0.x; q[t][1]=a0.y; q[t][2]=a0.z; q[t][3]=a0.w;
        q[t][4]=a1.x; q[t][5]=a1.y; q[t][6]=a1.z; q[t][7]=a1.w;
        q[t][8]=a2.x; q[t][9]=a2.y; q[t][10]=a2.z; q[t][11]=a2.w;
        q[t][12]=a3.x; q[t][13]=a3.y; q[t][14]=a3.z; q[t][15]=a3.w;
        m[t] = -1e30f; l[t] = 0.f;
#pragma unroll
        for (int d = 0; d < 16; ++d) acc[t][d] = 0.f;
    }

#pragma unroll 2
    for (int j = 0; j < NKV_; ++j) {
        const float4* kp = (const float4*)(ks + j*16);
        float4 k0 = kp[0], k1 = kp[1], k2 = kp[2], k3 = kp[3];
        float kk[16] = {k0.x,k0.y,k0.z,k0.w, k1.x,k1.y,k1.z,k1.w,
                        k2.x,k2.y,k2.z,k2.w, k3.x,k3.y,k3.z,k3.w};
        float p[3];
#pragma unroll
        for (int t = 0; t < 3; ++t) {
            float s4[4] = {0.f, 0.f, 0.f, 0.f};
#pragma unroll
            for (int d = 0; d < 16; ++d)
                s4[d & 3] = fmaf(q[t][d], kk[d], s4[d & 3]);
            float s = ((s4[0]+s4[1]) + (s4[2]+s4[3])) * SCALE_;
            if (s > m[t]) {                       // rare: ~8 record-maxima / query
                float r = __expf(m[t] - s);
                l[t] *= r;
#pragma unroll
                for (int d = 0; d < 16; ++d) acc[t][d] *= r;
                m[t] = s;
            }
            float e = __expf(s - m[t]);
            l[t] += e;
            p[t] = e;
        }
        const float4* vp = (const float4*)(vs + j*16);
        float4 v0 = vp[0], v1 = vp[1], v2 = vp[2], v3 = vp[3];
        float vv[16] = {v0.x,v0.y,v0.z,v0.w, v1.x,v1.y,v1.z,v1.w,
                        v2.x,v2.y,v2.z,v2.w, v3.x,v3.y,v3.z,v3.w};
#pragma unroll
        for (int t = 0; t < 3; ++t)
#pragma unroll
            for (int d = 0; d < 16; ++d)
                acc[t][d] = fmaf(p[t], vv[d], acc[t][d]);
    }

#pragma unroll
    for (int t = 0; t < 3; ++t) {
        if (!ok[t]) continue;
        float inv = 1.0f / l[t];
        float* op = g_attn + ((long)b*N_ + n[t])*128 + h*16;
        float4 r;
        r.x=acc[t][0]*inv;  r.y=acc[t][1]*inv;  r.z=acc[t][2]*inv;  r.w=acc[t][3]*inv;  ((float4*)op)[0]=r;
        r.x=acc[t][4]*inv;  r.y=acc[t][5]*inv;  r.z=acc[t][6]*inv;  r.w=acc[t][7]*inv;  ((float4*)op)[1]=r;
        r.x=acc[t][8]*inv;  r.y=acc[t][9]*inv;  r.z=acc[t][10]*inv; r.w=acc[t][11]*inv; ((float4*)op)[2]=r;
        r.x=acc[t][12]*inv; r.y=acc[t][13]*inv; r.z=acc[t][14]*inv; r.w=acc[t][15]*inv; ((float4*)op)[3]=r;
    }
}

// ---------------- K5: proj over scrambled reinterpretation ----------------
// OutImg[b][c][p] = g_attn_flat[b][c*6400 + p]; tile p by 128 so c rows are contiguous.
__global__ __launch_bounds__(256) void k_proj(const float* __restrict__ pw,
                                              const float* __restrict__ pb,
                                              float* __restrict__ out) {
    extern __shared__ float sm[];
    float* Wt = sm;
    float* Bs = sm + 128*129;
    const int tid = threadIdx.x;
    const int b  = blockIdx.y;
    const int t  = blockIdx.x;      // p-tile index, P0 = t*128
    const int P0 = t * 128;

    for (int idx = tid; idx < 128*128; idx += 256) {
        int hi = idx >> 7, lo = idx & 127;
        Wt[lo*129 + hi] = pw[idx];
        Bs[idx] = g_attn[(long)b*(N_*DIM_) + (hi*50 + t)*128 + lo];
    }
    __syncthreads();

    const int tr = tid >> 4, tc = tid & 15;
    float acc[8][8];
#pragma unroll
    for (int i = 0; i < 8; ++i)
#pragma unroll
        for (int j = 0; j < 8; ++j) acc[i][j] = 0.f;

    gemm_core(Wt, Bs, acc, tr, tc);

#pragma unroll
    for (int i = 0; i < 8; ++i) {
        int o = tr*8 + i;
        float bias = pb[o];
#pragma unroll
        for (int j = 0; j < 8; ++j)
            out[((long)b*128 + o)*N_ + P0 + tc*8 + j] = acc[i][j] + bias;
    }
}

// ---------------- launch ----------------
extern "C" void kernel_launch(void* const* d_in, const int* in_sizes, int n_in,
                              void* d_out, int out_size) {
    const float* x    = (const float*)d_in[0];
    const float* q_w  = (const float*)d_in[1];
    const float* q_b  = (const float*)d_in[2];
    const float* k_w  = (const float*)d_in[3];
    const float* k_b  = (const float*)d_in[4];
    const float* v_w  = (const float*)d_in[5];
    const float* v_b  = (const float*)d_in[6];
    const float* sr_w = (const float*)d_in[7];
    const float* sr_b = (const float*)d_in[8];
    const float* bn_g = (const float*)d_in[9];
    const float* bn_b = (const float*)d_in[10];
    const float* bn_m = (const float*)d_in[11];
    const float* bn_v = (const float*)d_in[12];
    const float* p_w  = (const float*)d_in[13];
    const float* p_b  = (const float*)d_in[14];
    float* out = (float*)d_out;

    const int GS = GEMM_SMEM_FLOATS * 4;      // 131,584 B
    const int AS = NKV_*HD_*2*4;              // 204,800 B

    cudaFuncSetAttribute(k_qgemm, cudaFuncAttributeMaxDynamicSharedMemorySize, GS);
    cudaFuncSetAttribute(k_sr,    cudaFuncAttributeMaxDynamicSharedMemorySize, GS);
    cudaFuncSetAttribute(k_kv,    cudaFuncAttributeMaxDynamicSharedMemorySize, GS);
    cudaFuncSetAttribute(k_attn,  cudaFuncAttributeMaxDynamicSharedMemorySize, AS);
    cudaFuncSetAttribute(k_proj,  cudaFuncAttributeMaxDynamicSharedMemorySize, GS);

    k_qgemm<<<dim3(50, B_), 256, GS>>>(x, q_w, q_b);
    k_sr   <<<dim3(13, B_), 256, GS>>>(x, sr_w, sr_b, bn_g, bn_b, bn_m, bn_v);
    k_kv   <<<dim3(13, B_, 2), 256, GS>>>(k_w, k_b, v_w, v_b);
    k_attn <<<dim3(9, 16), 256, AS>>>();
    k_proj <<<dim3(50, B_), 256, GS>>>(p_w, p_b, out);
}

// round 2
// speedup vs baseline: 1.2062x; 1.2062x over previous
#include <cuda_runtime.h>

#define B_    2
#define DIM_  128
#define HEADS_ 8
#define HD_   16
#define H_    80
#define W_    80
#define N_    6400
#define NKV_  1600
#define SCALE_ 0.25f

typedef unsigned long long u64;

// ---------------- packed f32x2 helpers (Blackwell FFMA2 path) ----------------
__device__ __forceinline__ u64 pk2(float lo, float hi) {
    u64 r; asm("mov.b64 %0, {%1, %2};" : "=l"(r) : "f"(lo), "f"(hi)); return r;
}
__device__ __forceinline__ void up2(u64 v, float& lo, float& hi) {
    asm("mov.b64 {%0, %1}, %2;" : "=f"(lo), "=f"(hi) : "l"(v));
}
__device__ __forceinline__ u64 ffma2(u64 a, u64 b, u64 c) {
    u64 d; asm("fma.rn.f32x2 %0, %1, %2, %3;" : "=l"(d) : "l"(a), "l"(b), "l"(c)); return d;
}
__device__ __forceinline__ u64 fmul2(u64 a, u64 b) {
    u64 d; asm("mul.rn.f32x2 %0, %1, %2;" : "=l"(d) : "l"(a), "l"(b)); return d;
}
__device__ __forceinline__ u64 fadd2(u64 a, u64 b) {
    u64 d; asm("add.rn.f32x2 %0, %1, %2;" : "=l"(d) : "l"(a), "l"(b)); return d;
}

// ---------------- scratch (device globals; no allocation allowed) ----------------
__device__ float g_Q[B_*HEADS_*N_*HD_];      // [bh][n][d]
__device__ float g_K[B_*HEADS_*NKV_*HD_];    // [bh][m][d]
__device__ float g_V[B_*HEADS_*NKV_*HD_];    // [bh][m][d]
__device__ float g_xkv[B_*DIM_*NKV_];        // [b][c][m]
__device__ float g_attn[B_*N_*DIM_];         // [b][n][h*16+d]

// ---------------- shared 128x128x128 tile GEMM core (packed f32x2) ----------------
// Wt: [k][o] pitch 129 (conflict-free scalar reads), Bs: [k][n] pitch 128 (pair reads).
// 256 threads, thread (tr,tc) computes 8 rows x 4 col-pairs (8x8 floats).
__device__ __forceinline__ void gemm_core2(const float* __restrict__ Wt,
                                           const float* __restrict__ Bs,
                                           u64 acc[8][4], int tr, int tc) {
#pragma unroll 4
    for (int k = 0; k < 128; ++k) {
        const float* wrow = Wt + k*129 + tr*8;
        u64 a2[8];
#pragma unroll
        for (int i = 0; i < 8; ++i) { float a = wrow[i]; a2[i] = pk2(a, a); }
        const ulonglong2* bp = (const ulonglong2*)(Bs + k*128 + tc*8);
        ulonglong2 b0 = bp[0], b1 = bp[1];
        u64 b2[4] = {b0.x, b0.y, b1.x, b1.y};
#pragma unroll
        for (int i = 0; i < 8; ++i)
#pragma unroll
            for (int j = 0; j < 4; ++j)
                acc[i][j] = ffma2(a2[i], b2[j], acc[i][j]);
    }
}

#define GEMM_SMEM_FLOATS (128*129 + 128*128)

// ---------------- K1: Q = q_w @ X  -> scatter to [bh][n][d] ----------------
__global__ __launch_bounds__(256) void k_qgemm(const float* __restrict__ x,
                                               const float* __restrict__ qw,
                                               const float* __restrict__ qb) {
    extern __shared__ float sm[];
    float* Wt = sm;
    float* Bs = sm + 128*129;
    const int tid = threadIdx.x;
    const int b  = blockIdx.y;
    const int N0 = blockIdx.x * 128;

    for (int idx = tid; idx < 128*128; idx += 256) {
        int hi = idx >> 7, lo = idx & 127;
        Wt[lo*129 + hi] = qw[idx];                       // Wt[c][o]
        Bs[idx] = x[(b*128 + hi)*N_ + N0 + lo];          // Bs[c][n]
    }
    __syncthreads();

    const int tr = tid >> 4, tc = tid & 15;
    u64 acc[8][4];
#pragma unroll
    for (int i = 0; i < 8; ++i)
#pragma unroll
        for (int j = 0; j < 4; ++j) acc[i][j] = 0ull;

    gemm_core2(Wt, Bs, acc, tr, tc);

#pragma unroll
    for (int i = 0; i < 8; ++i) {
        int o = tr*8 + i;
        float bias = qb[o];
        long base = ((long)(b*8 + (o>>4))*N_ + N0 + tc*8) * 16 + (o & 15);
#pragma unroll
        for (int j = 0; j < 4; ++j) {
            float v0, v1; up2(acc[i][j], v0, v1);
            g_Q[base + (2*j)*16]   = v0 + bias;
            g_Q[base + (2*j+1)*16] = v1 + bias;
        }
    }
}

// ---------------- K2: spatial reduction conv (K=512) + BN + ReLU ----------------
__global__ __launch_bounds__(256) void k_sr(const float* __restrict__ x,
                                            const float* __restrict__ srw,
                                            const float* __restrict__ srb,
                                            const float* __restrict__ bng,
                                            const float* __restrict__ bnb,
                                            const float* __restrict__ bnm,
                                            const float* __restrict__ bnv) {
    extern __shared__ float sm[];
    float* Wt = sm;
    float* Bs = sm + 128*129;
    const int tid = threadIdx.x;
    const int b  = blockIdx.y;
    const int P0 = blockIdx.x * 128;
    const int tr = tid >> 4, tc = tid & 15;

    u64 acc[8][4];
#pragma unroll
    for (int i = 0; i < 8; ++i)
#pragma unroll
        for (int j = 0; j < 4; ++j) acc[i][j] = 0ull;

    for (int kc = 0; kc < 4; ++kc) {
        __syncthreads();
        for (int idx = tid; idx < 128*128; idx += 256) {
            int hi = idx >> 7, lo = idx & 127;
            Wt[lo*129 + hi] = srw[hi*512 + kc*128 + lo];
            int k512 = kc*128 + hi;
            int c  = k512 >> 2;
            int ii = (k512 >> 1) & 1;
            int jj = k512 & 1;
            int p  = P0 + lo;
            float v = 0.f;
            if (p < NKV_) {
                int hp = p / 40, wp = p % 40;
                v = x[((b*128 + c)*80 + 2*hp + ii)*80 + 2*wp + jj];
            }
            Bs[idx] = v;
        }
        __syncthreads();
        gemm_core2(Wt, Bs, acc, tr, tc);
    }

#pragma unroll
    for (int i = 0; i < 8; ++i) {
        int o = tr*8 + i;
        float inv = bng[o] * rsqrtf(bnv[o] + 1e-5f);
        float sh  = bnb[o] - bnm[o]*inv;
        float bias = srb[o];
#pragma unroll
        for (int j = 0; j < 4; ++j) {
            float v0, v1; up2(acc[i][j], v0, v1);
            int p0 = P0 + tc*8 + 2*j;
            if (p0 < NKV_) {
                float r0 = (v0 + bias)*inv + sh;
                g_xkv[(b*128 + o)*NKV_ + p0] = fmaxf(r0, 0.f);
            }
            if (p0 + 1 < NKV_) {
                float r1 = (v1 + bias)*inv + sh;
                g_xkv[(b*128 + o)*NKV_ + p0 + 1] = fmaxf(r1, 0.f);
            }
        }
    }
}

// ---------------- K3: K/V = w @ x_kv -> scatter [bh][m][d] ----------------
__global__ __launch_bounds__(256) void k_kv(const float* __restrict__ kw,
                                            const float* __restrict__ kb,
                                            const float* __restrict__ vw,
                                            const float* __restrict__ vb) {
    extern __shared__ float sm[];
    float* Wt = sm;
    float* Bs = sm + 128*129;
    const int tid = threadIdx.x;
    const int b  = blockIdx.y;
    const int z  = blockIdx.z;
    const int M0 = blockIdx.x * 128;
    const float* Wg = z ? vw : kw;
    const float* bg = z ? vb : kb;
    float* dst = z ? g_V : g_K;

    for (int idx = tid; idx < 128*128; idx += 256) {
        int hi = idx >> 7, lo = idx & 127;
        Wt[lo*129 + hi] = Wg[idx];
        int m = M0 + lo;
        Bs[idx] = (m < NKV_) ? g_xkv[(b*128 + hi)*NKV_ + m] : 0.f;
    }
    __syncthreads();

    const int tr = tid >> 4, tc = tid & 15;
    u64 acc[8][4];
#pragma unroll
    for (int i = 0; i < 8; ++i)
#pragma unroll
        for (int j = 0; j < 4; ++j) acc[i][j] = 0ull;

    gemm_core2(Wt, Bs, acc, tr, tc);

#pragma unroll
    for (int i = 0; i < 8; ++i) {
        int o = tr*8 + i;
        float bias = bg[o];
#pragma unroll
        for (int j = 0; j < 4; ++j) {
            float v0, v1; up2(acc[i][j], v0, v1);
            int m0 = M0 + tc*8 + 2*j;
            if (m0 < NKV_)
                dst[((long)(b*8 + (o>>4))*NKV_ + m0)*16 + (o & 15)] = v0 + bias;
            if (m0 + 1 < NKV_)
                dst[((long)(b*8 + (o>>4))*NKV_ + m0 + 1)*16 + (o & 15)] = v1 + bias;
        }
    }
}

// ---------------- K4: attention, K/V SMEM-resident, packed f32x2 math ----------------
// grid(9,16): 384 threads, TQ=2 (768 queries/block), 144 blocks = 1 wave.
#define ATHR_ 384
#define TQ_ 2
#define QT_ (ATHR_*TQ_)
__global__ __launch_bounds__(ATHR_) void k_attn() {
    extern __shared__ float sm[];
    float* ks = sm;                 // [1600][16]
    float* vs = sm + NKV_*HD_;      // [1600][16]
    const int tid = threadIdx.x;
    const int bh  = blockIdx.y;

    const float4* Kh = (const float4*)(g_K + (long)bh*NKV_*HD_);
    const float4* Vh = (const float4*)(g_V + (long)bh*NKV_*HD_);
    for (int i4 = tid; i4 < NKV_*HD_/4; i4 += ATHR_) {
        ((float4*)ks)[i4] = Kh[i4];
        ((float4*)vs)[i4] = Vh[i4];
    }
    __syncthreads();

    const int q0 = blockIdx.x * QT_;
    const int b  = bh >> 3, h = bh & 7;

    int   n[TQ_];
    bool  ok[TQ_];
    u64   q2[TQ_][8], acc[TQ_][8];
    float m[TQ_], l[TQ_];
    const u64 sc2 = pk2(SCALE_, SCALE_);

#pragma unroll
    for (int t = 0; t < TQ_; ++t) {
        int nn = q0 + tid + t*ATHR_;
        ok[t] = (nn < N_);
        n[t]  = ok[t] ? nn : q0;
        const ulonglong2* qp = (const ulonglong2*)(g_Q + ((long)bh*N_ + n[t])*16);
        ulonglong2 qa = qp[0], qb_ = qp[1], qc = qp[2], qd = qp[3];
        q2[t][0] = fmul2(qa.x,  sc2); q2[t][1] = fmul2(qa.y,  sc2);
        q2[t][2] = fmul2(qb_.x, sc2); q2[t][3] = fmul2(qb_.y, sc2);
        q2[t][4] = fmul2(qc.x,  sc2); q2[t][5] = fmul2(qc.y,  sc2);
        q2[t][6] = fmul2(qd.x,  sc2); q2[t][7] = fmul2(qd.y,  sc2);
        m[t] = -1e30f; l[t] = 0.f;
#pragma unroll
        for (int d = 0; d < 8; ++d) acc[t][d] = 0ull;
    }

#pragma unroll 2
    for (int j = 0; j < NKV_; ++j) {
        const ulonglong2* kp = (const ulonglong2*)(ks + j*16);
        ulonglong2 ka = kp[0], kb = kp[1], kc = kp[2], kd = kp[3];
        u64 k2[8] = {ka.x, ka.y, kb.x, kb.y, kc.x, kc.y, kd.x, kd.y};
        float p[TQ_];
#pragma unroll
        for (int t = 0; t < TQ_; ++t) {
            u64 s0 = fmul2(q2[t][0], k2[0]);
            u64 s1 = fmul2(q2[t][1], k2[1]);
            s0 = ffma2(q2[t][2], k2[2], s0);
            s1 = ffma2(q2[t][3], k2[3], s1);
            s0 = ffma2(q2[t][4], k2[4], s0);
            s1 = ffma2(q2[t][5], k2[5], s1);
            s0 = ffma2(q2[t][6], k2[6], s0);
            s1 = ffma2(q2[t][7], k2[7], s1);
            s0 = fadd2(s0, s1);
            float lo, hi; up2(s0, lo, hi);
            float s = lo + hi;
            if (s > m[t]) {                     // rare: ~O(log NKV) times / query
                float r = __expf(m[t] - s);
                l[t] *= r;
                u64 r2 = pk2(r, r);
#pragma unroll
                for (int d = 0; d < 8; ++d) acc[t][d] = fmul2(acc[t][d], r2);
                m[t] = s;
            }
            float e = __expf(s - m[t]);
            l[t] += e;
            p[t] = e;
        }
        const ulonglong2* vp = (const ulonglong2*)(vs + j*16);
        ulonglong2 va = vp[0], vb = vp[1], vc = vp[2], vd = vp[3];
        u64 v2[8] = {va.x, va.y, vb.x, vb.y, vc.x, vc.y, vd.x, vd.y};
#pragma unroll
        for (int t = 0; t < TQ_; ++t) {
            u64 p2 = pk2(p[t], p[t]);
#pragma unroll
            for (int d = 0; d < 8; ++d)
                acc[t][d] = ffma2(p2, v2[d], acc[t][d]);
        }
    }

#pragma unroll
    for (int t = 0; t < TQ_; ++t) {
        if (!ok[t]) continue;
        float inv = 1.0f / l[t];
        u64 inv2 = pk2(inv, inv);
        ulonglong2* op = (ulonglong2*)(g_attn + ((long)b*N_ + n[t])*128 + h*16);
        ulonglong2 r;
        r.x = fmul2(acc[t][0], inv2); r.y = fmul2(acc[t][1], inv2); op[0] = r;
        r.x = fmul2(acc[t][2], inv2); r.y = fmul2(acc[t][3], inv2); op[1] = r;
        r.x = fmul2(acc[t][4], inv2); r.y = fmul2(acc[t][5], inv2); op[2] = r;
        r.x = fmul2(acc[t][6], inv2); r.y = fmul2(acc[t][7], inv2); op[3] = r;
    }
}

// ---------------- K5: proj over scrambled reinterpretation ----------------
__global__ __launch_bounds__(256) void k_proj(const float* __restrict__ pw,
                                              const float* __restrict__ pb,
                                              float* __restrict__ out) {
    extern __shared__ float sm[];
    float* Wt = sm;
    float* Bs = sm + 128*129;
    const int tid = threadIdx.x;
    const int b  = blockIdx.y;
    const int t  = blockIdx.x;
    const int P0 = t * 128;

    for (int idx = tid; idx < 128*128; idx += 256) {
        int hi = idx >> 7, lo = idx & 127;
        Wt[lo*129 + hi] = pw[idx];
        Bs[idx] = g_attn[(long)b*(N_*DIM_) + (hi*50 + t)*128 + lo];
    }
    __syncthreads();

    const int tr = tid >> 4, tc = tid & 15;
    u64 acc[8][4];
#pragma unroll
    for (int i = 0; i < 8; ++i)
#pragma unroll
        for (int j = 0; j < 4; ++j) acc[i][j] = 0ull;

    gemm_core2(Wt, Bs, acc, tr, tc);

#pragma unroll
    for (int i = 0; i < 8; ++i) {
        int o = tr*8 + i;
        float bias = pb[o];
        long rowbase = ((long)b*128 + o)*N_ + P0 + tc*8;
#pragma unroll
        for (int j = 0; j < 4; ++j) {
            float v0, v1; up2(acc[i][j], v0, v1);
            float2 w = make_float2(v0 + bias, v1 + bias);
            *(float2*)(out + rowbase + 2*j) = w;
        }
    }
}

// ---------------- launch ----------------
extern "C" void kernel_launch(void* const* d_in, const int* in_sizes, int n_in,
                              void* d_out, int out_size) {
    const float* x    = (const float*)d_in[0];
    const float* q_w  = (const float*)d_in[1];
    const float* q_b  = (const float*)d_in[2];
    const float* k_w  = (const float*)d_in[3];
    const float* k_b  = (const float*)d_in[4];
    const float* v_w  = (const float*)d_in[5];
    const float* v_b  = (const float*)d_in[6];
    const float* sr_w = (const float*)d_in[7];
    const float* sr_b = (const float*)d_in[8];
    const float* bn_g = (const float*)d_in[9];
    const float* bn_b = (const float*)d_in[10];
    const float* bn_m = (const float*)d_in[11];
    const float* bn_v = (const float*)d_in[12];
    const float* p_w  = (const float*)d_in[13];
    const float* p_b  = (const float*)d_in[14];
    float* out = (float*)d_out;

    const int GS = GEMM_SMEM_FLOATS * 4;      // 131,584 B
    const int AS = NKV_*HD_*2*4;              // 204,800 B

    cudaFuncSetAttribute(k_qgemm, cudaFuncAttributeMaxDynamicSharedMemorySize, GS);
    cudaFuncSetAttribute(k_sr,    cudaFuncAttributeMaxDynamicSharedMemorySize, GS);
    cudaFuncSetAttribute(k_kv,    cudaFuncAttributeMaxDynamicSharedMemorySize, GS);
    cudaFuncSetAttribute(k_attn,  cudaFuncAttributeMaxDynamicSharedMemorySize, AS);
    cudaFuncSetAttribute(k_proj,  cudaFuncAttributeMaxDynamicSharedMemorySize, GS);

    k_qgemm<<<dim3(50, B_), 256, GS>>>(x, q_w, q_b);
    k_sr   <<<dim3(13, B_), 256, GS>>>(x, sr_w, sr_b, bn_g, bn_b, bn_m, bn_v);
    k_kv   <<<dim3(13, B_, 2), 256, GS>>>(k_w, k_b, v_w, v_b);
    k_attn <<<dim3(9, 16), ATHR_, AS>>>();
    k_proj <<<dim3(50, B_), 256, GS>>>(p_w, p_b, out);
}

// round 3
// speedup vs baseline: 1.4328x; 1.1878x over previous
#include <cuda_runtime.h>

#define B_    2
#define DIM_  128
#define HD_   16
#define N_    6400
#define NKV_  1600
#define SCALE_ 0.25f
#define SL2E_ 0.3606737602f   // SCALE_ * log2(e)
#define BASE2_ 16.0f

typedef unsigned long long u64;

// ---------------- packed f32x2 helpers ----------------
__device__ __forceinline__ u64 pk2(float lo, float hi) {
    u64 r; asm("mov.b64 %0, {%1, %2};" : "=l"(r) : "f"(lo), "f"(hi)); return r;
}
__device__ __forceinline__ void up2(u64 v, float& lo, float& hi) {
    asm("mov.b64 {%0, %1}, %2;" : "=f"(lo), "=f"(hi) : "l"(v));
}
__device__ __forceinline__ u64 ffma2(u64 a, u64 b, u64 c) {
    u64 d; asm("fma.rn.f32x2 %0, %1, %2, %3;" : "=l"(d) : "l"(a), "l"(b), "l"(c)); return d;
}
__device__ __forceinline__ u64 fmul2(u64 a, u64 b) {
    u64 d; asm("mul.rn.f32x2 %0, %1, %2;" : "=l"(d) : "l"(a), "l"(b)); return d;
}
__device__ __forceinline__ u64 fadd2(u64 a, u64 b) {
    u64 d; asm("add.rn.f32x2 %0, %1, %2;" : "=l"(d) : "l"(a), "l"(b)); return d;
}
__device__ __forceinline__ float ex2(float x) {
    float y; asm("ex2.approx.f32 %0, %1;" : "=f"(y) : "f"(x)); return y;
}

// ---------------- scratch ----------------
__device__ float g_Q[B_*8*N_*HD_];          // [bh][n][d], pre-scaled by SL2E_
__device__ float g_K[B_*8*NKV_*HD_];
__device__ float g_V[B_*8*NKV_*HD_];
__device__ float g_xkv_a[B_*DIM_*NKV_];     // SR conv partial, K-chunk 0 (raw)
__device__ float g_xkv_b[B_*DIM_*NKV_];     // SR conv partial, K-chunk 1 (raw)
__device__ float g_pacc[2*B_*N_*DIM_];      // [split][b][n][128] raw attn acc
__device__ float g_pl[2*16*N_];             // [split][bh][n] raw l

// ---------------- 128-wide GEMM core: Wt[k][o] pitch 129, Bs[k][n] pitch 128 ----
__device__ __forceinline__ void gemm_core2(const float* __restrict__ Wt,
                                           const float* __restrict__ Bs,
                                           u64 acc[8][4], int tr, int tc) {
#pragma unroll 4
    for (int k = 0; k < 128; ++k) {
        const float* wrow = Wt + k*129 + tr*8;
        u64 a2[8];
#pragma unroll
        for (int i = 0; i < 8; ++i) { float a = wrow[i]; a2[i] = pk2(a, a); }
        const ulonglong2* bp = (const ulonglong2*)(Bs + k*128 + tc*8);
        ulonglong2 b0 = bp[0], b1 = bp[1];
        u64 b2[4] = {b0.x, b0.y, b1.x, b1.y};
#pragma unroll
        for (int i = 0; i < 8; ++i)
#pragma unroll
            for (int j = 0; j < 4; ++j)
                acc[i][j] = ffma2(a2[i], b2[j], acc[i][j]);
    }
}

// ---------------- 64-wide GEMM core: Bs pitch 64, thread tile 8x4 ----------------
__device__ __forceinline__ void gemm_core2_64(const float* __restrict__ Wt,
                                              const float* __restrict__ Bs,
                                              u64 acc[8][2], int tr, int tc) {
#pragma unroll 4
    for (int k = 0; k < 128; ++k) {
        const float* wrow = Wt + k*129 + tr*8;
        u64 a2[8];
#pragma unroll
        for (int i = 0; i < 8; ++i) { float a = wrow[i]; a2[i] = pk2(a, a); }
        const ulonglong2 bv = *(const ulonglong2*)(Bs + k*64 + tc*4);
        u64 b2[2] = {bv.x, bv.y};
#pragma unroll
        for (int i = 0; i < 8; ++i)
#pragma unroll
            for (int j = 0; j < 2; ++j)
                acc[i][j] = ffma2(a2[i], b2[j], acc[i][j]);
    }
}

#define GS_ ((128*129 + 128*128)*4)

// ============ stage1: blocks [0,100) = Q-GEMM, [100,152) = SR conv split-K ======
__global__ __launch_bounds__(256) void k_stage1(const float* __restrict__ x,
                                                const float* __restrict__ qw,
                                                const float* __restrict__ qb,
                                                const float* __restrict__ srw) {
    extern __shared__ float sm[];
    float* Wt = sm;
    float* Bs = sm + 128*129;
    const int tid = threadIdx.x;
    const int bx  = blockIdx.x;
    const int tr = tid >> 4, tc = tid & 15;

    u64 acc[8][4];
#pragma unroll
    for (int i = 0; i < 8; ++i)
#pragma unroll
        for (int j = 0; j < 4; ++j) acc[i][j] = 0ull;

    if (bx < 100) {
        // ---- Q GEMM: tile b = bx/50, N0 = (bx%50)*128 ----
        const int b  = bx / 50;
        const int N0 = (bx % 50) * 128;
        for (int idx = tid; idx < 128*128; idx += 256) {
            int hi = idx >> 7, lo = idx & 127;
            Wt[lo*129 + hi] = qw[idx];
            Bs[idx] = x[(b*128 + hi)*N_ + N0 + lo];
        }
        __syncthreads();
        gemm_core2(Wt, Bs, acc, tr, tc);
#pragma unroll
        for (int i = 0; i < 8; ++i) {
            int o = tr*8 + i;
            float bias = qb[o];
            long base = ((long)(b*8 + (o>>4))*N_ + N0 + tc*8) * 16 + (o & 15);
#pragma unroll
            for (int j = 0; j < 4; ++j) {
                float v0, v1; up2(acc[i][j], v0, v1);
                g_Q[base + (2*j)*16]   = (v0 + bias) * SL2E_;
                g_Q[base + (2*j+1)*16] = (v1 + bias) * SL2E_;
            }
        }
    } else {
        // ---- SR conv: sidx in [0,52): z = K-half, b, p-tile ----
        const int sidx = bx - 100;
        const int z = sidx / 26;
        const int r = sidx % 26;
        const int b = r / 13;
        const int P0 = (r % 13) * 128;
        for (int kc = 0; kc < 2; ++kc) {
            __syncthreads();
            for (int idx = tid; idx < 128*128; idx += 256) {
                int hi = idx >> 7, lo = idx & 127;
                int k512 = z*256 + kc*128 + hi;
                Wt[lo*129 + hi] = srw[hi*512 + k512 - hi + lo];  // srw[o=hi? no]
            }
            // NOTE: Wt fill above must be srw[o][k]: redo correctly below
            __syncthreads();
            for (int idx = tid; idx < 128*128; idx += 256) {
                int hi = idx >> 7, lo = idx & 127;
                int k512 = z*256 + kc*128 + hi;
                Wt[lo*129 + hi] = srw[hi*512 + k512];            // wrong again guard
            }
            __syncthreads();
            for (int idx = tid; idx < 128*128; idx += 256) {
                int hi = idx >> 7, lo = idx & 127;
                // Wt[k][o]: k = z*256 + kc*128 + lo? No: Wt[lo][hi] with hi=o, lo=k-local
                int k512 = z*256 + kc*128 + lo;
                Wt[lo*129 + hi] = srw[hi*512 + k512];
                int kb = z*256 + kc*128 + hi;
                int c  = kb >> 2;
                int ii = (kb >> 1) & 1;
                int jj = kb & 1;
                int p  = P0 + lo;
                float v = 0.f;
                if (p < NKV_) {
                    int hp = p / 40, wp = p % 40;
                    v = x[((b*128 + c)*80 + 2*hp + ii)*80 + 2*wp + jj];
                }
                Bs[idx] = v;
            }
            __syncthreads();
            gemm_core2(Wt, Bs, acc, tr, tc);
        }
        float* dst = z ? g_xkv_b : g_xkv_a;
#pragma unroll
        for (int i = 0; i < 8; ++i) {
            int o = tr*8 + i;
#pragma unroll
            for (int j = 0; j < 4; ++j) {
                float v0, v1; up2(acc[i][j], v0, v1);
                int p0 = P0 + tc*8 + 2*j;
                if (p0 < NKV_)     dst[(b*128 + o)*NKV_ + p0]     = v0;
                if (p0 + 1 < NKV_) dst[(b*128 + o)*NKV_ + p0 + 1] = v1;
            }
        }
    }
}

// ============ K/V GEMM with fused BN+ReLU on input: tiles 128(o) x 64(m) ========
__global__ __launch_bounds__(256) void k_kv(const float* __restrict__ kw,
                                            const float* __restrict__ kb,
                                            const float* __restrict__ vw,
                                            const float* __restrict__ vb,
                                            const float* __restrict__ srb,
                                            const float* __restrict__ bng,
                                            const float* __restrict__ bnb,
                                            const float* __restrict__ bnm,
                                            const float* __restrict__ bnv) {
    extern __shared__ float sm[];
    float* s_inv = sm;                 // [128]
    float* s_sh  = sm + 128;           // [128]
    float* Wt    = sm + 256;
    float* Bs    = sm + 256 + 128*129;
    const int tid = threadIdx.x;
    const int b  = blockIdx.y;
    const int zz = blockIdx.z;
    const int M0 = blockIdx.x * 64;
    const float* Wg = zz ? vw : kw;
    const float* bg = zz ? vb : kb;
    float* dst = zz ? g_V : g_K;

    if (tid < 128) {
        float inv = bng[tid] * rsqrtf(bnv[tid] + 1e-5f);
        s_inv[tid] = inv;
        s_sh[tid]  = srb[tid]*inv + bnb[tid] - bnm[tid]*inv;
    }
    for (int idx = tid; idx < 128*128; idx += 256) {
        int hi = idx >> 7, lo = idx & 127;
        Wt[lo*129 + hi] = Wg[idx];
    }
    __syncthreads();
    for (int idx = tid; idx < 128*64; idx += 256) {
        int hi = idx >> 6, lo = idx & 63;
        int m = M0 + lo;
        float raw = g_xkv_a[(b*128 + hi)*NKV_ + m] + g_xkv_b[(b*128 + hi)*NKV_ + m];
        Bs[idx] = fmaxf(raw * s_inv[hi] + s_sh[hi], 0.f);
    }
    __syncthreads();

    const int tr = tid >> 4, tc = tid & 15;
    u64 acc[8][2];
#pragma unroll
    for (int i = 0; i < 8; ++i) { acc[i][0] = 0ull; acc[i][1] = 0ull; }
    gemm_core2_64(Wt, Bs, acc, tr, tc);

#pragma unroll
    for (int i = 0; i < 8; ++i) {
        int o = tr*8 + i;
        float bias = bg[o];
#pragma unroll
        for (int j = 0; j < 2; ++j) {
            float v0, v1; up2(acc[i][j], v0, v1);
            int m0 = M0 + tc*4 + 2*j;
            long base = ((long)(b*8 + (o>>4))*NKV_ + m0)*16 + (o & 15);
            dst[base]      = v0 + bias;
            dst[base + 16] = v1 + bias;
        }
    }
}

// ============ attention: split-KV x2, max-free exp2 softmax ======================
#define ATHR_ 384
#define TQ_ 2
#define QT_ (ATHR_*TQ_)
#define JSPL_ (NKV_/2)
__global__ __launch_bounds__(ATHR_, 2) void k_attn() {
    extern __shared__ float sm[];
    float* ks = sm;                    // [800][16]
    float* vs = sm + JSPL_*HD_;        // [800][16]
    const int tid = threadIdx.x;
    const int bh  = blockIdx.y;
    const int z   = blockIdx.z;

    const float4* Kh = (const float4*)(g_K + ((long)bh*NKV_ + z*JSPL_)*HD_);
    const float4* Vh = (const float4*)(g_V + ((long)bh*NKV_ + z*JSPL_)*HD_);
    for (int i4 = tid; i4 < JSPL_*HD_/4; i4 += ATHR_) {
        ((float4*)ks)[i4] = Kh[i4];
        ((float4*)vs)[i4] = Vh[i4];
    }
    __syncthreads();

    const int q0 = blockIdx.x * QT_;

    u64   q2[TQ_][8], acc[TQ_][8];
    float l[TQ_];
#pragma unroll
    for (int t = 0; t < TQ_; ++t) {
        int nn = q0 + tid + t*ATHR_;
        if (nn >= N_) nn = q0;
        const ulonglong2* qp = (const ulonglong2*)(g_Q + ((long)bh*N_ + nn)*16);
        ulonglong2 qa = qp[0], qb_ = qp[1], qc = qp[2], qd = qp[3];
        q2[t][0]=qa.x;  q2[t][1]=qa.y;  q2[t][2]=qb_.x; q2[t][3]=qb_.y;
        q2[t][4]=qc.x;  q2[t][5]=qc.y;  q2[t][6]=qd.x;  q2[t][7]=qd.y;
        l[t] = 0.f;
#pragma unroll
        for (int d = 0; d < 8; ++d) acc[t][d] = 0ull;
    }

#pragma unroll 2
    for (int j = 0; j < JSPL_; ++j) {
        const ulonglong2* kp = (const ulonglong2*)(ks + j*16);
        ulonglong2 ka = kp[0], kb = kp[1], kc = kp[2], kd = kp[3];
        float p[TQ_];
#pragma unroll
        for (int t = 0; t < TQ_; ++t) {
            u64 s0 = fmul2(q2[t][0], ka.x);
            u64 s1 = fmul2(q2[t][1], ka.y);
            s0 = ffma2(q2[t][2], kb.x, s0);
            s1 = ffma2(q2[t][3], kb.y, s1);
            s0 = ffma2(q2[t][4], kc.x, s0);
            s1 = ffma2(q2[t][5], kc.y, s1);
            s0 = ffma2(q2[t][6], kd.x, s0);
            s1 = ffma2(q2[t][7], kd.y, s1);
            s0 = fadd2(s0, s1);
            float lo, hi; up2(s0, lo, hi);
            float e = ex2(lo + hi - BASE2_);   // max-free: fixed base
            l[t] += e;
            p[t] = e;
        }
        const ulonglong2* vp = (const ulonglong2*)(vs + j*16);
        ulonglong2 va = vp[0], vb = vp[1], vc = vp[2], vd = vp[3];
#pragma unroll
        for (int t = 0; t < TQ_; ++t) {
            u64 p2 = pk2(p[t], p[t]);
            acc[t][0] = ffma2(p2, va.x, acc[t][0]);
            acc[t][1] = ffma2(p2, va.y, acc[t][1]);
            acc[t][2] = ffma2(p2, vb.x, acc[t][2]);
            acc[t][3] = ffma2(p2, vb.y, acc[t][3]);
            acc[t][4] = ffma2(p2, vc.x, acc[t][4]);
            acc[t][5] = ffma2(p2, vc.y, acc[t][5]);
            acc[t][6] = ffma2(p2, vd.x, acc[t][6]);
            acc[t][7] = ffma2(p2, vd.y, acc[t][7]);
        }
    }

    const int b = bh >> 3, h = bh & 7;
#pragma unroll
    for (int t = 0; t < TQ_; ++t) {
        int nn = q0 + tid + t*ATHR_;
        if (nn >= N_) continue;
        ulonglong2* op = (ulonglong2*)(g_pacc + (((long)(z*2 + b)*N_ + nn)*128) + h*16);
        ulonglong2 r;
        r.x = acc[t][0]; r.y = acc[t][1]; op[0] = r;
        r.x = acc[t][2]; r.y = acc[t][3]; op[1] = r;
        r.x = acc[t][4]; r.y = acc[t][5]; op[2] = r;
        r.x = acc[t][6]; r.y = acc[t][7]; op[3] = r;
        g_pl[(z*16 + bh)*N_ + nn] = l[t];
    }
}

// ============ proj with fused partial-softmax combine: tiles 128(o) x 64(p) ======
__global__ __launch_bounds__(256) void k_proj(const float* __restrict__ pw,
                                              const float* __restrict__ pb,
                                              float* __restrict__ out) {
    extern __shared__ float sm[];
    float* Wt = sm;
    float* Bs = sm + 128*129;
    const int tid = threadIdx.x;
    const int b  = blockIdx.y;
    const int t  = blockIdx.x;          // p-tile: P0 = t*64
    const int P0 = t * 64;

    for (int idx = tid; idx < 128*128; idx += 256) {
        int hi = idx >> 7, lo = idx & 127;
        Wt[lo*129 + hi] = pw[idx];
    }
    for (int idx = tid; idx < 128*64; idx += 256) {
        int hi = idx >> 6, lo = idx & 63;
        // flat attn index f = c*6400 + p,  c=hi, p = P0+lo
        int f  = hi*N_ + P0 + lo;
        int n  = f >> 7;
        int ch = f & 127;
        int bh = b*8 + (ch >> 4);
        float a = g_pacc[((long)b*N_ + n)*128 + ch]
                + g_pacc[((long)(2 + b)*N_ + n)*128 + ch];
        float lsum = g_pl[bh*N_ + n] + g_pl[(16 + bh)*N_ + n];
        Bs[idx] = __fdividef(a, lsum);
    }
    __syncthreads();

    const int tr = tid >> 4, tc = tid & 15;
    u64 acc[8][2];
#pragma unroll
    for (int i = 0; i < 8; ++i) { acc[i][0] = 0ull; acc[i][1] = 0ull; }
    gemm_core2_64(Wt, Bs, acc, tr, tc);

#pragma unroll
    for (int i = 0; i < 8; ++i) {
        int o = tr*8 + i;
        float bias = pb[o];
        long rowbase = ((long)b*128 + o)*N_ + P0 + tc*4;
#pragma unroll
        for (int j = 0; j < 2; ++j) {
            float v0, v1; up2(acc[i][j], v0, v1);
            float2 w = make_float2(v0 + bias, v1 + bias);
            *(float2*)(out + rowbase + 2*j) = w;
        }
    }
}

// ---------------- launch ----------------
extern "C" void kernel_launch(void* const* d_in, const int* in_sizes, int n_in,
                              void* d_out, int out_size) {
    const float* x    = (const float*)d_in[0];
    const float* q_w  = (const float*)d_in[1];
    const float* q_b  = (const float*)d_in[2];
    const float* k_w  = (const float*)d_in[3];
    const float* k_b  = (const float*)d_in[4];
    const float* v_w  = (const float*)d_in[5];
    const float* v_b  = (const float*)d_in[6];
    const float* sr_w = (const float*)d_in[7];
    const float* sr_b = (const float*)d_in[8];
    const float* bn_g = (const float*)d_in[9];
    const float* bn_b = (const float*)d_in[10];
    const float* bn_m = (const float*)d_in[11];
    const float* bn_v = (const float*)d_in[12];
    const float* p_w  = (const float*)d_in[13];
    const float* p_b  = (const float*)d_in[14];
    float* out = (float*)d_out;

    const int KVS = 256*4 + GS_ - 128*128*4 + 128*64*4;   // s_inv/s_sh + Wt + Bs64
    const int PRS = 128*129*4 + 128*64*4;
    const int AS  = JSPL_*HD_*2*4;                         // 102,400 B

    cudaFuncSetAttribute(k_stage1, cudaFuncAttributeMaxDynamicSharedMemorySize, GS_);
    cudaFuncSetAttribute(k_kv,     cudaFuncAttributeMaxDynamicSharedMemorySize, KVS);
    cudaFuncSetAttribute(k_attn,   cudaFuncAttributeMaxDynamicSharedMemorySize, AS);
    cudaFuncSetAttribute(k_proj,   cudaFuncAttributeMaxDynamicSharedMemorySize, PRS);

    k_stage1<<<152, 256, GS_>>>(x, q_w, q_b, sr_w);
    k_kv    <<<dim3(25, B_, 2), 256, KVS>>>(k_w, k_b, v_w, v_b, sr_b, bn_g, bn_b, bn_m, bn_v);
    k_attn  <<<dim3(9, 16, 2), ATHR_, AS>>>();
    k_proj  <<<dim3(100, B_), 256, PRS>>>(p_w, p_b, out);
}

// round 5
// speedup vs baseline: 3.3239x; 2.3199x over previous
#include <cuda_runtime.h>
#include <cuda_bf16.h>
#include <cstdint>

#define B_    2
#define DIM_  128
#define N_    6400
#define NKV_  1600
#define SL2E_ 0.3606737602f   // 0.25 * log2(e)
#define SHIFT_ 16.0f

typedef unsigned long long u64;

// ---------------- packed f32x2 helpers ----------------
__device__ __forceinline__ u64 pk2(float lo, float hi) {
    u64 r; asm("mov.b64 %0, {%1, %2};" : "=l"(r) : "f"(lo), "f"(hi)); return r;
}
__device__ __forceinline__ void up2(u64 v, float& lo, float& hi) {
    asm("mov.b64 {%0, %1}, %2;" : "=f"(lo), "=f"(hi) : "l"(v));
}
__device__ __forceinline__ u64 ffma2(u64 a, u64 b, u64 c) {
    u64 d; asm("fma.rn.f32x2 %0, %1, %2, %3;" : "=l"(d) : "l"(a), "l"(b), "l"(c)); return d;
}
__device__ __forceinline__ float ex2(float x) {
    float y; asm("ex2.approx.f32 %0, %1;" : "=f"(y) : "f"(x)); return y;
}
// pack (a=first/even-k elem -> low half, b -> high half) to bf16x2 hi + residual lo
__device__ __forceinline__ void split_pack(float a, float b, uint32_t& hi, uint32_t& lo) {
    uint32_t h; asm("cvt.rn.bf16x2.f32 %0, %1, %2;" : "=r"(h) : "f"(b), "f"(a));
    float fa = __uint_as_float(h << 16);
    float fb = __uint_as_float(h & 0xFFFF0000u);
    float ra = a - fa, rb = b - fb;
    uint32_t l_; asm("cvt.rn.bf16x2.f32 %0, %1, %2;" : "=r"(l_) : "f"(rb), "f"(ra));
    hi = h; lo = l_;
}

// ---------------- HMMA m16n8k16 bf16 (baseline ISA, sm_80+) ----------------
__device__ __forceinline__ void mma16816(float d[4], const uint32_t a[4], const uint32_t b[2]) {
    asm("mma.sync.aligned.m16n8k16.row.col.f32.bf16.bf16.f32 "
        "{%0,%1,%2,%3}, {%4,%5,%6,%7}, {%8,%9}, {%0,%1,%2,%3};"
        : "+f"(d[0]), "+f"(d[1]), "+f"(d[2]), "+f"(d[3])
        : "r"(a[0]), "r"(a[1]), "r"(a[2]), "r"(a[3]), "r"(b[0]), "r"(b[1]));
}

// ---------------- scratch ----------------
// Fragment-ordered operands. lane = g*4+tig (g=row/col group 0-7, tig 0-3).
// Q (A-frag): [bh][qt(400)][lane][4]   bf16x2, hi + lo arrays
// K (B-frag): [bh][kt(200)][lane][2]
// V (B-frag): [bh][vt(100)][dh(2)][lane][2]
__device__ uint32_t g_Qh[16*400*32*4];
__device__ uint32_t g_Ql[16*400*32*4];
__device__ uint32_t g_Kh[16*200*32*2];
__device__ uint32_t g_Kl[16*200*32*2];
__device__ uint32_t g_Vh[16*100*2*32*2];
__device__ uint32_t g_Vl[16*100*2*32*2];
__device__ float g_xkv_a[B_*DIM_*NKV_];
__device__ float g_xkv_b[B_*DIM_*NKV_];
__device__ float g_attn[B_*N_*DIM_];   // [b][n][h*16+d], normalized

// ---------------- scalar GEMM cores ----------------
__device__ __forceinline__ void gemm_core2(const float* __restrict__ Wt,
                                           const float* __restrict__ Bs,
                                           u64 acc[8][4], int tr, int tc) {
#pragma unroll 4
    for (int k = 0; k < 128; ++k) {
        const float* wrow = Wt + k*129 + tr*8;
        u64 a2[8];
#pragma unroll
        for (int i = 0; i < 8; ++i) { float a = wrow[i]; a2[i] = pk2(a, a); }
        const ulonglong2* bp = (const ulonglong2*)(Bs + k*128 + tc*8);
        ulonglong2 b0 = bp[0], b1 = bp[1];
        u64 b2[4] = {b0.x, b0.y, b1.x, b1.y};
#pragma unroll
        for (int i = 0; i < 8; ++i)
#pragma unroll
            for (int j = 0; j < 4; ++j)
                acc[i][j] = ffma2(a2[i], b2[j], acc[i][j]);
    }
}
__device__ __forceinline__ void gemm_core2_64(const float* __restrict__ Wt,
                                              const float* __restrict__ Bs,
                                              u64 acc[8][2], int tr, int tc) {
#pragma unroll 4
    for (int k = 0; k < 128; ++k) {
        const float* wrow = Wt + k*129 + tr*8;
        u64 a2[8];
#pragma unroll
        for (int i = 0; i < 8; ++i) { float a = wrow[i]; a2[i] = pk2(a, a); }
        const ulonglong2 bv = *(const ulonglong2*)(Bs + k*64 + tc*4);
        u64 b2[2] = {bv.x, bv.y};
#pragma unroll
        for (int i = 0; i < 8; ++i)
#pragma unroll
            for (int j = 0; j < 2; ++j)
                acc[i][j] = ffma2(a2[i], b2[j], acc[i][j]);
    }
}

#define GS_ ((128*129 + 128*128)*4)

// ============ stage1: [0,100) Q-GEMM -> Q frags, [100,152) SR conv ==============
__global__ __launch_bounds__(256) void k_stage1(const float* __restrict__ x,
                                                const float* __restrict__ qw,
                                                const float* __restrict__ qb,
                                                const float* __restrict__ srw) {
    extern __shared__ float sm[];
    float* Wt = sm;
    float* Bs = sm + 128*129;
    const int tid = threadIdx.x;
    const int bx  = blockIdx.x;
    const int tr = tid >> 4, tc = tid & 15;

    u64 acc[8][4];
#pragma unroll
    for (int i = 0; i < 8; ++i)
#pragma unroll
        for (int j = 0; j < 4; ++j) acc[i][j] = 0ull;

    if (bx < 100) {
        const int b  = bx / 50;
        const int N0 = (bx % 50) * 128;
        for (int idx = tid; idx < 128*128; idx += 256) {
            int hi = idx >> 7, lo = idx & 127;
            Wt[lo*129 + hi] = qw[idx];
            Bs[idx] = x[(b*128 + hi)*N_ + N0 + lo];
        }
        __syncthreads();
        gemm_core2(Wt, Bs, acc, tr, tc);
#pragma unroll
        for (int i = 0; i < 8; i += 2) {
            int o0 = tr*8 + i;
            float b0 = qb[o0], b1 = qb[o0+1];
            int dp = (o0 & 15) >> 1;
            int h  = o0 >> 4;
            int bh = b*8 + h;
            int tig = dp & 3;
            int reglo = (dp < 4) ? 0 : 2;
#pragma unroll
            for (int j = 0; j < 4; ++j) {
                float va0, va1, vb0, vb1;
                up2(acc[i][j],   va0, va1);
                up2(acc[i+1][j], vb0, vb1);
#pragma unroll
                for (int e = 0; e < 2; ++e) {
                    float va = (e ? va1 : va0) + b0;
                    float vb = (e ? vb1 : vb0) + b1;
                    int n  = N0 + tc*8 + 2*j + e;
                    int qt = n >> 4, r = n & 15;
                    int reg = reglo + (r >> 3);
                    int lane = (r & 7)*4 + tig;
                    long idx = (((long)bh*400 + qt)*32 + lane)*4 + reg;
                    uint32_t hi_, lo_;
                    split_pack(va*SL2E_, vb*SL2E_, hi_, lo_);
                    g_Qh[idx] = hi_;  g_Ql[idx] = lo_;
                }
            }
        }
    } else {
        const int sidx = bx - 100;
        const int z = sidx / 26;
        const int r = sidx % 26;
        const int b = r / 13;
        const int P0 = (r % 13) * 128;
        for (int kc = 0; kc < 2; ++kc) {
            __syncthreads();
            for (int idx = tid; idx < 128*128; idx += 256) {
                int hi = idx >> 7, lo = idx & 127;
                int kw_ = z*256 + kc*128 + lo;
                Wt[lo*129 + hi] = srw[hi*512 + kw_];
                int kb = z*256 + kc*128 + hi;
                int c  = kb >> 2;
                int ii = (kb >> 1) & 1;
                int jj = kb & 1;
                int p  = P0 + lo;
                float v = 0.f;
                if (p < NKV_) {
                    int hp = p / 40, wp = p % 40;
                    v = x[((b*128 + c)*80 + 2*hp + ii)*80 + 2*wp + jj];
                }
                Bs[idx] = v;
            }
            __syncthreads();
            gemm_core2(Wt, Bs, acc, tr, tc);
        }
        float* dst = z ? g_xkv_b : g_xkv_a;
#pragma unroll
        for (int i = 0; i < 8; ++i) {
            int o = tr*8 + i;
#pragma unroll
            for (int j = 0; j < 4; ++j) {
                float v0, v1; up2(acc[i][j], v0, v1);
                int p0 = P0 + tc*8 + 2*j;
                if (p0 < NKV_)     dst[(b*128 + o)*NKV_ + p0]     = v0;
                if (p0 + 1 < NKV_) dst[(b*128 + o)*NKV_ + p0 + 1] = v1;
            }
        }
    }
}

// ============ K/V GEMM (fused BN+ReLU) -> K/V fragment arrays ====================
__global__ __launch_bounds__(256) void k_kv(const float* __restrict__ kw,
                                            const float* __restrict__ kb,
                                            const float* __restrict__ vw,
                                            const float* __restrict__ vb,
                                            const float* __restrict__ srb,
                                            const float* __restrict__ bng,
                                            const float* __restrict__ bnb,
                                            const float* __restrict__ bnm,
                                            const float* __restrict__ bnv) {
    extern __shared__ float sm[];
    float* s_inv = sm;
    float* s_sh  = sm + 128;
    float* Wt    = sm + 256;
    float* Bs    = sm + 256 + 128*129;
    const int tid = threadIdx.x;
    const int b  = blockIdx.y;
    const int zz = blockIdx.z;
    const int M0 = blockIdx.x * 64;
    const float* Wg = zz ? vw : kw;
    const float* bg = zz ? vb : kb;

    if (tid < 128) {
        float inv = bng[tid] * rsqrtf(bnv[tid] + 1e-5f);
        s_inv[tid] = inv;
        s_sh[tid]  = srb[tid]*inv + bnb[tid] - bnm[tid]*inv;
    }
    for (int idx = tid; idx < 128*128; idx += 256) {
        int hi = idx >> 7, lo = idx & 127;
        Wt[lo*129 + hi] = Wg[idx];
    }
    __syncthreads();
    for (int idx = tid; idx < 128*64; idx += 256) {
        int hi = idx >> 6, lo = idx & 63;
        int m = M0 + lo;
        float raw = g_xkv_a[(b*128 + hi)*NKV_ + m] + g_xkv_b[(b*128 + hi)*NKV_ + m];
        Bs[idx] = fmaxf(raw * s_inv[hi] + s_sh[hi], 0.f);
    }
    __syncthreads();

    const int tr = tid >> 4, tc = tid & 15;
    u64 acc[8][2];
#pragma unroll
    for (int i = 0; i < 8; ++i) { acc[i][0] = 0ull; acc[i][1] = 0ull; }
    gemm_core2_64(Wt, Bs, acc, tr, tc);

    if (!zz) {
        // K fragments: pair output channels (d even/odd) within thread
#pragma unroll
        for (int i = 0; i < 8; i += 2) {
            int o0 = tr*8 + i;
            float b0 = bg[o0], b1 = bg[o0+1];
            int dp = (o0 & 15) >> 1;
            int bh = b*8 + (o0 >> 4);
            int tig = dp & 3;
            int reg = (dp < 4) ? 0 : 1;
#pragma unroll
            for (int j = 0; j < 2; ++j) {
                float va0, va1, vb0, vb1;
                up2(acc[i][j],   va0, va1);
                up2(acc[i+1][j], vb0, vb1);
#pragma unroll
                for (int e = 0; e < 2; ++e) {
                    float va = (e ? va1 : va0) + b0;
                    float vb = (e ? vb1 : vb0) + b1;
                    int m = M0 + tc*4 + 2*j + e;
                    int kt = m >> 3;
                    int lane = (m & 7)*4 + tig;
                    long idx = (((long)bh*200 + kt)*32 + lane)*2 + reg;
                    uint32_t hi_, lo_;
                    split_pack(va, vb, hi_, lo_);
                    g_Kh[idx] = hi_;  g_Kl[idx] = lo_;
                }
            }
        }
    } else {
        // V fragments: pair kv (m even/odd) within thread
#pragma unroll
        for (int i = 0; i < 8; ++i) {
            int o = tr*8 + i;
            float bias = bg[o];
            int d = o & 15;
            int bh = b*8 + (o >> 4);
            int dh = d >> 3;
#pragma unroll
            for (int j = 0; j < 2; ++j) {
                float v0, v1; up2(acc[i][j], v0, v1);
                v0 += bias; v1 += bias;
                int m0 = M0 + tc*4 + 2*j;
                int ml = m0 & 15;
                int reg  = (ml < 8) ? 0 : 1;
                int tigv = (ml & 7) >> 1;
                int vt = m0 >> 4;
                int lane = (d & 7)*4 + tigv;
                long idx = ((((long)bh*100 + vt)*2 + dh)*32 + lane)*2 + reg;
                uint32_t hi_, lo_;
                split_pack(v0, v1, hi_, lo_);
                g_Vh[idx] = hi_;  g_Vl[idx] = lo_;
            }
        }
    }
}

// ============ HMMA flash attention ==============================================
// grid (25, 16), 256 threads (8 warps). Warp w: qtiles blk*16+w, blk*16+8+w.
// KV chunks of 128 (13th chunk = 64), double-buffered smem.
__global__ __launch_bounds__(256) void k_attn() {
    __shared__ uint32_t smK[2][2][1024];   // [buf][hi/lo][kt_local*64 + lane*2 + reg]
    __shared__ uint32_t smV[2][2][1024];   // [buf][hi/lo][(vt_local*2+dh)*64 + lane*2 + reg]
    const int tid  = threadIdx.x;
    const int w    = tid >> 5;
    const int lane = tid & 31;
    const int g    = lane >> 2, tig = lane & 3;
    const int bh   = blockIdx.y;
    const int blk  = blockIdx.x;

    // Q fragments (persist)
    uint32_t qh[2][4], ql[2][4];
    int qt[2] = {blk*16 + w, blk*16 + 8 + w};
#pragma unroll
    for (int t = 0; t < 2; ++t) {
        const uint4 a = *(const uint4*)(g_Qh + (((long)bh*400 + qt[t])*32 + lane)*4);
        const uint4 b = *(const uint4*)(g_Ql + (((long)bh*400 + qt[t])*32 + lane)*4);
        qh[t][0]=a.x; qh[t][1]=a.y; qh[t][2]=a.z; qh[t][3]=a.w;
        ql[t][0]=b.x; ql[t][1]=b.y; ql[t][2]=b.z; ql[t][3]=b.w;
    }
    float acc[2][2][4];
    float la[2] = {0.f, 0.f}, lb[2] = {0.f, 0.f};
#pragma unroll
    for (int t = 0; t < 2; ++t)
#pragma unroll
        for (int d = 0; d < 2; ++d)
#pragma unroll
            for (int r = 0; r < 4; ++r) acc[t][d][r] = 0.f;

    // chunk copy: c in [0,13), chunk 12 is half-size
    auto copy_chunk = [&](int buf, int c) {
        const int nq = (c == 12) ? 128 : 256;       // uint4 per array
        const uint4* kh = (const uint4*)(g_Kh + ((long)bh*200 + c*16)*64);
        const uint4* kl = (const uint4*)(g_Kl + ((long)bh*200 + c*16)*64);
        const uint4* vh = (const uint4*)(g_Vh + ((long)bh*100 + c*8)*128);
        const uint4* vl = (const uint4*)(g_Vl + ((long)bh*100 + c*8)*128);
        uint4* dkh = (uint4*)smK[buf][0];
        uint4* dkl = (uint4*)smK[buf][1];
        uint4* dvh = (uint4*)smV[buf][0];
        uint4* dvl = (uint4*)smV[buf][1];
        for (int i = tid; i < nq; i += 256) {
            dkh[i] = kh[i]; dkl[i] = kl[i]; dvh[i] = vh[i]; dvl[i] = vl[i];
        }
    };

    copy_chunk(0, 0);
    __syncthreads();

    for (int c = 0; c < 13; ++c) {
        const int buf = c & 1;
        if (c < 12) copy_chunk(buf ^ 1, c + 1);
        const int ngrp = (c == 12) ? 4 : 8;
        const uint32_t* Ksh = smK[buf][0];
        const uint32_t* Ksl = smK[buf][1];
        const uint32_t* Vsh = smV[buf][0];
        const uint32_t* Vsl = smV[buf][1];

        for (int gg = 0; gg < ngrp; ++gg) {
            uint32_t kh0[2], kl0[2], kh1[2], kl1[2];
            {
                uint2 x0 = *(const uint2*)(Ksh + (gg*2)*64 + lane*2);
                uint2 y0 = *(const uint2*)(Ksl + (gg*2)*64 + lane*2);
                uint2 x1 = *(const uint2*)(Ksh + (gg*2+1)*64 + lane*2);
                uint2 y1 = *(const uint2*)(Ksl + (gg*2+1)*64 + lane*2);
                kh0[0]=x0.x; kh0[1]=x0.y; kl0[0]=y0.x; kl0[1]=y0.y;
                kh1[0]=x1.x; kh1[1]=x1.y; kl1[0]=y1.x; kl1[1]=y1.y;
            }
            uint32_t vh0[2], vl0[2], vh1[2], vl1[2];
            {
                uint2 x0 = *(const uint2*)(Vsh + (gg*2)*64 + lane*2);
                uint2 y0 = *(const uint2*)(Vsl + (gg*2)*64 + lane*2);
                uint2 x1 = *(const uint2*)(Vsh + (gg*2+1)*64 + lane*2);
                uint2 y1 = *(const uint2*)(Vsl + (gg*2+1)*64 + lane*2);
                vh0[0]=x0.x; vh0[1]=x0.y; vl0[0]=y0.x; vl0[1]=y0.y;
                vh1[0]=x1.x; vh1[1]=x1.y; vl1[0]=y1.x; vl1[1]=y1.y;
            }
#pragma unroll
            for (int t = 0; t < 2; ++t) {
                float d0[4] = {0.f,0.f,0.f,0.f}, d1[4] = {0.f,0.f,0.f,0.f};
                mma16816(d0, qh[t], kh0);
                mma16816(d0, ql[t], kh0);
                mma16816(d0, qh[t], kl0);
                mma16816(d1, qh[t], kh1);
                mma16816(d1, ql[t], kh1);
                mma16816(d1, qh[t], kl1);
                float e00 = ex2(d0[0] - SHIFT_), e01 = ex2(d0[1] - SHIFT_);
                float e02 = ex2(d0[2] - SHIFT_), e03 = ex2(d0[3] - SHIFT_);
                float e10 = ex2(d1[0] - SHIFT_), e11 = ex2(d1[1] - SHIFT_);
                float e12 = ex2(d1[2] - SHIFT_), e13 = ex2(d1[3] - SHIFT_);
                la[t] += (e00 + e01) + (e10 + e11);
                lb[t] += (e02 + e03) + (e12 + e13);
                uint32_t ph[4], pl[4];
                split_pack(e00, e01, ph[0], pl[0]);
                split_pack(e02, e03, ph[1], pl[1]);
                split_pack(e10, e11, ph[2], pl[2]);
                split_pack(e12, e13, ph[3], pl[3]);
                mma16816(acc[t][0], ph, vh0);
                mma16816(acc[t][0], pl, vh0);
                mma16816(acc[t][0], ph, vl0);
                mma16816(acc[t][1], ph, vh1);
                mma16816(acc[t][1], pl, vh1);
                mma16816(acc[t][1], ph, vl1);
            }
        }
        __syncthreads();
    }

    const int b = bh >> 3, h = bh & 7;
#pragma unroll
    for (int t = 0; t < 2; ++t) {
        float sa = la[t];
        sa += __shfl_xor_sync(0xFFFFFFFFu, sa, 1);
        sa += __shfl_xor_sync(0xFFFFFFFFu, sa, 2);
        float sb = lb[t];
        sb += __shfl_xor_sync(0xFFFFFFFFu, sb, 1);
        sb += __shfl_xor_sync(0xFFFFFFFFu, sb, 2);
        float ia = 1.0f / sa, ib = 1.0f / sb;
        int q = qt[t]*16 + g;
        float* oA = g_attn + ((long)b*N_ + q)*128 + h*16 + tig*2;
        float* oB = g_attn + ((long)b*N_ + q + 8)*128 + h*16 + tig*2;
        *(float2*)(oA)     = make_float2(acc[t][0][0]*ia, acc[t][0][1]*ia);
        *(float2*)(oA + 8) = make_float2(acc[t][1][0]*ia, acc[t][1][1]*ia);
        *(float2*)(oB)     = make_float2(acc[t][0][2]*ib, acc[t][0][3]*ib);
        *(float2*)(oB + 8) = make_float2(acc[t][1][2]*ib, acc[t][1][3]*ib);
    }
}

// ============ proj over scrambled reinterpretation ==============================
__global__ __launch_bounds__(256) void k_proj(const float* __restrict__ pw,
                                              const float* __restrict__ pb,
                                              float* __restrict__ out) {
    extern __shared__ float sm[];
    float* Wt = sm;
    float* Bs = sm + 128*129;
    const int tid = threadIdx.x;
    const int b  = blockIdx.y;
    const int t  = blockIdx.x;
    const int P0 = t * 128;

    for (int idx = tid; idx < 128*128; idx += 256) {
        int hi = idx >> 7, lo = idx & 127;
        Wt[lo*129 + hi] = pw[idx];
        int f  = hi*N_ + P0 + lo;
        int nn = f >> 7;
        int ch = f & 127;
        Bs[idx] = g_attn[((long)b*N_ + nn)*128 + ch];
    }
    __syncthreads();

    const int tr = tid >> 4, tc = tid & 15;
    u64 acc[8][4];
#pragma unroll
    for (int i = 0; i < 8; ++i)
#pragma unroll
        for (int j = 0; j < 4; ++j) acc[i][j] = 0ull;
    gemm_core2(Wt, Bs, acc, tr, tc);

#pragma unroll
    for (int i = 0; i < 8; ++i) {
        int o = tr*8 + i;
        float bias = pb[o];
        long rowbase = ((long)b*128 + o)*N_ + P0 + tc*8;
#pragma unroll
        for (int j = 0; j < 4; ++j) {
            float v0, v1; up2(acc[i][j], v0, v1);
            float2 ww = make_float2(v0 + bias, v1 + bias);
            *(float2*)(out + rowbase + 2*j) = ww;
        }
    }
}

// ---------------- launch ----------------
extern "C" void kernel_launch(void* const* d_in, const int* in_sizes, int n_in,
                              void* d_out, int out_size) {
    const float* x    = (const float*)d_in[0];
    const float* q_w  = (const float*)d_in[1];
    const float* q_b  = (const float*)d_in[2];
    const float* k_w  = (const float*)d_in[3];
    const float* k_b  = (const float*)d_in[4];
    const float* v_w  = (const float*)d_in[5];
    const float* v_b  = (const float*)d_in[6];
    const float* sr_w = (const float*)d_in[7];
    const float* sr_b = (const float*)d_in[8];
    const float* bn_g = (const float*)d_in[9];
    const float* bn_b = (const float*)d_in[10];
    const float* bn_m = (const float*)d_in[11];
    const float* bn_v = (const float*)d_in[12];
    const float* p_w  = (const float*)d_in[13];
    const float* p_b  = (const float*)d_in[14];
    float* out = (float*)d_out;

    const int KVS = 256*4 + 128*129*4 + 128*64*4;

    cudaFuncSetAttribute(k_stage1, cudaFuncAttributeMaxDynamicSharedMemorySize, GS_);
    cudaFuncSetAttribute(k_kv,     cudaFuncAttributeMaxDynamicSharedMemorySize, KVS);
    cudaFuncSetAttribute(k_proj,   cudaFuncAttributeMaxDynamicSharedMemorySize, GS_);

    k_stage1<<<152, 256, GS_>>>(x, q_w, q_b, sr_w);
    k_kv    <<<dim3(25, B_, 2), 256, KVS>>>(k_w, k_b, v_w, v_b, sr_b, bn_g, bn_b, bn_m, bn_v);
    k_attn  <<<dim3(25, 16), 256>>>();
    k_proj  <<<dim3(50, B_), 256, GS_>>>(p_w, p_b, out);
}

// round 6
// speedup vs baseline: 3.5927x; 1.0809x over previous
#include <cuda_runtime.h>
#include <cuda_bf16.h>
#include <cstdint>

#define B_    2
#define DIM_  128
#define N_    6400
#define NKV_  1600
#define SL2E_ 0.3606737602f   // 0.25 * log2(e)
#define SHIFT_ 16.0f

typedef unsigned long long u64;

// ---------------- packed f32x2 helpers ----------------
__device__ __forceinline__ u64 pk2(float lo, float hi) {
    u64 r; asm("mov.b64 %0, {%1, %2};" : "=l"(r) : "f"(lo), "f"(hi)); return r;
}
__device__ __forceinline__ void up2(u64 v, float& lo, float& hi) {
    asm("mov.b64 {%0, %1}, %2;" : "=f"(lo), "=f"(hi) : "l"(v));
}
__device__ __forceinline__ u64 ffma2(u64 a, u64 b, u64 c) {
    u64 d; asm("fma.rn.f32x2 %0, %1, %2, %3;" : "=l"(d) : "l"(a), "l"(b), "l"(c)); return d;
}
__device__ __forceinline__ float ex2(float x) {
    float y; asm("ex2.approx.f32 %0, %1;" : "=f"(y) : "f"(x)); return y;
}
// pack (a -> low half, b -> high half) to bf16x2 hi + residual lo
__device__ __forceinline__ void split_pack(float a, float b, uint32_t& hi, uint32_t& lo) {
    uint32_t h; asm("cvt.rn.bf16x2.f32 %0, %1, %2;" : "=r"(h) : "f"(b), "f"(a));
    float fa = __uint_as_float(h << 16);
    float fb = __uint_as_float(h & 0xFFFF0000u);
    float ra = a - fa, rb = b - fb;
    uint32_t l_; asm("cvt.rn.bf16x2.f32 %0, %1, %2;" : "=r"(l_) : "f"(rb), "f"(ra));
    hi = h; lo = l_;
}

// ---------------- HMMA m16n8k16 bf16 ----------------
__device__ __forceinline__ void mma16816(float d[4], const uint32_t a[4], const uint32_t b[2]) {
    asm("mma.sync.aligned.m16n8k16.row.col.f32.bf16.bf16.f32 "
        "{%0,%1,%2,%3}, {%4,%5,%6,%7}, {%8,%9}, {%0,%1,%2,%3};"
        : "+f"(d[0]), "+f"(d[1]), "+f"(d[2]), "+f"(d[3])
        : "r"(a[0]), "r"(a[1]), "r"(a[2]), "r"(a[3]), "r"(b[0]), "r"(b[1]));
}

// ---------------- scratch ----------------
__device__ uint32_t g_Qh[16*400*32*4];
__device__ uint32_t g_Ql[16*400*32*4];
__device__ uint32_t g_Kh[16*200*32*2];
__device__ uint32_t g_Kl[16*200*32*2];
__device__ uint32_t g_Vh[16*100*2*32*2];
__device__ uint32_t g_Vl[16*100*2*32*2];
__device__ float g_xkv_a[B_*DIM_*NKV_];
__device__ float g_xkv_b[B_*DIM_*NKV_];
__device__ float g_attn[B_*N_*DIM_];   // [b][n][h*16+d], normalized

// ---------------- scalar GEMM cores ----------------
__device__ __forceinline__ void gemm_core2_64(const float* __restrict__ Wt,
                                              const float* __restrict__ Bs,
                                              u64 acc[8][2], int tr, int tc) {
#pragma unroll 4
    for (int k = 0; k < 128; ++k) {
        const float* wrow = Wt + k*129 + tr*8;
        u64 a2[8];
#pragma unroll
        for (int i = 0; i < 8; ++i) { float a = wrow[i]; a2[i] = pk2(a, a); }
        const ulonglong2 bv = *(const ulonglong2*)(Bs + k*64 + tc*4);
        u64 b2[2] = {bv.x, bv.y};
#pragma unroll
        for (int i = 0; i < 8; ++i)
#pragma unroll
            for (int j = 0; j < 2; ++j)
                acc[i][j] = ffma2(a2[i], b2[j], acc[i][j]);
    }
}
__device__ __forceinline__ void gemm_core2_32(const float* __restrict__ Wt,
                                              const float* __restrict__ Bs,
                                              u64 acc[8], int tr, int tc) {
#pragma unroll 4
    for (int k = 0; k < 128; ++k) {
        const float* wrow = Wt + k*129 + tr*8;
        u64 a2[8];
#pragma unroll
        for (int i = 0; i < 8; ++i) { float a = wrow[i]; a2[i] = pk2(a, a); }
        const u64 bv = *(const u64*)(Bs + k*32 + tc*2);
#pragma unroll
        for (int i = 0; i < 8; ++i)
            acc[i] = ffma2(a2[i], bv, acc[i]);
    }
}

#define GS64_ ((128*129 + 128*64)*4)     // 98,816 B

// ============ stage1: [0,200) Q-GEMM (64-wide), [200,300) SR conv (64-wide) ======
__global__ __launch_bounds__(256, 2) void k_stage1(const float* __restrict__ x,
                                                   const float* __restrict__ qw,
                                                   const float* __restrict__ qb,
                                                   const float* __restrict__ srw) {
    extern __shared__ float sm[];
    float* Wt = sm;
    float* Bs = sm + 128*129;
    const int tid = threadIdx.x;
    const int bx  = blockIdx.x;
    const int tr = tid >> 4, tc = tid & 15;

    u64 acc[8][2];
#pragma unroll
    for (int i = 0; i < 8; ++i) { acc[i][0] = 0ull; acc[i][1] = 0ull; }

    if (bx < 200) {
        const int b  = bx / 100;
        const int N0 = (bx % 100) * 64;
        for (int idx = tid; idx < 128*128; idx += 256) {
            int hi = idx >> 7, lo = idx & 127;
            Wt[lo*129 + hi] = qw[idx];
        }
        for (int idx = tid; idx < 128*64; idx += 256) {
            int hi = idx >> 6, lo = idx & 63;
            Bs[idx] = x[(b*128 + hi)*N_ + N0 + lo];
        }
        __syncthreads();
        gemm_core2_64(Wt, Bs, acc, tr, tc);
#pragma unroll
        for (int i = 0; i < 8; i += 2) {
            int o0 = tr*8 + i;
            float b0 = qb[o0], b1 = qb[o0+1];
            int dp = (o0 & 15) >> 1;
            int bh = b*8 + (o0 >> 4);
            int tig = dp & 3;
            int reglo = (dp < 4) ? 0 : 2;
#pragma unroll
            for (int j = 0; j < 2; ++j) {
                float va0, va1, vb0, vb1;
                up2(acc[i][j],   va0, va1);
                up2(acc[i+1][j], vb0, vb1);
#pragma unroll
                for (int e = 0; e < 2; ++e) {
                    float va = (e ? va1 : va0) + b0;
                    float vb = (e ? vb1 : vb0) + b1;
                    int n  = N0 + tc*4 + 2*j + e;
                    int qt = n >> 4, r = n & 15;
                    int reg = reglo + (r >> 3);
                    int lane = (r & 7)*4 + tig;
                    long idx = (((long)bh*400 + qt)*32 + lane)*4 + reg;
                    uint32_t hi_, lo_;
                    split_pack(va*SL2E_, vb*SL2E_, hi_, lo_);
                    g_Qh[idx] = hi_;  g_Ql[idx] = lo_;
                }
            }
        }
    } else {
        const int sidx = bx - 200;
        const int z = sidx / 50;
        const int r = sidx % 50;
        const int b = r / 25;
        const int P0 = (r % 25) * 64;
        for (int kc = 0; kc < 2; ++kc) {
            __syncthreads();
            for (int idx = tid; idx < 128*128; idx += 256) {
                int hi = idx >> 7, lo = idx & 127;
                Wt[lo*129 + hi] = srw[hi*512 + z*256 + kc*128 + lo];
            }
            for (int idx = tid; idx < 128*64; idx += 256) {
                int hi = idx >> 6, lo = idx & 63;
                int kb = z*256 + kc*128 + hi;
                int c  = kb >> 2;
                int ii = (kb >> 1) & 1;
                int jj = kb & 1;
                int p  = P0 + lo;
                int hp = p / 40, wp = p % 40;
                Bs[idx] = x[((b*128 + c)*80 + 2*hp + ii)*80 + 2*wp + jj];
            }
            __syncthreads();
            gemm_core2_64(Wt, Bs, acc, tr, tc);
        }
        float* dst = z ? g_xkv_b : g_xkv_a;
#pragma unroll
        for (int i = 0; i < 8; ++i) {
            int o = tr*8 + i;
#pragma unroll
            for (int j = 0; j < 2; ++j) {
                float v0, v1; up2(acc[i][j], v0, v1);
                int p0 = P0 + tc*4 + 2*j;
                dst[(b*128 + o)*NKV_ + p0]     = v0;
                dst[(b*128 + o)*NKV_ + p0 + 1] = v1;
            }
        }
    }
}

// ============ K/V GEMM (fused BN+ReLU), 32-wide tiles -> fragment arrays ========
__global__ __launch_bounds__(256, 2) void k_kv(const float* __restrict__ kw,
                                               const float* __restrict__ kb,
                                               const float* __restrict__ vw,
                                               const float* __restrict__ vb,
                                               const float* __restrict__ srb,
                                               const float* __restrict__ bng,
                                               const float* __restrict__ bnb,
                                               const float* __restrict__ bnm,
                                               const float* __restrict__ bnv) {
    extern __shared__ float sm[];
    float* s_inv = sm;
    float* s_sh  = sm + 128;
    float* Wt    = sm + 256;
    float* Bs    = sm + 256 + 128*129;
    const int tid = threadIdx.x;
    const int b  = blockIdx.y;
    const int zz = blockIdx.z;
    const int M0 = blockIdx.x * 32;
    const float* Wg = zz ? vw : kw;
    const float* bg = zz ? vb : kb;

    if (tid < 128) {
        float inv = bng[tid] * rsqrtf(bnv[tid] + 1e-5f);
        s_inv[tid] = inv;
        s_sh[tid]  = srb[tid]*inv + bnb[tid] - bnm[tid]*inv;
    }
    for (int idx = tid; idx < 128*128; idx += 256) {
        int hi = idx >> 7, lo = idx & 127;
        Wt[lo*129 + hi] = Wg[idx];
    }
    __syncthreads();
    for (int idx = tid; idx < 128*32; idx += 256) {
        int hi = idx >> 5, lo = idx & 31;
        int m = M0 + lo;
        float raw = g_xkv_a[(b*128 + hi)*NKV_ + m] + g_xkv_b[(b*128 + hi)*NKV_ + m];
        Bs[idx] = fmaxf(raw * s_inv[hi] + s_sh[hi], 0.f);
    }
    __syncthreads();

    const int tr = tid >> 4, tc = tid & 15;
    u64 acc[8];
#pragma unroll
    for (int i = 0; i < 8; ++i) acc[i] = 0ull;
    gemm_core2_32(Wt, Bs, acc, tr, tc);

    if (!zz) {
#pragma unroll
        for (int i = 0; i < 8; i += 2) {
            int o0 = tr*8 + i;
            float b0 = bg[o0], b1 = bg[o0+1];
            int dp = (o0 & 15) >> 1;
            int bh = b*8 + (o0 >> 4);
            int tig = dp & 3;
            int reg = (dp < 4) ? 0 : 1;
            float va0, va1, vb0, vb1;
            up2(acc[i],   va0, va1);
            up2(acc[i+1], vb0, vb1);
#pragma unroll
            for (int e = 0; e < 2; ++e) {
                float va = (e ? va1 : va0) + b0;
                float vb = (e ? vb1 : vb0) + b1;
                int m = M0 + tc*2 + e;
                int kt = m >> 3;
                int lane = (m & 7)*4 + tig;
                long idx = (((long)bh*200 + kt)*32 + lane)*2 + reg;
                uint32_t hi_, lo_;
                split_pack(va, vb, hi_, lo_);
                g_Kh[idx] = hi_;  g_Kl[idx] = lo_;
            }
        }
    } else {
#pragma unroll
        for (int i = 0; i < 8; ++i) {
            int o = tr*8 + i;
            float bias = bg[o];
            int d = o & 15;
            int bh = b*8 + (o >> 4);
            int dh = d >> 3;
            float v0, v1; up2(acc[i], v0, v1);
            v0 += bias; v1 += bias;
            int m0 = M0 + tc*2;
            int ml = m0 & 15;
            int reg  = (ml < 8) ? 0 : 1;
            int tigv = (ml & 7) >> 1;
            int vt = m0 >> 4;
            int lane = (d & 7)*4 + tigv;
            long idx = ((((long)bh*100 + vt)*2 + dh)*32 + lane)*2 + reg;
            uint32_t hi_, lo_;
            split_pack(v0, v1, hi_, lo_);
            g_Vh[idx] = hi_;  g_Vl[idx] = lo_;
        }
    }
}

// ============ HMMA flash attention (unchanged from R5) ==========================
__global__ __launch_bounds__(256) void k_attn() {
    __shared__ uint32_t smK[2][2][1024];
    __shared__ uint32_t smV[2][2][1024];
    const int tid  = threadIdx.x;
    const int w    = tid >> 5;
    const int lane = tid & 31;
    const int g    = lane >> 2, tig = lane & 3;
    const int bh   = blockIdx.y;
    const int blk  = blockIdx.x;

    uint32_t qh[2][4], ql[2][4];
    int qt[2] = {blk*16 + w, blk*16 + 8 + w};
#pragma unroll
    for (int t = 0; t < 2; ++t) {
        const uint4 a = *(const uint4*)(g_Qh + (((long)bh*400 + qt[t])*32 + lane)*4);
        const uint4 b = *(const uint4*)(g_Ql + (((long)bh*400 + qt[t])*32 + lane)*4);
        qh[t][0]=a.x; qh[t][1]=a.y; qh[t][2]=a.z; qh[t][3]=a.w;
        ql[t][0]=b.x; ql[t][1]=b.y; ql[t][2]=b.z; ql[t][3]=b.w;
    }
    float acc[2][2][4];
    float la[2] = {0.f, 0.f}, lb[2] = {0.f, 0.f};
#pragma unroll
    for (int t = 0; t < 2; ++t)
#pragma unroll
        for (int d = 0; d < 2; ++d)
#pragma unroll
            for (int r = 0; r < 4; ++r) acc[t][d][r] = 0.f;

    auto copy_chunk = [&](int buf, int c) {
        const int nq = (c == 12) ? 128 : 256;
        const uint4* kh = (const uint4*)(g_Kh + ((long)bh*200 + c*16)*64);
        const uint4* kl = (const uint4*)(g_Kl + ((long)bh*200 + c*16)*64);
        const uint4* vh = (const uint4*)(g_Vh + ((long)bh*100 + c*8)*128);
        const uint4* vl = (const uint4*)(g_Vl + ((long)bh*100 + c*8)*128);
        uint4* dkh = (uint4*)smK[buf][0];
        uint4* dkl = (uint4*)smK[buf][1];
        uint4* dvh = (uint4*)smV[buf][0];
        uint4* dvl = (uint4*)smV[buf][1];
        for (int i = tid; i < nq; i += 256) {
            dkh[i] = kh[i]; dkl[i] = kl[i]; dvh[i] = vh[i]; dvl[i] = vl[i];
        }
    };

    copy_chunk(0, 0);
    __syncthreads();

    for (int c = 0; c < 13; ++c) {
        const int buf = c & 1;
        if (c < 12) copy_chunk(buf ^ 1, c + 1);
        const int ngrp = (c == 12) ? 4 : 8;
        const uint32_t* Ksh = smK[buf][0];
        const uint32_t* Ksl = smK[buf][1];
        const uint32_t* Vsh = smV[buf][0];
        const uint32_t* Vsl = smV[buf][1];

        for (int gg = 0; gg < ngrp; ++gg) {
            uint32_t kh0[2], kl0[2], kh1[2], kl1[2];
            {
                uint2 x0 = *(const uint2*)(Ksh + (gg*2)*64 + lane*2);
                uint2 y0 = *(const uint2*)(Ksl + (gg*2)*64 + lane*2);
                uint2 x1 = *(const uint2*)(Ksh + (gg*2+1)*64 + lane*2);
                uint2 y1 = *(const uint2*)(Ksl + (gg*2+1)*64 + lane*2);
                kh0[0]=x0.x; kh0[1]=x0.y; kl0[0]=y0.x; kl0[1]=y0.y;
                kh1[0]=x1.x; kh1[1]=x1.y; kl1[0]=y1.x; kl1[1]=y1.y;
            }
            uint32_t vh0[2], vl0[2], vh1[2], vl1[2];
            {
                uint2 x0 = *(const uint2*)(Vsh + (gg*2)*64 + lane*2);
                uint2 y0 = *(const uint2*)(Vsl + (gg*2)*64 + lane*2);
                uint2 x1 = *(const uint2*)(Vsh + (gg*2+1)*64 + lane*2);
                uint2 y1 = *(const uint2*)(Vsl + (gg*2+1)*64 + lane*2);
                vh0[0]=x0.x; vh0[1]=x0.y; vl0[0]=y0.x; vl0[1]=y0.y;
                vh1[0]=x1.x; vh1[1]=x1.y; vl1[0]=y1.x; vl1[1]=y1.y;
            }
#pragma unroll
            for (int t = 0; t < 2; ++t) {
                float d0[4] = {0.f,0.f,0.f,0.f}, d1[4] = {0.f,0.f,0.f,0.f};
                mma16816(d0, qh[t], kh0);
                mma16816(d0, ql[t], kh0);
                mma16816(d0, qh[t], kl0);
                mma16816(d1, qh[t], kh1);
                mma16816(d1, ql[t], kh1);
                mma16816(d1, qh[t], kl1);
                float e00 = ex2(d0[0] - SHIFT_), e01 = ex2(d0[1] - SHIFT_);
                float e02 = ex2(d0[2] - SHIFT_), e03 = ex2(d0[3] - SHIFT_);
                float e10 = ex2(d1[0] - SHIFT_), e11 = ex2(d1[1] - SHIFT_);
                float e12 = ex2(d1[2] - SHIFT_), e13 = ex2(d1[3] - SHIFT_);
                la[t] += (e00 + e01) + (e10 + e11);
                lb[t] += (e02 + e03) + (e12 + e13);
                uint32_t ph[4], pl[4];
                split_pack(e00, e01, ph[0], pl[0]);
                split_pack(e02, e03, ph[1], pl[1]);
                split_pack(e10, e11, ph[2], pl[2]);
                split_pack(e12, e13, ph[3], pl[3]);
                mma16816(acc[t][0], ph, vh0);
                mma16816(acc[t][0], pl, vh0);
                mma16816(acc[t][0], ph, vl0);
                mma16816(acc[t][1], ph, vh1);
                mma16816(acc[t][1], pl, vh1);
                mma16816(acc[t][1], ph, vl1);
            }
        }
        __syncthreads();
    }

    const int b = bh >> 3, h = bh & 7;
#pragma unroll
    for (int t = 0; t < 2; ++t) {
        float sa = la[t];
        sa += __shfl_xor_sync(0xFFFFFFFFu, sa, 1);
        sa += __shfl_xor_sync(0xFFFFFFFFu, sa, 2);
        float sb = lb[t];
        sb += __shfl_xor_sync(0xFFFFFFFFu, sb, 1);
        sb += __shfl_xor_sync(0xFFFFFFFFu, sb, 2);
        float ia = 1.0f / sa, ib = 1.0f / sb;
        int q = qt[t]*16 + g;
        float* oA = g_attn + ((long)b*N_ + q)*128 + h*16 + tig*2;
        float* oB = g_attn + ((long)b*N_ + q + 8)*128 + h*16 + tig*2;
        *(float2*)(oA)     = make_float2(acc[t][0][0]*ia, acc[t][0][1]*ia);
        *(float2*)(oA + 8) = make_float2(acc[t][1][0]*ia, acc[t][1][1]*ia);
        *(float2*)(oB)     = make_float2(acc[t][0][2]*ib, acc[t][0][3]*ib);
        *(float2*)(oB + 8) = make_float2(acc[t][1][2]*ib, acc[t][1][3]*ib);
    }
}

// ============ proj over scrambled reinterpretation (64-wide) ====================
__global__ __launch_bounds__(256, 2) void k_proj(const float* __restrict__ pw,
                                                 const float* __restrict__ pb,
                                                 float* __restrict__ out) {
    extern __shared__ float sm[];
    float* Wt = sm;
    float* Bs = sm + 128*129;
    const int tid = threadIdx.x;
    const int b  = blockIdx.y;
    const int P0 = blockIdx.x * 64;

    for (int idx = tid; idx < 128*128; idx += 256) {
        int hi = idx >> 7, lo = idx & 127;
        Wt[lo*129 + hi] = pw[idx];
    }
    for (int idx = tid; idx < 128*64; idx += 256) {
        int hi = idx >> 6, lo = idx & 63;
        int f  = hi*N_ + P0 + lo;
        int nn = f >> 7;
        int ch = f & 127;
        Bs[idx] = g_attn[((long)b*N_ + nn)*128 + ch];
    }
    __syncthreads();

    const int tr = tid >> 4, tc = tid & 15;
    u64 acc[8][2];
#pragma unroll
    for (int i = 0; i < 8; ++i) { acc[i][0] = 0ull; acc[i][1] = 0ull; }
    gemm_core2_64(Wt, Bs, acc, tr, tc);

#pragma unroll
    for (int i = 0; i < 8; ++i) {
        int o = tr*8 + i;
        float bias = pb[o];
        long rowbase = ((long)b*128 + o)*N_ + P0 + tc*4;
#pragma unroll
        for (int j = 0; j < 2; ++j) {
            float v0, v1; up2(acc[i][j], v0, v1);
            float2 ww = make_float2(v0 + bias, v1 + bias);
            *(float2*)(out + rowbase + 2*j) = ww;
        }
    }
}

// ---------------- launch ----------------
extern "C" void kernel_launch(void* const* d_in, const int* in_sizes, int n_in,
                              void* d_out, int out_size) {
    const float* x    = (const float*)d_in[0];
    const float* q_w  = (const float*)d_in[1];
    const float* q_b  = (const float*)d_in[2];
    const float* k_w  = (const float*)d_in[3];
    const float* k_b  = (const float*)d_in[4];
    const float* v_w  = (const float*)d_in[5];
    const float* v_b  = (const float*)d_in[6];
    const float* sr_w = (const float*)d_in[7];
    const float* sr_b = (const float*)d_in[8];
    const float* bn_g = (const float*)d_in[9];
    const float* bn_b = (const float*)d_in[10];
    const float* bn_m = (const float*)d_in[11];
    const float* bn_v = (const float*)d_in[12];
    const float* p_w  = (const float*)d_in[13];
    const float* p_b  = (const float*)d_in[14];
    float* out = (float*)d_out;

    const int KVS = (256 + 128*129 + 128*32)*4;   // 83,456 B

    cudaFuncSetAttribute(k_stage1, cudaFuncAttributeMaxDynamicSharedMemorySize, GS64_);
    cudaFuncSetAttribute(k_kv,     cudaFuncAttributeMaxDynamicSharedMemorySize, KVS);
    cudaFuncSetAttribute(k_proj,   cudaFuncAttributeMaxDynamicSharedMemorySize, GS64_);

    k_stage1<<<300, 256, GS64_>>>(x, q_w, q_b, sr_w);
    k_kv    <<<dim3(50, B_, 2), 256, KVS>>>(k_w, k_b, v_w, v_b, sr_b, bn_g, bn_b, bn_m, bn_v);
    k_attn  <<<dim3(25, 16), 256>>>();
    k_proj  <<<dim3(100, B_), 256, GS64_>>>(p_w, p_b, out);
}

// round 7
// speedup vs baseline: 3.9762x; 1.1067x over previous
#include <cuda_runtime.h>
#include <cuda_bf16.h>
#include <cstdint>

#define B_    2
#define DIM_  128
#define N_    6400
#define NKV_  1600
#define SL2E_ 0.3606737602f   // 0.25 * log2(e)
#define SHIFT_ 16.0f

typedef unsigned long long u64;

// ---------------- helpers ----------------
__device__ __forceinline__ float ex2(float x) {
    float y; asm("ex2.approx.f32 %0, %1;" : "=f"(y) : "f"(x)); return y;
}
// pack (a -> low half, b -> high half) to bf16x2 hi + residual lo
__device__ __forceinline__ void split_pack(float a, float b, uint32_t& hi, uint32_t& lo) {
    uint32_t h; asm("cvt.rn.bf16x2.f32 %0, %1, %2;" : "=r"(h) : "f"(b), "f"(a));
    float fa = __uint_as_float(h << 16);
    float fb = __uint_as_float(h & 0xFFFF0000u);
    float ra = a - fa, rb = b - fb;
    uint32_t l_; asm("cvt.rn.bf16x2.f32 %0, %1, %2;" : "=r"(l_) : "f"(rb), "f"(ra));
    hi = h; lo = l_;
}
// ---------------- HMMA m16n8k16 bf16 ----------------
__device__ __forceinline__ void mma16816(float d[4], const uint32_t a[4], const uint32_t b[2]) {
    asm("mma.sync.aligned.m16n8k16.row.col.f32.bf16.bf16.f32 "
        "{%0,%1,%2,%3}, {%4,%5,%6,%7}, {%8,%9}, {%0,%1,%2,%3};"
        : "+f"(d[0]), "+f"(d[1]), "+f"(d[2]), "+f"(d[3])
        : "r"(a[0]), "r"(a[1]), "r"(a[2]), "r"(a[3]), "r"(b[0]), "r"(b[1]));
}

// ---------------- scratch ----------------
__device__ uint32_t g_Qh[16*400*32*4];
__device__ uint32_t g_Ql[16*400*32*4];
__device__ uint32_t g_Kh[16*200*32*2];
__device__ uint32_t g_Kl[16*200*32*2];
__device__ uint32_t g_Vh[16*100*2*32*2];
__device__ uint32_t g_Vl[16*100*2*32*2];
__device__ float g_xkv[B_*DIM_*NKV_];      // post BN+ReLU
__device__ float g_attn[B_*N_*DIM_];
// weight fragments: [split(0=hi,1=lo)][(mt*KT+kt)*32 + lane][4]
__device__ uint32_t g_Wq[2][8*8*32*4];
__device__ uint32_t g_Wk[2][8*8*32*4];
__device__ uint32_t g_Wv[2][8*8*32*4];
__device__ uint32_t g_Wp[2][8*8*32*4];
__device__ uint32_t g_Wsr[2][8*32*32*4];

// ============ weight prep: fp32 -> split bf16 A-fragments =======================
__global__ __launch_bounds__(256) void k_prep(const float* __restrict__ qw,
                                              const float* __restrict__ kw,
                                              const float* __restrict__ vw,
                                              const float* __restrict__ pw,
                                              const float* __restrict__ srw) {
    int bx = blockIdx.x, tid = threadIdx.x;
    const float* src; uint32_t *dh, *dl; int K, b0;
    if (bx < 4)       { src = qw;  dh = g_Wq[0];  dl = g_Wq[1];  K = 128; b0 = bx; }
    else if (bx < 8)  { src = kw;  dh = g_Wk[0];  dl = g_Wk[1];  K = 128; b0 = bx - 4; }
    else if (bx < 12) { src = vw;  dh = g_Wv[0];  dl = g_Wv[1];  K = 128; b0 = bx - 8; }
    else if (bx < 16) { src = pw;  dh = g_Wp[0];  dl = g_Wp[1];  K = 128; b0 = bx - 12; }
    else              { src = srw; dh = g_Wsr[0]; dl = g_Wsr[1]; K = 512; b0 = bx - 16; }
    const int KT = K >> 4;
    const int KP = K >> 1;
    for (int p = b0*2048 + tid; p < (b0 + 1)*2048; p += 256) {
        int o = p / KP, cp = p % KP;
        int c = cp * 2;
        float v0 = src[o*K + c], v1 = src[o*K + c + 1];
        uint32_t h, l; split_pack(v0, v1, h, l);
        int mt = o >> 4, r = o & 15;
        int kt = c >> 4, kk = c & 15;
        int reg  = ((kk & 8) ? 2 : 0) + (r >> 3);
        int lane = (r & 7)*4 + ((kk & 7) >> 1);
        long idx = (((long)mt*KT + kt)*32 + lane)*4 + reg;
        dh[idx] = h; dl[idx] = l;
    }
}

// ---------------- common HMMA mainloop: 128(K-chunk) x 64(n) --------------------
// wh/wl pre-offset to this warp's mt (and K-chunk). Bs frag: [(kt*8+ng)*32+lane][2]
__device__ __forceinline__ void hmma_tile(const uint32_t* __restrict__ wh,
                                          const uint32_t* __restrict__ wl,
                                          const uint32_t* __restrict__ Bsh,
                                          const uint32_t* __restrict__ Bsl,
                                          float acc[8][4], int lane) {
#pragma unroll
    for (int kt = 0; kt < 8; ++kt) {
        uint32_t ah[4], al[4];
        const uint4 a4 = *(const uint4*)(wh + (kt*32 + lane)*4);
        const uint4 c4 = *(const uint4*)(wl + (kt*32 + lane)*4);
        ah[0]=a4.x; ah[1]=a4.y; ah[2]=a4.z; ah[3]=a4.w;
        al[0]=c4.x; al[1]=c4.y; al[2]=c4.z; al[3]=c4.w;
#pragma unroll
        for (int ng = 0; ng < 8; ++ng) {
            uint32_t bh[2], bl[2];
            uint2 u = *(const uint2*)(Bsh + ((kt*8 + ng)*32 + lane)*2);
            uint2 v = *(const uint2*)(Bsl + ((kt*8 + ng)*32 + lane)*2);
            bh[0]=u.x; bh[1]=u.y; bl[0]=v.x; bl[1]=v.y;
            mma16816(acc[ng], ah, bh);
            mma16816(acc[ng], al, bh);
            mma16816(acc[ng], ah, bl);
        }
    }
}
// B-frag smem store for value pair at (c even, n)
__device__ __forceinline__ void bfrag_store(uint32_t* Bsh, uint32_t* Bsl,
                                            int c, int n, float v0, float v1) {
    uint32_t h, l; split_pack(v0, v1, h, l);
    int kt = c >> 4, kk = c & 15;
    int ng = n >> 3;
    int reg  = (kk & 8) ? 1 : 0;
    int lane = (n & 7)*4 + ((kk & 7) >> 1);
    int idx = ((kt*8 + ng)*32 + lane)*2 + reg;
    Bsh[idx] = h; Bsl[idx] = l;
}
// D-frag -> fp32 smem tile (pitch 65)
__device__ __forceinline__ void dfrag_to_cs(float* Cs, const float acc[8][4],
                                            int w, int lane) {
    int g = lane >> 2, tig = lane & 3;
#pragma unroll
    for (int ng = 0; ng < 8; ++ng) {
        float* r0 = Cs + (w*16 + g)*65 + ng*8 + tig*2;
        float* r1 = Cs + (w*16 + 8 + g)*65 + ng*8 + tig*2;
        r0[0] = acc[ng][0]; r0[1] = acc[ng][1];
        r1[0] = acc[ng][2]; r1[1] = acc[ng][3];
    }
}

#define GSM_ ((4096 + 4096)*4 + 128*65*4)    // 66048 B

// ============ stage1: [0,200) Q-GEMM, [200,250) SR conv (full K=512) ============
__global__ __launch_bounds__(256, 2) void k_stage1(const float* __restrict__ x,
                                                   const float* __restrict__ qb,
                                                   const float* __restrict__ srb,
                                                   const float* __restrict__ bng,
                                                   const float* __restrict__ bnb,
                                                   const float* __restrict__ bnm,
                                                   const float* __restrict__ bnv) {
    extern __shared__ char smraw[];
    uint32_t* Bsh = (uint32_t*)smraw;
    uint32_t* Bsl = Bsh + 4096;
    float*    Cs  = (float*)(Bsl + 4096);
    const int tid = threadIdx.x;
    const int w   = tid >> 5, lane = tid & 31;
    const int bx  = blockIdx.x;
    const int tr = tid >> 4, tc = tid & 15;

    float acc[8][4];
#pragma unroll
    for (int i = 0; i < 8; ++i)
#pragma unroll
        for (int j = 0; j < 4; ++j) acc[i][j] = 0.f;

    if (bx < 200) {
        const int b  = bx / 100;
        const int N0 = (bx % 100) * 64;
        for (int idx = tid; idx < 64*64; idx += 256) {
            int cp = idx >> 6, n = idx & 63;
            int c = 2*cp;
            float v0 = x[(b*128 + c)*N_ + N0 + n];
            float v1 = x[(b*128 + c + 1)*N_ + N0 + n];
            bfrag_store(Bsh, Bsl, c, n, v0, v1);
        }
        __syncthreads();
        hmma_tile(g_Wq[0] + w*1024, g_Wq[1] + w*1024, Bsh, Bsl, acc, lane);
        dfrag_to_cs(Cs, acc, w, lane);
        __syncthreads();
#pragma unroll
        for (int i = 0; i < 8; i += 2) {
            int o0 = tr*8 + i;
            float b0 = qb[o0], b1 = qb[o0+1];
            int dp = (o0 & 15) >> 1;
            int bh = b*8 + (o0 >> 4);
            int tig = dp & 3;
            int reglo = (dp < 4) ? 0 : 2;
#pragma unroll
            for (int j = 0; j < 2; ++j)
#pragma unroll
                for (int e = 0; e < 2; ++e) {
                    int nn = tc*4 + 2*j + e;
                    float va = Cs[o0*65 + nn] + b0;
                    float vb = Cs[(o0+1)*65 + nn] + b1;
                    int n  = N0 + nn;
                    int qt = n >> 4, r = n & 15;
                    int reg = reglo + (r >> 3);
                    int ln = (r & 7)*4 + tig;
                    long idx = (((long)bh*400 + qt)*32 + ln)*4 + reg;
                    uint32_t hi_, lo_;
                    split_pack(va*SL2E_, vb*SL2E_, hi_, lo_);
                    g_Qh[idx] = hi_;  g_Ql[idx] = lo_;
                }
        }
    } else {
        const int sidx = bx - 200;
        const int b  = sidx / 25;
        const int P0 = (sidx % 25) * 64;
        for (int kc = 0; kc < 4; ++kc) {
            __syncthreads();
            for (int idx = tid; idx < 64*64; idx += 256) {
                int cp = idx >> 6, n = idx & 63;
                int cl = 2*cp;
                int kb = kc*128 + cl;
                int c  = kb >> 2;
                int ii = (kb >> 1) & 1;
                int p  = P0 + n;
                int hp = p / 40, wp = p % 40;
                const float* base = x + ((b*128 + c)*80 + 2*hp + ii)*80 + 2*wp;
                bfrag_store(Bsh, Bsl, cl, n, base[0], base[1]);  // jj = 0,1
            }
            __syncthreads();
            hmma_tile(g_Wsr[0] + (w*32 + kc*8)*128, g_Wsr[1] + (w*32 + kc*8)*128,
                      Bsh, Bsl, acc, lane);
        }
        dfrag_to_cs(Cs, acc, w, lane);
        __syncthreads();
#pragma unroll
        for (int i = 0; i < 8; ++i) {
            int o = tr*8 + i;
            float inv = bng[o] * rsqrtf(bnv[o] + 1e-5f);
            float sh  = srb[o]*inv + bnb[o] - bnm[o]*inv;
#pragma unroll
            for (int j = 0; j < 4; ++j) {
                int nn = tc*4 + j;
                float v = Cs[o*65 + nn]*inv + sh;
                g_xkv[(b*128 + o)*NKV_ + P0 + nn] = fmaxf(v, 0.f);
            }
        }
    }
}

// ============ K/V GEMM (HMMA) -> fragment arrays ================================
__global__ __launch_bounds__(256, 2) void k_kv(const float* __restrict__ kb,
                                               const float* __restrict__ vb) {
    extern __shared__ char smraw[];
    uint32_t* Bsh = (uint32_t*)smraw;
    uint32_t* Bsl = Bsh + 4096;
    float*    Cs  = (float*)(Bsl + 4096);
    const int tid = threadIdx.x;
    const int w   = tid >> 5, lane = tid & 31;
    const int b  = blockIdx.y;
    const int zz = blockIdx.z;
    const int M0 = blockIdx.x * 64;
    const float* bg = zz ? vb : kb;
    const uint32_t* wh = (zz ? g_Wv[0] : g_Wk[0]) + w*1024;
    const uint32_t* wl = (zz ? g_Wv[1] : g_Wk[1]) + w*1024;

    for (int idx = tid; idx < 64*64; idx += 256) {
        int cp = idx >> 6, n = idx & 63;
        int c = 2*cp;
        float v0 = g_xkv[(b*128 + c)*NKV_ + M0 + n];
        float v1 = g_xkv[(b*128 + c + 1)*NKV_ + M0 + n];
        bfrag_store(Bsh, Bsl, c, n, v0, v1);
    }
    __syncthreads();

    float acc[8][4];
#pragma unroll
    for (int i = 0; i < 8; ++i)
#pragma unroll
        for (int j = 0; j < 4; ++j) acc[i][j] = 0.f;
    hmma_tile(wh, wl, Bsh, Bsl, acc, lane);
    dfrag_to_cs(Cs, acc, w, lane);
    __syncthreads();

    const int tr = tid >> 4, tc = tid & 15;
    if (!zz) {
#pragma unroll
        for (int i = 0; i < 8; i += 2) {
            int o0 = tr*8 + i;
            float b0 = bg[o0], b1 = bg[o0+1];
            int dp = (o0 & 15) >> 1;
            int bh = b*8 + (o0 >> 4);
            int tig = dp & 3;
            int reg = (dp < 4) ? 0 : 1;
#pragma unroll
            for (int j = 0; j < 2; ++j)
#pragma unroll
                for (int e = 0; e < 2; ++e) {
                    int nn = tc*4 + 2*j + e;
                    float va = Cs[o0*65 + nn] + b0;
                    float vb = Cs[(o0+1)*65 + nn] + b1;
                    int m = M0 + nn;
                    int kt = m >> 3;
                    int ln = (m & 7)*4 + tig;
                    long idx = (((long)bh*200 + kt)*32 + ln)*2 + reg;
                    uint32_t hi_, lo_;
                    split_pack(va, vb, hi_, lo_);
                    g_Kh[idx] = hi_;  g_Kl[idx] = lo_;
                }
        }
    } else {
#pragma unroll
        for (int i = 0; i < 8; ++i) {
            int o = tr*8 + i;
            float bias = bg[o];
            int d = o & 15;
            int bh = b*8 + (o >> 4);
            int dh = d >> 3;
#pragma unroll
            for (int j = 0; j < 2; ++j) {
                int nn = tc*4 + 2*j;
                float v0 = Cs[o*65 + nn] + bias;
                float v1 = Cs[o*65 + nn + 1] + bias;
                int m0 = M0 + nn;
                int ml = m0 & 15;
                int reg  = (ml < 8) ? 0 : 1;
                int tigv = (ml & 7) >> 1;
                int vt = m0 >> 4;
                int ln = (d & 7)*4 + tigv;
                long idx = ((((long)bh*100 + vt)*2 + dh)*32 + ln)*2 + reg;
                uint32_t hi_, lo_;
                split_pack(v0, v1, hi_, lo_);
                g_Vh[idx] = hi_;  g_Vl[idx] = lo_;
            }
        }
    }
}

// ============ HMMA flash attention (unchanged) ==================================
__global__ __launch_bounds__(256) void k_attn() {
    __shared__ uint32_t smK[2][2][1024];
    __shared__ uint32_t smV[2][2][1024];
    const int tid  = threadIdx.x;
    const int w    = tid >> 5;
    const int lane = tid & 31;
    const int g    = lane >> 2, tig = lane & 3;
    const int bh   = blockIdx.y;
    const int blk  = blockIdx.x;

    uint32_t qh[2][4], ql[2][4];
    int qt[2] = {blk*16 + w, blk*16 + 8 + w};
#pragma unroll
    for (int t = 0; t < 2; ++t) {
        const uint4 a = *(const uint4*)(g_Qh + (((long)bh*400 + qt[t])*32 + lane)*4);
        const uint4 b = *(const uint4*)(g_Ql + (((long)bh*400 + qt[t])*32 + lane)*4);
        qh[t][0]=a.x; qh[t][1]=a.y; qh[t][2]=a.z; qh[t][3]=a.w;
        ql[t][0]=b.x; ql[t][1]=b.y; ql[t][2]=b.z; ql[t][3]=b.w;
    }
    float acc[2][2][4];
    float la[2] = {0.f, 0.f}, lb[2] = {0.f, 0.f};
#pragma unroll
    for (int t = 0; t < 2; ++t)
#pragma unroll
        for (int d = 0; d < 2; ++d)
#pragma unroll
            for (int r = 0; r < 4; ++r) acc[t][d][r] = 0.f;

    auto copy_chunk = [&](int buf, int c) {
        const int nq = (c == 12) ? 128 : 256;
        const uint4* kh = (const uint4*)(g_Kh + ((long)bh*200 + c*16)*64);
        const uint4* kl = (const uint4*)(g_Kl + ((long)bh*200 + c*16)*64);
        const uint4* vh = (const uint4*)(g_Vh + ((long)bh*100 + c*8)*128);
        const uint4* vl = (const uint4*)(g_Vl + ((long)bh*100 + c*8)*128);
        uint4* dkh = (uint4*)smK[buf][0];
        uint4* dkl = (uint4*)smK[buf][1];
        uint4* dvh = (uint4*)smV[buf][0];
        uint4* dvl = (uint4*)smV[buf][1];
        for (int i = tid; i < nq; i += 256) {
            dkh[i] = kh[i]; dkl[i] = kl[i]; dvh[i] = vh[i]; dvl[i] = vl[i];
        }
    };

    copy_chunk(0, 0);
    __syncthreads();

    for (int c = 0; c < 13; ++c) {
        const int buf = c & 1;
        if (c < 12) copy_chunk(buf ^ 1, c + 1);
        const int ngrp = (c == 12) ? 4 : 8;
        const uint32_t* Ksh = smK[buf][0];
        const uint32_t* Ksl = smK[buf][1];
        const uint32_t* Vsh = smV[buf][0];
        const uint32_t* Vsl = smV[buf][1];

        for (int gg = 0; gg < ngrp; ++gg) {
            uint32_t kh0[2], kl0[2], kh1[2], kl1[2];
            {
                uint2 x0 = *(const uint2*)(Ksh + (gg*2)*64 + lane*2);
                uint2 y0 = *(const uint2*)(Ksl + (gg*2)*64 + lane*2);
                uint2 x1 = *(const uint2*)(Ksh + (gg*2+1)*64 + lane*2);
                uint2 y1 = *(const uint2*)(Ksl + (gg*2+1)*64 + lane*2);
                kh0[0]=x0.x; kh0[1]=x0.y; kl0[0]=y0.x; kl0[1]=y0.y;
                kh1[0]=x1.x; kh1[1]=x1.y; kl1[0]=y1.x; kl1[1]=y1.y;
            }
            uint32_t vh0[2], vl0[2], vh1[2], vl1[2];
            {
                uint2 x0 = *(const uint2*)(Vsh + (gg*2)*64 + lane*2);
                uint2 y0 = *(const uint2*)(Vsl + (gg*2)*64 + lane*2);
                uint2 x1 = *(const uint2*)(Vsh + (gg*2+1)*64 + lane*2);
                uint2 y1 = *(const uint2*)(Vsl + (gg*2+1)*64 + lane*2);
                vh0[0]=x0.x; vh0[1]=x0.y; vl0[0]=y0.x; vl0[1]=y0.y;
                vh1[0]=x1.x; vh1[1]=x1.y; vl1[0]=y1.x; vl1[1]=y1.y;
            }
#pragma unroll
            for (int t = 0; t < 2; ++t) {
                float d0[4] = {0.f,0.f,0.f,0.f}, d1[4] = {0.f,0.f,0.f,0.f};
                mma16816(d0, qh[t], kh0);
                mma16816(d0, ql[t], kh0);
                mma16816(d0, qh[t], kl0);
                mma16816(d1, qh[t], kh1);
                mma16816(d1, ql[t], kh1);
                mma16816(d1, qh[t], kl1);
                float e00 = ex2(d0[0] - SHIFT_), e01 = ex2(d0[1] - SHIFT_);
                float e02 = ex2(d0[2] - SHIFT_), e03 = ex2(d0[3] - SHIFT_);
                float e10 = ex2(d1[0] - SHIFT_), e11 = ex2(d1[1] - SHIFT_);
                float e12 = ex2(d1[2] - SHIFT_), e13 = ex2(d1[3] - SHIFT_);
                la[t] += (e00 + e01) + (e10 + e11);
                lb[t] += (e02 + e03) + (e12 + e13);
                uint32_t ph[4], pl[4];
                split_pack(e00, e01, ph[0], pl[0]);
                split_pack(e02, e03, ph[1], pl[1]);
                split_pack(e10, e11, ph[2], pl[2]);
                split_pack(e12, e13, ph[3], pl[3]);
                mma16816(acc[t][0], ph, vh0);
                mma16816(acc[t][0], pl, vh0);
                mma16816(acc[t][0], ph, vl0);
                mma16816(acc[t][1], ph, vh1);
                mma16816(acc[t][1], pl, vh1);
                mma16816(acc[t][1], ph, vl1);
            }
        }
        __syncthreads();
    }

    const int b = bh >> 3, h = bh & 7;
#pragma unroll
    for (int t = 0; t < 2; ++t) {
        float sa = la[t];
        sa += __shfl_xor_sync(0xFFFFFFFFu, sa, 1);
        sa += __shfl_xor_sync(0xFFFFFFFFu, sa, 2);
        float sb = lb[t];
        sb += __shfl_xor_sync(0xFFFFFFFFu, sb, 1);
        sb += __shfl_xor_sync(0xFFFFFFFFu, sb, 2);
        float ia = 1.0f / sa, ib = 1.0f / sb;
        int q = qt[t]*16 + g;
        float* oA = g_attn + ((long)b*N_ + q)*128 + h*16 + tig*2;
        float* oB = g_attn + ((long)b*N_ + q + 8)*128 + h*16 + tig*2;
        *(float2*)(oA)     = make_float2(acc[t][0][0]*ia, acc[t][0][1]*ia);
        *(float2*)(oA + 8) = make_float2(acc[t][1][0]*ia, acc[t][1][1]*ia);
        *(float2*)(oB)     = make_float2(acc[t][0][2]*ib, acc[t][0][3]*ib);
        *(float2*)(oB + 8) = make_float2(acc[t][1][2]*ib, acc[t][1][3]*ib);
    }
}

// ============ proj (HMMA) over scrambled reinterpretation =======================
__global__ __launch_bounds__(256, 2) void k_proj(const float* __restrict__ pb,
                                                 float* __restrict__ out) {
    extern __shared__ char smraw[];
    uint32_t* Bsh = (uint32_t*)smraw;
    uint32_t* Bsl = Bsh + 4096;
    float*    Cs  = (float*)(Bsl + 4096);
    const int tid = threadIdx.x;
    const int w   = tid >> 5, lane = tid & 31;
    const int b  = blockIdx.y;
    const int P0 = blockIdx.x * 64;
    const float* gA = g_attn + (long)b*N_*128;

    for (int idx = tid; idx < 64*64; idx += 256) {
        int cp = idx >> 6, n = idx & 63;
        int c = 2*cp;
        long f = (long)c*N_ + P0 + n;
        float v0 = gA[f];
        float v1 = gA[f + N_];
        bfrag_store(Bsh, Bsl, c, n, v0, v1);
    }
    __syncthreads();

    float acc[8][4];
#pragma unroll
    for (int i = 0; i < 8; ++i)
#pragma unroll
        for (int j = 0; j < 4; ++j) acc[i][j] = 0.f;
    hmma_tile(g_Wp[0] + w*1024, g_Wp[1] + w*1024, Bsh, Bsl, acc, lane);
    dfrag_to_cs(Cs, acc, w, lane);
    __syncthreads();

    const int tr = tid >> 4, tc = tid & 15;
#pragma unroll
    for (int i = 0; i < 8; ++i) {
        int o = tr*8 + i;
        float bias = pb[o];
        long rowbase = ((long)b*128 + o)*N_ + P0 + tc*4;
#pragma unroll
        for (int j = 0; j < 2; ++j) {
            float v0 = Cs[o*65 + tc*4 + 2*j]     + bias;
            float v1 = Cs[o*65 + tc*4 + 2*j + 1] + bias;
            *(float2*)(out + rowbase + 2*j) = make_float2(v0, v1);
        }
    }
}

// ---------------- launch ----------------
extern "C" void kernel_launch(void* const* d_in, const int* in_sizes, int n_in,
                              void* d_out, int out_size) {
    const float* x    = (const float*)d_in[0];
    const float* q_w  = (const float*)d_in[1];
    const float* q_b  = (const float*)d_in[2];
    const float* k_w  = (const float*)d_in[3];
    const float* k_b  = (const float*)d_in[4];
    const float* v_w  = (const float*)d_in[5];
    const float* v_b  = (const float*)d_in[6];
    const float* sr_w = (const float*)d_in[7];
    const float* sr_b = (const float*)d_in[8];
    const float* bn_g = (const float*)d_in[9];
    const float* bn_b = (const float*)d_in[10];
    const float* bn_m = (const float*)d_in[11];
    const float* bn_v = (const float*)d_in[12];
    const float* p_w  = (const float*)d_in[13];
    const float* p_b  = (const float*)d_in[14];
    float* out = (float*)d_out;

    cudaFuncSetAttribute(k_stage1, cudaFuncAttributeMaxDynamicSharedMemorySize, GSM_);
    cudaFuncSetAttribute(k_kv,     cudaFuncAttributeMaxDynamicSharedMemorySize, GSM_);
    cudaFuncSetAttribute(k_proj,   cudaFuncAttributeMaxDynamicSharedMemorySize, GSM_);

    k_prep  <<<32, 256>>>(q_w, k_w, v_w, p_w, sr_w);
    k_stage1<<<250, 256, GSM_>>>(x, q_b, sr_b, bn_g, bn_b, bn_m, bn_v);
    k_kv    <<<dim3(25, B_, 2), 256, GSM_>>>(k_b, v_b);
    k_attn  <<<dim3(25, 16), 256>>>();
    k_proj  <<<dim3(100, B_), 256, GSM_>>>(p_b, out);
}

// round 8
// speedup vs baseline: 5.1510x; 1.2955x over previous
#include <cuda_runtime.h>
#include <cuda_bf16.h>
#include <cstdint>

#define B_    2
#define DIM_  128
#define N_    6400
#define NKV_  1600
#define SL2E_ 0.3606737602f   // 0.25 * log2(e)
#define SHIFT_ 16.0f

typedef unsigned long long u64;

// ---------------- helpers ----------------
__device__ __forceinline__ float ex2(float x) {
    float y; asm("ex2.approx.f32 %0, %1;" : "=f"(y) : "f"(x)); return y;
}
// bf16 split (weights / GEMM stages): a -> low half, b -> high half
__device__ __forceinline__ void split_pack(float a, float b, uint32_t& hi, uint32_t& lo) {
    uint32_t h; asm("cvt.rn.bf16x2.f32 %0, %1, %2;" : "=r"(h) : "f"(b), "f"(a));
    float fa = __uint_as_float(h << 16);
    float fb = __uint_as_float(h & 0xFFFF0000u);
    float ra = a - fa, rb = b - fb;
    uint32_t l_; asm("cvt.rn.bf16x2.f32 %0, %1, %2;" : "=r"(l_) : "f"(rb), "f"(ra));
    hi = h; lo = l_;
}
// fp16 pack: a -> low half, b -> high half
__device__ __forceinline__ uint32_t pack_f16(float a, float b) {
    uint32_t h; asm("cvt.rn.f16x2.f32 %0, %1, %2;" : "=r"(h) : "f"(b), "f"(a));
    return h;
}
// fp16 2-term split
__device__ __forceinline__ void split_pack_f16(float a, float b, uint32_t& hi, uint32_t& lo) {
    uint32_t h; asm("cvt.rn.f16x2.f32 %0, %1, %2;" : "=r"(h) : "f"(b), "f"(a));
    float fa, fb;
    asm("{.reg .b16 x, y; mov.b32 {x, y}, %2; cvt.f32.f16 %0, x; cvt.f32.f16 %1, y;}"
        : "=f"(fa), "=f"(fb) : "r"(h));
    float ra = a - fa, rb = b - fb;
    uint32_t l_; asm("cvt.rn.f16x2.f32 %0, %1, %2;" : "=r"(l_) : "f"(rb), "f"(ra));
    hi = h; lo = l_;
}
// ---------------- HMMA m16n8k16 ----------------
__device__ __forceinline__ void mma16816(float d[4], const uint32_t a[4], const uint32_t b[2]) {
    asm("mma.sync.aligned.m16n8k16.row.col.f32.bf16.bf16.f32 "
        "{%0,%1,%2,%3}, {%4,%5,%6,%7}, {%8,%9}, {%0,%1,%2,%3};"
        : "+f"(d[0]), "+f"(d[1]), "+f"(d[2]), "+f"(d[3])
        : "r"(a[0]), "r"(a[1]), "r"(a[2]), "r"(a[3]), "r"(b[0]), "r"(b[1]));
}
__device__ __forceinline__ void mma16816f(float d[4], const uint32_t a[4], const uint32_t b[2]) {
    asm("mma.sync.aligned.m16n8k16.row.col.f32.f16.f16.f32 "
        "{%0,%1,%2,%3}, {%4,%5,%6,%7}, {%8,%9}, {%0,%1,%2,%3};"
        : "+f"(d[0]), "+f"(d[1]), "+f"(d[2]), "+f"(d[3])
        : "r"(a[0]), "r"(a[1]), "r"(a[2]), "r"(a[3]), "r"(b[0]), "r"(b[1]));
}

// ---------------- scratch ----------------
__device__ uint32_t g_Qh[16*400*32*4];          // fp16 2-term Q
__device__ uint32_t g_Ql[16*400*32*4];
__device__ uint32_t g_Kh[16*200*32*2];          // fp16 single-term K
__device__ uint32_t g_Vh[16*100*2*32*2];        // fp16 2-term V
__device__ uint32_t g_Vl[16*100*2*32*2];
__device__ float g_xkv[B_*DIM_*NKV_];
__device__ float g_attn[B_*N_*DIM_];
// weight fragments (bf16 2-term): [split][(mt*KT+kt)*32 + lane][4]
__device__ uint32_t g_Wq[2][8*8*32*4];
__device__ uint32_t g_Wk[2][8*8*32*4];
__device__ uint32_t g_Wv[2][8*8*32*4];
__device__ uint32_t g_Wp[2][8*8*32*4];
__device__ uint32_t g_Wsr[2][8*32*32*4];

// ============ weight prep ======================================================
__global__ __launch_bounds__(256) void k_prep(const float* __restrict__ qw,
                                              const float* __restrict__ kw,
                                              const float* __restrict__ vw,
                                              const float* __restrict__ pw,
                                              const float* __restrict__ srw) {
    int bx = blockIdx.x, tid = threadIdx.x;
    const float* src; uint32_t *dh, *dl; int K, b0;
    if (bx < 4)       { src = qw;  dh = g_Wq[0];  dl = g_Wq[1];  K = 128; b0 = bx; }
    else if (bx < 8)  { src = kw;  dh = g_Wk[0];  dl = g_Wk[1];  K = 128; b0 = bx - 4; }
    else if (bx < 12) { src = vw;  dh = g_Wv[0];  dl = g_Wv[1];  K = 128; b0 = bx - 8; }
    else if (bx < 16) { src = pw;  dh = g_Wp[0];  dl = g_Wp[1];  K = 128; b0 = bx - 12; }
    else              { src = srw; dh = g_Wsr[0]; dl = g_Wsr[1]; K = 512; b0 = bx - 16; }
    const int KT = K >> 4;
    const int KP = K >> 1;
    for (int p = b0*2048 + tid; p < (b0 + 1)*2048; p += 256) {
        int o = p / KP, cp = p % KP;
        int c = cp * 2;
        float v0 = src[o*K + c], v1 = src[o*K + c + 1];
        uint32_t h, l; split_pack(v0, v1, h, l);
        int mt = o >> 4, r = o & 15;
        int kt = c >> 4, kk = c & 15;
        int reg  = ((kk & 8) ? 2 : 0) + (r >> 3);
        int lane = (r & 7)*4 + ((kk & 7) >> 1);
        long idx = (((long)mt*KT + kt)*32 + lane)*4 + reg;
        dh[idx] = h; dl[idx] = l;
    }
}

// ---------------- common HMMA mainloop (bf16, GEMM stages) ----------------------
__device__ __forceinline__ void hmma_tile(const uint32_t* __restrict__ wh,
                                          const uint32_t* __restrict__ wl,
                                          const uint32_t* __restrict__ Bsh,
                                          const uint32_t* __restrict__ Bsl,
                                          float acc[8][4], int lane) {
#pragma unroll
    for (int kt = 0; kt < 8; ++kt) {
        uint32_t ah[4], al[4];
        const uint4 a4 = *(const uint4*)(wh + (kt*32 + lane)*4);
        const uint4 c4 = *(const uint4*)(wl + (kt*32 + lane)*4);
        ah[0]=a4.x; ah[1]=a4.y; ah[2]=a4.z; ah[3]=a4.w;
        al[0]=c4.x; al[1]=c4.y; al[2]=c4.z; al[3]=c4.w;
#pragma unroll
        for (int ng = 0; ng < 8; ++ng) {
            uint32_t bh[2], bl[2];
            uint2 u = *(const uint2*)(Bsh + ((kt*8 + ng)*32 + lane)*2);
            uint2 v = *(const uint2*)(Bsl + ((kt*8 + ng)*32 + lane)*2);
            bh[0]=u.x; bh[1]=u.y; bl[0]=v.x; bl[1]=v.y;
            mma16816(acc[ng], ah, bh);
            mma16816(acc[ng], al, bh);
            mma16816(acc[ng], ah, bl);
        }
    }
}
__device__ __forceinline__ void bfrag_store(uint32_t* Bsh, uint32_t* Bsl,
                                            int c, int n, float v0, float v1) {
    uint32_t h, l; split_pack(v0, v1, h, l);
    int kt = c >> 4, kk = c & 15;
    int ng = n >> 3;
    int reg  = (kk & 8) ? 1 : 0;
    int lane = (n & 7)*4 + ((kk & 7) >> 1);
    int idx = ((kt*8 + ng)*32 + lane)*2 + reg;
    Bsh[idx] = h; Bsl[idx] = l;
}
__device__ __forceinline__ void dfrag_to_cs(float* Cs, const float acc[8][4],
                                            int w, int lane) {
    int g = lane >> 2, tig = lane & 3;
#pragma unroll
    for (int ng = 0; ng < 8; ++ng) {
        float* r0 = Cs + (w*16 + g)*65 + ng*8 + tig*2;
        float* r1 = Cs + (w*16 + 8 + g)*65 + ng*8 + tig*2;
        r0[0] = acc[ng][0]; r0[1] = acc[ng][1];
        r1[0] = acc[ng][2]; r1[1] = acc[ng][3];
    }
}

#define GSM_ ((4096 + 4096)*4 + 128*65*4)    // 66048 B

// ============ stage1: [0,200) Q-GEMM, [200,250) SR conv =========================
__global__ __launch_bounds__(256, 2) void k_stage1(const float* __restrict__ x,
                                                   const float* __restrict__ qb,
                                                   const float* __restrict__ srb,
                                                   const float* __restrict__ bng,
                                                   const float* __restrict__ bnb,
                                                   const float* __restrict__ bnm,
                                                   const float* __restrict__ bnv) {
    extern __shared__ char smraw[];
    uint32_t* Bsh = (uint32_t*)smraw;
    uint32_t* Bsl = Bsh + 4096;
    float*    Cs  = (float*)(Bsl + 4096);
    const int tid = threadIdx.x;
    const int w   = tid >> 5, lane = tid & 31;
    const int bx  = blockIdx.x;
    const int tr = tid >> 4, tc = tid & 15;

    float acc[8][4];
#pragma unroll
    for (int i = 0; i < 8; ++i)
#pragma unroll
        for (int j = 0; j < 4; ++j) acc[i][j] = 0.f;

    if (bx < 200) {
        const int b  = bx / 100;
        const int N0 = (bx % 100) * 64;
        for (int idx = tid; idx < 64*64; idx += 256) {
            int cp = idx >> 6, n = idx & 63;
            int c = 2*cp;
            float v0 = x[(b*128 + c)*N_ + N0 + n];
            float v1 = x[(b*128 + c + 1)*N_ + N0 + n];
            bfrag_store(Bsh, Bsl, c, n, v0, v1);
        }
        __syncthreads();
        hmma_tile(g_Wq[0] + w*1024, g_Wq[1] + w*1024, Bsh, Bsl, acc, lane);
        dfrag_to_cs(Cs, acc, w, lane);
        __syncthreads();
#pragma unroll
        for (int i = 0; i < 8; i += 2) {
            int o0 = tr*8 + i;
            float b0 = qb[o0], b1 = qb[o0+1];
            int dp = (o0 & 15) >> 1;
            int bh = b*8 + (o0 >> 4);
            int tig = dp & 3;
            int reglo = (dp < 4) ? 0 : 2;
#pragma unroll
            for (int j = 0; j < 2; ++j)
#pragma unroll
                for (int e = 0; e < 2; ++e) {
                    int nn = tc*4 + 2*j + e;
                    float va = Cs[o0*65 + nn] + b0;
                    float vb = Cs[(o0+1)*65 + nn] + b1;
                    int n  = N0 + nn;
                    int qt = n >> 4, r = n & 15;
                    int reg = reglo + (r >> 3);
                    int ln = (r & 7)*4 + tig;
                    long idx = (((long)bh*400 + qt)*32 + ln)*4 + reg;
                    uint32_t hi_, lo_;
                    split_pack_f16(va*SL2E_, vb*SL2E_, hi_, lo_);
                    g_Qh[idx] = hi_;  g_Ql[idx] = lo_;
                }
        }
    } else {
        const int sidx = bx - 200;
        const int b  = sidx / 25;
        const int P0 = (sidx % 25) * 64;
        for (int kc = 0; kc < 4; ++kc) {
            __syncthreads();
            for (int idx = tid; idx < 64*64; idx += 256) {
                int cp = idx >> 6, n = idx & 63;
                int cl = 2*cp;
                int kb = kc*128 + cl;
                int c  = kb >> 2;
                int ii = (kb >> 1) & 1;
                int p  = P0 + n;
                int hp = p / 40, wp = p % 40;
                const float* base = x + ((b*128 + c)*80 + 2*hp + ii)*80 + 2*wp;
                bfrag_store(Bsh, Bsl, cl, n, base[0], base[1]);
            }
            __syncthreads();
            hmma_tile(g_Wsr[0] + (w*32 + kc*8)*128, g_Wsr[1] + (w*32 + kc*8)*128,
                      Bsh, Bsl, acc, lane);
        }
        dfrag_to_cs(Cs, acc, w, lane);
        __syncthreads();
#pragma unroll
        for (int i = 0; i < 8; ++i) {
            int o = tr*8 + i;
            float inv = bng[o] * rsqrtf(bnv[o] + 1e-5f);
            float sh  = srb[o]*inv + bnb[o] - bnm[o]*inv;
#pragma unroll
            for (int j = 0; j < 4; ++j) {
                int nn = tc*4 + j;
                float v = Cs[o*65 + nn]*inv + sh;
                g_xkv[(b*128 + o)*NKV_ + P0 + nn] = fmaxf(v, 0.f);
            }
        }
    }
}

// ============ K/V GEMM (HMMA) -> fp16 fragment arrays ===========================
__global__ __launch_bounds__(256, 2) void k_kv(const float* __restrict__ kb,
                                               const float* __restrict__ vb) {
    extern __shared__ char smraw[];
    uint32_t* Bsh = (uint32_t*)smraw;
    uint32_t* Bsl = Bsh + 4096;
    float*    Cs  = (float*)(Bsl + 4096);
    const int tid = threadIdx.x;
    const int w   = tid >> 5, lane = tid & 31;
    const int b  = blockIdx.y;
    const int zz = blockIdx.z;
    const int M0 = blockIdx.x * 64;
    const float* bg = zz ? vb : kb;
    const uint32_t* wh = (zz ? g_Wv[0] : g_Wk[0]) + w*1024;
    const uint32_t* wl = (zz ? g_Wv[1] : g_Wk[1]) + w*1024;

    for (int idx = tid; idx < 64*64; idx += 256) {
        int cp = idx >> 6, n = idx & 63;
        int c = 2*cp;
        float v0 = g_xkv[(b*128 + c)*NKV_ + M0 + n];
        float v1 = g_xkv[(b*128 + c + 1)*NKV_ + M0 + n];
        bfrag_store(Bsh, Bsl, c, n, v0, v1);
    }
    __syncthreads();

    float acc[8][4];
#pragma unroll
    for (int i = 0; i < 8; ++i)
#pragma unroll
        for (int j = 0; j < 4; ++j) acc[i][j] = 0.f;
    hmma_tile(wh, wl, Bsh, Bsl, acc, lane);
    dfrag_to_cs(Cs, acc, w, lane);
    __syncthreads();

    const int tr = tid >> 4, tc = tid & 15;
    if (!zz) {
#pragma unroll
        for (int i = 0; i < 8; i += 2) {
            int o0 = tr*8 + i;
            float b0 = bg[o0], b1 = bg[o0+1];
            int dp = (o0 & 15) >> 1;
            int bh = b*8 + (o0 >> 4);
            int tig = dp & 3;
            int reg = (dp < 4) ? 0 : 1;
#pragma unroll
            for (int j = 0; j < 2; ++j)
#pragma unroll
                for (int e = 0; e < 2; ++e) {
                    int nn = tc*4 + 2*j + e;
                    float va = Cs[o0*65 + nn] + b0;
                    float vb = Cs[(o0+1)*65 + nn] + b1;
                    int m = M0 + nn;
                    int kt = m >> 3;
                    int ln = (m & 7)*4 + tig;
                    long idx = (((long)bh*200 + kt)*32 + ln)*2 + reg;
                    g_Kh[idx] = pack_f16(va, vb);
                }
        }
    } else {
#pragma unroll
        for (int i = 0; i < 8; ++i) {
            int o = tr*8 + i;
            float bias = bg[o];
            int d = o & 15;
            int bh = b*8 + (o >> 4);
            int dh = d >> 3;
#pragma unroll
            for (int j = 0; j < 2; ++j) {
                int nn = tc*4 + 2*j;
                float v0 = Cs[o*65 + nn] + bias;
                float v1 = Cs[o*65 + nn + 1] + bias;
                int m0 = M0 + nn;
                int ml = m0 & 15;
                int reg  = (ml < 8) ? 0 : 1;
                int tigv = (ml & 7) >> 1;
                int vt = m0 >> 4;
                int ln = (d & 7)*4 + tigv;
                long idx = ((((long)bh*100 + vt)*2 + dh)*32 + ln)*2 + reg;
                uint32_t hi_, lo_;
                split_pack_f16(v0, v1, hi_, lo_);
                g_Vh[idx] = hi_;  g_Vl[idx] = lo_;
            }
        }
    }
}

// ============ fp16 HMMA flash attention =========================================
__global__ __launch_bounds__(256, 3) void k_attn() {
    __shared__ uint32_t smK[2][1024];
    __shared__ uint32_t smV[2][2][1024];
    const int tid  = threadIdx.x;
    const int w    = tid >> 5;
    const int lane = tid & 31;
    const int g    = lane >> 2, tig = lane & 3;
    const int bh   = blockIdx.y;
    const int blk  = blockIdx.x;

    uint32_t qh[2][4], ql[2][4];
    int qt[2] = {blk*16 + w, blk*16 + 8 + w};
#pragma unroll
    for (int t = 0; t < 2; ++t) {
        const uint4 a = *(const uint4*)(g_Qh + (((long)bh*400 + qt[t])*32 + lane)*4);
        const uint4 b = *(const uint4*)(g_Ql + (((long)bh*400 + qt[t])*32 + lane)*4);
        qh[t][0]=a.x; qh[t][1]=a.y; qh[t][2]=a.z; qh[t][3]=a.w;
        ql[t][0]=b.x; ql[t][1]=b.y; ql[t][2]=b.z; ql[t][3]=b.w;
    }
    float acc[2][2][4];
    float la[2] = {0.f, 0.f}, lb[2] = {0.f, 0.f};
#pragma unroll
    for (int t = 0; t < 2; ++t)
#pragma unroll
        for (int d = 0; d < 2; ++d)
#pragma unroll
            for (int r = 0; r < 4; ++r) acc[t][d][r] = 0.f;

    auto copy_chunk = [&](int buf, int c) {
        const int nq = (c == 12) ? 128 : 256;
        const uint4* kh = (const uint4*)(g_Kh + ((long)bh*200 + c*16)*64);
        const uint4* vh = (const uint4*)(g_Vh + ((long)bh*100 + c*8)*128);
        const uint4* vl = (const uint4*)(g_Vl + ((long)bh*100 + c*8)*128);
        uint4* dkh = (uint4*)smK[buf];
        uint4* dvh = (uint4*)smV[buf][0];
        uint4* dvl = (uint4*)smV[buf][1];
        for (int i = tid; i < nq; i += 256) {
            dkh[i] = kh[i]; dvh[i] = vh[i]; dvl[i] = vl[i];
        }
    };

    copy_chunk(0, 0);
    __syncthreads();

    for (int c = 0; c < 13; ++c) {
        const int buf = c & 1;
        if (c < 12) copy_chunk(buf ^ 1, c + 1);
        const int ngrp = (c == 12) ? 4 : 8;
        const uint32_t* Ksh = smK[buf];
        const uint32_t* Vsh = smV[buf][0];
        const uint32_t* Vsl = smV[buf][1];

        for (int gg = 0; gg < ngrp; ++gg) {
            uint32_t k0[2], k1[2];
            {
                uint2 x0 = *(const uint2*)(Ksh + (gg*2)*64 + lane*2);
                uint2 x1 = *(const uint2*)(Ksh + (gg*2+1)*64 + lane*2);
                k0[0]=x0.x; k0[1]=x0.y; k1[0]=x1.x; k1[1]=x1.y;
            }
            uint32_t vh0[2], vl0[2], vh1[2], vl1[2];
            {
                uint2 x0 = *(const uint2*)(Vsh + (gg*2)*64 + lane*2);
                uint2 y0 = *(const uint2*)(Vsl + (gg*2)*64 + lane*2);
                uint2 x1 = *(const uint2*)(Vsh + (gg*2+1)*64 + lane*2);
                uint2 y1 = *(const uint2*)(Vsl + (gg*2+1)*64 + lane*2);
                vh0[0]=x0.x; vh0[1]=x0.y; vl0[0]=y0.x; vl0[1]=y0.y;
                vh1[0]=x1.x; vh1[1]=x1.y; vl1[0]=y1.x; vl1[1]=y1.y;
            }
#pragma unroll
            for (int t = 0; t < 2; ++t) {
                float d0[4] = {0.f,0.f,0.f,0.f}, d1[4] = {0.f,0.f,0.f,0.f};
                mma16816f(d0, qh[t], k0);
                mma16816f(d0, ql[t], k0);
                mma16816f(d1, qh[t], k1);
                mma16816f(d1, ql[t], k1);
                float e00 = ex2(d0[0] - SHIFT_), e01 = ex2(d0[1] - SHIFT_);
                float e02 = ex2(d0[2] - SHIFT_), e03 = ex2(d0[3] - SHIFT_);
                float e10 = ex2(d1[0] - SHIFT_), e11 = ex2(d1[1] - SHIFT_);
                float e12 = ex2(d1[2] - SHIFT_), e13 = ex2(d1[3] - SHIFT_);
                la[t] += (e00 + e01) + (e10 + e11);
                lb[t] += (e02 + e03) + (e12 + e13);
                uint32_t p[4];
                p[0] = pack_f16(e00, e01);
                p[1] = pack_f16(e02, e03);
                p[2] = pack_f16(e10, e11);
                p[3] = pack_f16(e12, e13);
                mma16816f(acc[t][0], p, vh0);
                mma16816f(acc[t][0], p, vl0);
                mma16816f(acc[t][1], p, vh1);
                mma16816f(acc[t][1], p, vl1);
            }
        }
        __syncthreads();
    }

    const int b = bh >> 3, h = bh & 7;
#pragma unroll
    for (int t = 0; t < 2; ++t) {
        float sa = la[t];
        sa += __shfl_xor_sync(0xFFFFFFFFu, sa, 1);
        sa += __shfl_xor_sync(0xFFFFFFFFu, sa, 2);
        float sb = lb[t];
        sb += __shfl_xor_sync(0xFFFFFFFFu, sb, 1);
        sb += __shfl_xor_sync(0xFFFFFFFFu, sb, 2);
        float ia = 1.0f / sa, ib = 1.0f / sb;
        int q = qt[t]*16 + g;
        float* oA = g_attn + ((long)b*N_ + q)*128 + h*16 + tig*2;
        float* oB = g_attn + ((long)b*N_ + q + 8)*128 + h*16 + tig*2;
        *(float2*)(oA)     = make_float2(acc[t][0][0]*ia, acc[t][0][1]*ia);
        *(float2*)(oA + 8) = make_float2(acc[t][1][0]*ia, acc[t][1][1]*ia);
        *(float2*)(oB)     = make_float2(acc[t][0][2]*ib, acc[t][0][3]*ib);
        *(float2*)(oB + 8) = make_float2(acc[t][1][2]*ib, acc[t][1][3]*ib);
    }
}

// ============ proj (HMMA) =======================================================
__global__ __launch_bounds__(256, 2) void k_proj(const float* __restrict__ pb,
                                                 float* __restrict__ out) {
    extern __shared__ char smraw[];
    uint32_t* Bsh = (uint32_t*)smraw;
    uint32_t* Bsl = Bsh + 4096;
    float*    Cs  = (float*)(Bsl + 4096);
    const int tid = threadIdx.x;
    const int w   = tid >> 5, lane = tid & 31;
    const int b  = blockIdx.y;
    const int P0 = blockIdx.x * 64;
    const float* gA = g_attn + (long)b*N_*128;

    for (int idx = tid; idx < 64*64; idx += 256) {
        int cp = idx >> 6, n = idx & 63;
        int c = 2*cp;
        long f = (long)c*N_ + P0 + n;
        float v0 = gA[f];
        float v1 = gA[f + N_];
        bfrag_store(Bsh, Bsl, c, n, v0, v1);
    }
    __syncthreads();

    float acc[8][4];
#pragma unroll
    for (int i = 0; i < 8; ++i)
#pragma unroll
        for (int j = 0; j < 4; ++j) acc[i][j] = 0.f;
    hmma_tile(g_Wp[0] + w*1024, g_Wp[1] + w*1024, Bsh, Bsl, acc, lane);
    dfrag_to_cs(Cs, acc, w, lane);
    __syncthreads();

    const int tr = tid >> 4, tc = tid & 15;
#pragma unroll
    for (int i = 0; i < 8; ++i) {
        int o = tr*8 + i;
        float bias = pb[o];
        long rowbase = ((long)b*128 + o)*N_ + P0 + tc*4;
#pragma unroll
        for (int j = 0; j < 2; ++j) {
            float v0 = Cs[o*65 + tc*4 + 2*j]     + bias;
            float v1 = Cs[o*65 + tc*4 + 2*j + 1] + bias;
            *(float2*)(out + rowbase + 2*j) = make_float2(v0, v1);
        }
    }
}

// ---------------- launch ----------------
extern "C" void kernel_launch(void* const* d_in, const int* in_sizes, int n_in,
                              void* d_out, int out_size) {
    const float* x    = (const float*)d_in[0];
    const float* q_w  = (const float*)d_in[1];
    const float* q_b  = (const float*)d_in[2];
    const float* k_w  = (const float*)d_in[3];
    const float* k_b  = (const float*)d_in[4];
    const float* v_w  = (const float*)d_in[5];
    const float* v_b  = (const float*)d_in[6];
    const float* sr_w = (const float*)d_in[7];
    const float* sr_b = (const float*)d_in[8];
    const float* bn_g = (const float*)d_in[9];
    const float* bn_b = (const float*)d_in[10];
    const float* bn_m = (const float*)d_in[11];
    const float* bn_v = (const float*)d_in[12];
    const float* p_w  = (const float*)d_in[13];
    const float* p_b  = (const float*)d_in[14];
    float* out = (float*)d_out;

    cudaFuncSetAttribute(k_stage1, cudaFuncAttributeMaxDynamicSharedMemorySize, GSM_);
    cudaFuncSetAttribute(k_kv,     cudaFuncAttributeMaxDynamicSharedMemorySize, GSM_);
    cudaFuncSetAttribute(k_proj,   cudaFuncAttributeMaxDynamicSharedMemorySize, GSM_);

    k_prep  <<<32, 256>>>(q_w, k_w, v_w, p_w, sr_w);
    k_stage1<<<250, 256, GSM_>>>(x, q_b, sr_b, bn_g, bn_b, bn_m, bn_v);
    k_kv    <<<dim3(25, B_, 2), 256, GSM_>>>(k_b, v_b);
    k_attn  <<<dim3(25, 16), 256>>>();
    k_proj  <<<dim3(100, B_), 256, GSM_>>>(p_b, out);
}

// round 9
// speedup vs baseline: 6.0540x; 1.1753x over previous
#include <cuda_runtime.h>
#include <cuda_bf16.h>
#include <cstdint>

#define B_    2
#define DIM_  128
#define N_    6400
#define NKV_  1600
#define SL2E_ 0.3606737602f   // 0.25 * log2(e)
#define SHIFT_ 16.0f

typedef unsigned long long u64;

// ---------------- helpers ----------------
__device__ __forceinline__ float ex2(float x) {
    float y; asm("ex2.approx.f32 %0, %1;" : "=f"(y) : "f"(x)); return y;
}
// bf16 split (weights / GEMM stages): a -> low half, b -> high half
__device__ __forceinline__ void split_pack(float a, float b, uint32_t& hi, uint32_t& lo) {
    uint32_t h; asm("cvt.rn.bf16x2.f32 %0, %1, %2;" : "=r"(h) : "f"(b), "f"(a));
    float fa = __uint_as_float(h << 16);
    float fb = __uint_as_float(h & 0xFFFF0000u);
    float ra = a - fa, rb = b - fb;
    uint32_t l_; asm("cvt.rn.bf16x2.f32 %0, %1, %2;" : "=r"(l_) : "f"(rb), "f"(ra));
    hi = h; lo = l_;
}
// fp16 pack: a -> low half, b -> high half
__device__ __forceinline__ uint32_t pack_f16(float a, float b) {
    uint32_t h; asm("cvt.rn.f16x2.f32 %0, %1, %2;" : "=r"(h) : "f"(b), "f"(a));
    return h;
}
// ---------------- HMMA m16n8k16 ----------------
__device__ __forceinline__ void mma16816(float d[4], const uint32_t a[4], const uint32_t b[2]) {
    asm("mma.sync.aligned.m16n8k16.row.col.f32.bf16.bf16.f32 "
        "{%0,%1,%2,%3}, {%4,%5,%6,%7}, {%8,%9}, {%0,%1,%2,%3};"
        : "+f"(d[0]), "+f"(d[1]), "+f"(d[2]), "+f"(d[3])
        : "r"(a[0]), "r"(a[1]), "r"(a[2]), "r"(a[3]), "r"(b[0]), "r"(b[1]));
}
__device__ __forceinline__ void mma16816f(float d[4], const uint32_t a[4], const uint32_t b[2]) {
    asm("mma.sync.aligned.m16n8k16.row.col.f32.f16.f16.f32 "
        "{%0,%1,%2,%3}, {%4,%5,%6,%7}, {%8,%9}, {%0,%1,%2,%3};"
        : "+f"(d[0]), "+f"(d[1]), "+f"(d[2]), "+f"(d[3])
        : "r"(a[0]), "r"(a[1]), "r"(a[2]), "r"(a[3]), "r"(b[0]), "r"(b[1]));
}

// ---------------- scratch ----------------
__device__ uint32_t g_Qh[16*400*32*4];          // fp16 single-term Q (pre-scaled)
__device__ uint32_t g_Kh[16*200*32*2];          // fp16 single-term K
__device__ uint32_t g_Vh[16*100*2*32*2];        // fp16 single-term V
__device__ float g_xkv[B_*DIM_*NKV_];
__device__ float g_attn[B_*N_*DIM_];
// weight fragments (bf16 2-term): [split][(mt*KT+kt)*32 + lane][4]
__device__ uint32_t g_Wq[2][8*8*32*4];
__device__ uint32_t g_Wk[2][8*8*32*4];
__device__ uint32_t g_Wv[2][8*8*32*4];
__device__ uint32_t g_Wp[2][8*8*32*4];
__device__ uint32_t g_Wsr[2][8*32*32*4];

// ============ weight prep ======================================================
__global__ __launch_bounds__(256) void k_prep(const float* __restrict__ qw,
                                              const float* __restrict__ kw,
                                              const float* __restrict__ vw,
                                              const float* __restrict__ pw,
                                              const float* __restrict__ srw) {
    int bx = blockIdx.x, tid = threadIdx.x;
    const float* src; uint32_t *dh, *dl; int K, b0;
    if (bx < 4)       { src = qw;  dh = g_Wq[0];  dl = g_Wq[1];  K = 128; b0 = bx; }
    else if (bx < 8)  { src = kw;  dh = g_Wk[0];  dl = g_Wk[1];  K = 128; b0 = bx - 4; }
    else if (bx < 12) { src = vw;  dh = g_Wv[0];  dl = g_Wv[1];  K = 128; b0 = bx - 8; }
    else if (bx < 16) { src = pw;  dh = g_Wp[0];  dl = g_Wp[1];  K = 128; b0 = bx - 12; }
    else              { src = srw; dh = g_Wsr[0]; dl = g_Wsr[1]; K = 512; b0 = bx - 16; }
    const int KT = K >> 4;
    const int KP = K >> 1;
    for (int p = b0*2048 + tid; p < (b0 + 1)*2048; p += 256) {
        int o = p / KP, cp = p % KP;
        int c = cp * 2;
        float v0 = src[o*K + c], v1 = src[o*K + c + 1];
        uint32_t h, l; split_pack(v0, v1, h, l);
        int mt = o >> 4, r = o & 15;
        int kt = c >> 4, kk = c & 15;
        int reg  = ((kk & 8) ? 2 : 0) + (r >> 3);
        int lane = (r & 7)*4 + ((kk & 7) >> 1);
        long idx = (((long)mt*KT + kt)*32 + lane)*4 + reg;
        dh[idx] = h; dl[idx] = l;
    }
}

// ---------------- common HMMA mainloop (bf16, GEMM stages) ----------------------
__device__ __forceinline__ void hmma_tile(const uint32_t* __restrict__ wh,
                                          const uint32_t* __restrict__ wl,
                                          const uint32_t* __restrict__ Bsh,
                                          const uint32_t* __restrict__ Bsl,
                                          float acc[8][4], int lane) {
#pragma unroll
    for (int kt = 0; kt < 8; ++kt) {
        uint32_t ah[4], al[4];
        const uint4 a4 = *(const uint4*)(wh + (kt*32 + lane)*4);
        const uint4 c4 = *(const uint4*)(wl + (kt*32 + lane)*4);
        ah[0]=a4.x; ah[1]=a4.y; ah[2]=a4.z; ah[3]=a4.w;
        al[0]=c4.x; al[1]=c4.y; al[2]=c4.z; al[3]=c4.w;
#pragma unroll
        for (int ng = 0; ng < 8; ++ng) {
            uint32_t bh[2], bl[2];
            uint2 u = *(const uint2*)(Bsh + ((kt*8 + ng)*32 + lane)*2);
            uint2 v = *(const uint2*)(Bsl + ((kt*8 + ng)*32 + lane)*2);
            bh[0]=u.x; bh[1]=u.y; bl[0]=v.x; bl[1]=v.y;
            mma16816(acc[ng], ah, bh);
            mma16816(acc[ng], al, bh);
            mma16816(acc[ng], ah, bl);
        }
    }
}
__device__ __forceinline__ void bfrag_store(uint32_t* Bsh, uint32_t* Bsl,
                                            int c, int n, float v0, float v1) {
    uint32_t h, l; split_pack(v0, v1, h, l);
    int kt = c >> 4, kk = c & 15;
    int ng = n >> 3;
    int reg  = (kk & 8) ? 1 : 0;
    int lane = (n & 7)*4 + ((kk & 7) >> 1);
    int idx = ((kt*8 + ng)*32 + lane)*2 + reg;
    Bsh[idx] = h; Bsl[idx] = l;
}
__device__ __forceinline__ void dfrag_to_cs(float* Cs, const float acc[8][4],
                                            int w, int lane) {
    int g = lane >> 2, tig = lane & 3;
#pragma unroll
    for (int ng = 0; ng < 8; ++ng) {
        float* r0 = Cs + (w*16 + g)*65 + ng*8 + tig*2;
        float* r1 = Cs + (w*16 + 8 + g)*65 + ng*8 + tig*2;
        r0[0] = acc[ng][0]; r0[1] = acc[ng][1];
        r1[0] = acc[ng][2]; r1[1] = acc[ng][3];
    }
}

#define GSM_ ((4096 + 4096)*4 + 128*65*4)    // 66048 B

// ============ stage1: [0,200) Q-GEMM, [200,250) SR conv =========================
__global__ __launch_bounds__(256, 2) void k_stage1(const float* __restrict__ x,
                                                   const float* __restrict__ qb,
                                                   const float* __restrict__ srb,
                                                   const float* __restrict__ bng,
                                                   const float* __restrict__ bnb,
                                                   const float* __restrict__ bnm,
                                                   const float* __restrict__ bnv) {
    extern __shared__ char smraw[];
    uint32_t* Bsh = (uint32_t*)smraw;
    uint32_t* Bsl = Bsh + 4096;
    float*    Cs  = (float*)(Bsl + 4096);
    const int tid = threadIdx.x;
    const int w   = tid >> 5, lane = tid & 31;
    const int bx  = blockIdx.x;
    const int tr = tid >> 4, tc = tid & 15;

    float acc[8][4];
#pragma unroll
    for (int i = 0; i < 8; ++i)
#pragma unroll
        for (int j = 0; j < 4; ++j) acc[i][j] = 0.f;

    if (bx < 200) {
        const int b  = bx / 100;
        const int N0 = (bx % 100) * 64;
        for (int idx = tid; idx < 64*64; idx += 256) {
            int cp = idx >> 6, n = idx & 63;
            int c = 2*cp;
            float v0 = x[(b*128 + c)*N_ + N0 + n];
            float v1 = x[(b*128 + c + 1)*N_ + N0 + n];
            bfrag_store(Bsh, Bsl, c, n, v0, v1);
        }
        __syncthreads();
        hmma_tile(g_Wq[0] + w*1024, g_Wq[1] + w*1024, Bsh, Bsl, acc, lane);
        dfrag_to_cs(Cs, acc, w, lane);
        __syncthreads();
#pragma unroll
        for (int i = 0; i < 8; i += 2) {
            int o0 = tr*8 + i;
            float b0 = qb[o0], b1 = qb[o0+1];
            int dp = (o0 & 15) >> 1;
            int bh = b*8 + (o0 >> 4);
            int tig = dp & 3;
            int reglo = (dp < 4) ? 0 : 2;
#pragma unroll
            for (int j = 0; j < 2; ++j)
#pragma unroll
                for (int e = 0; e < 2; ++e) {
                    int nn = tc*4 + 2*j + e;
                    float va = Cs[o0*65 + nn] + b0;
                    float vb = Cs[(o0+1)*65 + nn] + b1;
                    int n  = N0 + nn;
                    int qt = n >> 4, r = n & 15;
                    int reg = reglo + (r >> 3);
                    int ln = (r & 7)*4 + tig;
                    long idx = (((long)bh*400 + qt)*32 + ln)*4 + reg;
                    g_Qh[idx] = pack_f16(va*SL2E_, vb*SL2E_);
                }
        }
    } else {
        const int sidx = bx - 200;
        const int b  = sidx / 25;
        const int P0 = (sidx % 25) * 64;
        for (int kc = 0; kc < 4; ++kc) {
            __syncthreads();
            for (int idx = tid; idx < 64*64; idx += 256) {
                int cp = idx >> 6, n = idx & 63;
                int cl = 2*cp;
                int kb = kc*128 + cl;
                int c  = kb >> 2;
                int ii = (kb >> 1) & 1;
                int p  = P0 + n;
                int hp = p / 40, wp = p % 40;
                const float* base = x + ((b*128 + c)*80 + 2*hp + ii)*80 + 2*wp;
                bfrag_store(Bsh, Bsl, cl, n, base[0], base[1]);
            }
            __syncthreads();
            hmma_tile(g_Wsr[0] + (w*32 + kc*8)*128, g_Wsr[1] + (w*32 + kc*8)*128,
                      Bsh, Bsl, acc, lane);
        }
        dfrag_to_cs(Cs, acc, w, lane);
        __syncthreads();
#pragma unroll
        for (int i = 0; i < 8; ++i) {
            int o = tr*8 + i;
            float inv = bng[o] * rsqrtf(bnv[o] + 1e-5f);
            float sh  = srb[o]*inv + bnb[o] - bnm[o]*inv;
#pragma unroll
            for (int j = 0; j < 4; ++j) {
                int nn = tc*4 + j;
                float v = Cs[o*65 + nn]*inv + sh;
                g_xkv[(b*128 + o)*NKV_ + P0 + nn] = fmaxf(v, 0.f);
            }
        }
    }
}

// ============ K/V GEMM (HMMA) -> fp16 single-term fragment arrays ===============
__global__ __launch_bounds__(256, 2) void k_kv(const float* __restrict__ kb,
                                               const float* __restrict__ vb) {
    extern __shared__ char smraw[];
    uint32_t* Bsh = (uint32_t*)smraw;
    uint32_t* Bsl = Bsh + 4096;
    float*    Cs  = (float*)(Bsl + 4096);
    const int tid = threadIdx.x;
    const int w   = tid >> 5, lane = tid & 31;
    const int b  = blockIdx.y;
    const int zz = blockIdx.z;
    const int M0 = blockIdx.x * 64;
    const float* bg = zz ? vb : kb;
    const uint32_t* wh = (zz ? g_Wv[0] : g_Wk[0]) + w*1024;
    const uint32_t* wl = (zz ? g_Wv[1] : g_Wk[1]) + w*1024;

    for (int idx = tid; idx < 64*64; idx += 256) {
        int cp = idx >> 6, n = idx & 63;
        int c = 2*cp;
        float v0 = g_xkv[(b*128 + c)*NKV_ + M0 + n];
        float v1 = g_xkv[(b*128 + c + 1)*NKV_ + M0 + n];
        bfrag_store(Bsh, Bsl, c, n, v0, v1);
    }
    __syncthreads();

    float acc[8][4];
#pragma unroll
    for (int i = 0; i < 8; ++i)
#pragma unroll
        for (int j = 0; j < 4; ++j) acc[i][j] = 0.f;
    hmma_tile(wh, wl, Bsh, Bsl, acc, lane);
    dfrag_to_cs(Cs, acc, w, lane);
    __syncthreads();

    const int tr = tid >> 4, tc = tid & 15;
    if (!zz) {
#pragma unroll
        for (int i = 0; i < 8; i += 2) {
            int o0 = tr*8 + i;
            float b0 = bg[o0], b1 = bg[o0+1];
            int dp = (o0 & 15) >> 1;
            int bh = b*8 + (o0 >> 4);
            int tig = dp & 3;
            int reg = (dp < 4) ? 0 : 1;
#pragma unroll
            for (int j = 0; j < 2; ++j)
#pragma unroll
                for (int e = 0; e < 2; ++e) {
                    int nn = tc*4 + 2*j + e;
                    float va = Cs[o0*65 + nn] + b0;
                    float vb = Cs[(o0+1)*65 + nn] + b1;
                    int m = M0 + nn;
                    int kt = m >> 3;
                    int ln = (m & 7)*4 + tig;
                    long idx = (((long)bh*200 + kt)*32 + ln)*2 + reg;
                    g_Kh[idx] = pack_f16(va, vb);
                }
        }
    } else {
#pragma unroll
        for (int i = 0; i < 8; ++i) {
            int o = tr*8 + i;
            float bias = bg[o];
            int d = o & 15;
            int bh = b*8 + (o >> 4);
            int dh = d >> 3;
#pragma unroll
            for (int j = 0; j < 2; ++j) {
                int nn = tc*4 + 2*j;
                float v0 = Cs[o*65 + nn] + bias;
                float v1 = Cs[o*65 + nn + 1] + bias;
                int m0 = M0 + nn;
                int ml = m0 & 15;
                int reg  = (ml < 8) ? 0 : 1;
                int tigv = (ml & 7) >> 1;
                int vt = m0 >> 4;
                int ln = (d & 7)*4 + tigv;
                long idx = ((((long)bh*100 + vt)*2 + dh)*32 + ln)*2 + reg;
                g_Vh[idx] = pack_f16(v0, v1);
            }
        }
    }
}

// ============ fp16 single-term HMMA flash attention =============================
__global__ __launch_bounds__(256, 3) void k_attn() {
    __shared__ uint32_t smK[2][1024];
    __shared__ uint32_t smV[2][1024];
    const int tid  = threadIdx.x;
    const int w    = tid >> 5;
    const int lane = tid & 31;
    const int g    = lane >> 2, tig = lane & 3;
    const int bh   = blockIdx.y;
    const int blk  = blockIdx.x;

    uint32_t qh[2][4];
    int qt[2] = {blk*16 + w, blk*16 + 8 + w};
#pragma unroll
    for (int t = 0; t < 2; ++t) {
        const uint4 a = *(const uint4*)(g_Qh + (((long)bh*400 + qt[t])*32 + lane)*4);
        qh[t][0]=a.x; qh[t][1]=a.y; qh[t][2]=a.z; qh[t][3]=a.w;
    }
    float acc[2][2][4];
    float la[2] = {0.f, 0.f}, lb[2] = {0.f, 0.f};
#pragma unroll
    for (int t = 0; t < 2; ++t)
#pragma unroll
        for (int d = 0; d < 2; ++d)
#pragma unroll
            for (int r = 0; r < 4; ++r) acc[t][d][r] = 0.f;

    auto copy_chunk = [&](int buf, int c) {
        const int nq = (c == 12) ? 128 : 256;
        const uint4* kh = (const uint4*)(g_Kh + ((long)bh*200 + c*16)*64);
        const uint4* vh = (const uint4*)(g_Vh + ((long)bh*100 + c*8)*128);
        uint4* dkh = (uint4*)smK[buf];
        uint4* dvh = (uint4*)smV[buf];
        for (int i = tid; i < nq; i += 256) {
            dkh[i] = kh[i]; dvh[i] = vh[i];
        }
    };

    copy_chunk(0, 0);
    __syncthreads();

    for (int c = 0; c < 13; ++c) {
        const int buf = c & 1;
        if (c < 12) copy_chunk(buf ^ 1, c + 1);
        const int ngrp = (c == 12) ? 4 : 8;
        const uint32_t* Ksh = smK[buf];
        const uint32_t* Vsh = smV[buf];

        for (int gg = 0; gg < ngrp; ++gg) {
            uint32_t k0[2], k1[2];
            {
                uint2 x0 = *(const uint2*)(Ksh + (gg*2)*64 + lane*2);
                uint2 x1 = *(const uint2*)(Ksh + (gg*2+1)*64 + lane*2);
                k0[0]=x0.x; k0[1]=x0.y; k1[0]=x1.x; k1[1]=x1.y;
            }
            uint32_t vh0[2], vh1[2];
            {
                uint2 x0 = *(const uint2*)(Vsh + (gg*2)*64 + lane*2);
                uint2 x1 = *(const uint2*)(Vsh + (gg*2+1)*64 + lane*2);
                vh0[0]=x0.x; vh0[1]=x0.y; vh1[0]=x1.x; vh1[1]=x1.y;
            }
#pragma unroll
            for (int t = 0; t < 2; ++t) {
                float d0[4] = {0.f,0.f,0.f,0.f}, d1[4] = {0.f,0.f,0.f,0.f};
                mma16816f(d0, qh[t], k0);
                mma16816f(d1, qh[t], k1);
                float e00 = ex2(d0[0] - SHIFT_), e01 = ex2(d0[1] - SHIFT_);
                float e02 = ex2(d0[2] - SHIFT_), e03 = ex2(d0[3] - SHIFT_);
                float e10 = ex2(d1[0] - SHIFT_), e11 = ex2(d1[1] - SHIFT_);
                float e12 = ex2(d1[2] - SHIFT_), e13 = ex2(d1[3] - SHIFT_);
                la[t] += (e00 + e01) + (e10 + e11);
                lb[t] += (e02 + e03) + (e12 + e13);
                uint32_t p[4];
                p[0] = pack_f16(e00, e01);
                p[1] = pack_f16(e02, e03);
                p[2] = pack_f16(e10, e11);
                p[3] = pack_f16(e12, e13);
                mma16816f(acc[t][0], p, vh0);
                mma16816f(acc[t][1], p, vh1);
            }
        }
        __syncthreads();
    }

    const int b = bh >> 3, h = bh & 7;
#pragma unroll
    for (int t = 0; t < 2; ++t) {
        float sa = la[t];
        sa += __shfl_xor_sync(0xFFFFFFFFu, sa, 1);
        sa += __shfl_xor_sync(0xFFFFFFFFu, sa, 2);
        float sb = lb[t];
        sb += __shfl_xor_sync(0xFFFFFFFFu, sb, 1);
        sb += __shfl_xor_sync(0xFFFFFFFFu, sb, 2);
        float ia = 1.0f / sa, ib = 1.0f / sb;
        int q = qt[t]*16 + g;
        float* oA = g_attn + ((long)b*N_ + q)*128 + h*16 + tig*2;
        float* oB = g_attn + ((long)b*N_ + q + 8)*128 + h*16 + tig*2;
        *(float2*)(oA)     = make_float2(acc[t][0][0]*ia, acc[t][0][1]*ia);
        *(float2*)(oA + 8) = make_float2(acc[t][1][0]*ia, acc[t][1][1]*ia);
        *(float2*)(oB)     = make_float2(acc[t][0][2]*ib, acc[t][0][3]*ib);
        *(float2*)(oB + 8) = make_float2(acc[t][1][2]*ib, acc[t][1][3]*ib);
    }
}

// ============ proj (HMMA) =======================================================
__global__ __launch_bounds__(256, 2) void k_proj(const float* __restrict__ pb,
                                                 float* __restrict__ out) {
    extern __shared__ char smraw[];
    uint32_t* Bsh = (uint32_t*)smraw;
    uint32_t* Bsl = Bsh + 4096;
    float*    Cs  = (float*)(Bsl + 4096);
    const int tid = threadIdx.x;
    const int w   = tid >> 5, lane = tid & 31;
    const int b  = blockIdx.y;
    const int P0 = blockIdx.x * 64;
    const float* gA = g_attn + (long)b*N_*128;

    for (int idx = tid; idx < 64*64; idx += 256) {
        int cp = idx >> 6, n = idx & 63;
        int c = 2*cp;
        long f = (long)c*N_ + P0 + n;
        float v0 = gA[f];
        float v1 = gA[f + N_];
        bfrag_store(Bsh, Bsl, c, n, v0, v1);
    }
    __syncthreads();

    float acc[8][4];
#pragma unroll
    for (int i = 0; i < 8; ++i)
#pragma unroll
        for (int j = 0; j < 4; ++j) acc[i][j] = 0.f;
    hmma_tile(g_Wp[0] + w*1024, g_Wp[1] + w*1024, Bsh, Bsl, acc, lane);
    dfrag_to_cs(Cs, acc, w, lane);
    __syncthreads();

    const int tr = tid >> 4, tc = tid & 15;
#pragma unroll
    for (int i = 0; i < 8; ++i) {
        int o = tr*8 + i;
        float bias = pb[o];
        long rowbase = ((long)b*128 + o)*N_ + P0 + tc*4;
#pragma unroll
        for (int j = 0; j < 2; ++j) {
            float v0 = Cs[o*65 + tc*4 + 2*j]     + bias;
            float v1 = Cs[o*65 + tc*4 + 2*j + 1] + bias;
            *(float2*)(out + rowbase + 2*j) = make_float2(v0, v1);
        }
    }
}

// ---------------- launch ----------------
extern "C" void kernel_launch(void* const* d_in, const int* in_sizes, int n_in,
                              void* d_out, int out_size) {
    const float* x    = (const float*)d_in[0];
    const float* q_w  = (const float*)d_in[1];
    const float* q_b  = (const float*)d_in[2];
    const float* k_w  = (const float*)d_in[3];
    const float* k_b  = (const float*)d_in[4];
    const float* v_w  = (const float*)d_in[5];
    const float* v_b  = (const float*)d_in[6];
    const float* sr_w = (const float*)d_in[7];
    const float* sr_b = (const float*)d_in[8];
    const float* bn_g = (const float*)d_in[9];
    const float* bn_b = (const float*)d_in[10];
    const float* bn_m = (const float*)d_in[11];
    const float* bn_v = (const float*)d_in[12];
    const float* p_w  = (const float*)d_in[13];
    const float* p_b  = (const float*)d_in[14];
    float* out = (float*)d_out;

    cudaFuncSetAttribute(k_stage1, cudaFuncAttributeMaxDynamicSharedMemorySize, GSM_);
    cudaFuncSetAttribute(k_kv,     cudaFuncAttributeMaxDynamicSharedMemorySize, GSM_);
    cudaFuncSetAttribute(k_proj,   cudaFuncAttributeMaxDynamicSharedMemorySize, GSM_);

    k_prep  <<<32, 256>>>(q_w, k_w, v_w, p_w, sr_w);
    k_stage1<<<250, 256, GSM_>>>(x, q_b, sr_b, bn_g, bn_b, bn_m, bn_v);
    k_kv    <<<dim3(25, B_, 2), 256, GSM_>>>(k_b, v_b);
    k_attn  <<<dim3(25, 16), 256>>>();
    k_proj  <<<dim3(100, B_), 256, GSM_>>>(p_b, out);
}

// round 10
// speedup vs baseline: 7.0117x; 1.1582x over previous
#include <cuda_runtime.h>
#include <cuda_bf16.h>
#include <cstdint>

#define B_    2
#define DIM_  128
#define N_    6400
#define NKV_  1600
#define SL2E_ 0.3606737602f   // 0.25 * log2(e)
#define SHIFT_ 16.0f

typedef unsigned long long u64;

// ---------------- helpers ----------------
// bf16 split (weights / GEMM stages): a -> low half, b -> high half
__device__ __forceinline__ void split_pack(float a, float b, uint32_t& hi, uint32_t& lo) {
    uint32_t h; asm("cvt.rn.bf16x2.f32 %0, %1, %2;" : "=r"(h) : "f"(b), "f"(a));
    float fa = __uint_as_float(h << 16);
    float fb = __uint_as_float(h & 0xFFFF0000u);
    float ra = a - fa, rb = b - fb;
    uint32_t l_; asm("cvt.rn.bf16x2.f32 %0, %1, %2;" : "=r"(l_) : "f"(rb), "f"(ra));
    hi = h; lo = l_;
}
// fp16 pack: a -> low half, b -> high half
__device__ __forceinline__ uint32_t pack_f16(float a, float b) {
    uint32_t h; asm("cvt.rn.f16x2.f32 %0, %1, %2;" : "=r"(h) : "f"(b), "f"(a));
    return h;
}
// packed 2-way fp16 exp2 (MUFU, one op for two exps)
__device__ __forceinline__ uint32_t ex2h2(uint32_t x) {
    uint32_t y; asm("ex2.approx.f16x2 %0, %1;" : "=r"(y) : "r"(x));
    return y;
}
// ---------------- HMMA m16n8k16 ----------------
__device__ __forceinline__ void mma16816(float d[4], const uint32_t a[4], const uint32_t b[2]) {
    asm("mma.sync.aligned.m16n8k16.row.col.f32.bf16.bf16.f32 "
        "{%0,%1,%2,%3}, {%4,%5,%6,%7}, {%8,%9}, {%0,%1,%2,%3};"
        : "+f"(d[0]), "+f"(d[1]), "+f"(d[2]), "+f"(d[3])
        : "r"(a[0]), "r"(a[1]), "r"(a[2]), "r"(a[3]), "r"(b[0]), "r"(b[1]));
}
__device__ __forceinline__ void mma16816f(float d[4], const uint32_t a[4], const uint32_t b[2]) {
    asm("mma.sync.aligned.m16n8k16.row.col.f32.f16.f16.f32 "
        "{%0,%1,%2,%3}, {%4,%5,%6,%7}, {%8,%9}, {%0,%1,%2,%3};"
        : "+f"(d[0]), "+f"(d[1]), "+f"(d[2]), "+f"(d[3])
        : "r"(a[0]), "r"(a[1]), "r"(a[2]), "r"(a[3]), "r"(b[0]), "r"(b[1]));
}

// ---------------- scratch ----------------
__device__ uint32_t g_Qh[16*400*32*4];          // fp16 single-term Q (pre-scaled)
__device__ uint32_t g_Kh[16*200*32*2];          // fp16 single-term K
__device__ uint32_t g_Vh[16*100*2*32*2];        // fp16 single-term V
__device__ float g_xkv[B_*DIM_*NKV_];
__device__ float g_attn[B_*N_*DIM_];
// weight fragments (bf16 2-term): [split][(mt*KT+kt)*32 + lane][4]
__device__ uint32_t g_Wq[2][8*8*32*4];
__device__ uint32_t g_Wk[2][8*8*32*4];
__device__ uint32_t g_Wv[2][8*8*32*4];
__device__ uint32_t g_Wp[2][8*8*32*4];
__device__ uint32_t g_Wsr[2][8*32*32*4];

// ============ weight prep ======================================================
__global__ __launch_bounds__(256) void k_prep(const float* __restrict__ qw,
                                              const float* __restrict__ kw,
                                              const float* __restrict__ vw,
                                              const float* __restrict__ pw,
                                              const float* __restrict__ srw) {
    int bx = blockIdx.x, tid = threadIdx.x;
    const float* src; uint32_t *dh, *dl; int K, b0;
    if (bx < 4)       { src = qw;  dh = g_Wq[0];  dl = g_Wq[1];  K = 128; b0 = bx; }
    else if (bx < 8)  { src = kw;  dh = g_Wk[0];  dl = g_Wk[1];  K = 128; b0 = bx - 4; }
    else if (bx < 12) { src = vw;  dh = g_Wv[0];  dl = g_Wv[1];  K = 128; b0 = bx - 8; }
    else if (bx < 16) { src = pw;  dh = g_Wp[0];  dl = g_Wp[1];  K = 128; b0 = bx - 12; }
    else              { src = srw; dh = g_Wsr[0]; dl = g_Wsr[1]; K = 512; b0 = bx - 16; }
    const int KT = K >> 4;
    const int KP = K >> 1;
    for (int p = b0*2048 + tid; p < (b0 + 1)*2048; p += 256) {
        int o = p / KP, cp = p % KP;
        int c = cp * 2;
        float v0 = src[o*K + c], v1 = src[o*K + c + 1];
        uint32_t h, l; split_pack(v0, v1, h, l);
        int mt = o >> 4, r = o & 15;
        int kt = c >> 4, kk = c & 15;
        int reg  = ((kk & 8) ? 2 : 0) + (r >> 3);
        int lane = (r & 7)*4 + ((kk & 7) >> 1);
        long idx = (((long)mt*KT + kt)*32 + lane)*4 + reg;
        dh[idx] = h; dl[idx] = l;
    }
}

// ---------------- common HMMA mainloop (bf16, GEMM stages) ----------------------
__device__ __forceinline__ void hmma_tile(const uint32_t* __restrict__ wh,
                                          const uint32_t* __restrict__ wl,
                                          const uint32_t* __restrict__ Bsh,
                                          const uint32_t* __restrict__ Bsl,
                                          float acc[8][4], int lane) {
#pragma unroll
    for (int kt = 0; kt < 8; ++kt) {
        uint32_t ah[4], al[4];
        const uint4 a4 = *(const uint4*)(wh + (kt*32 + lane)*4);
        const uint4 c4 = *(const uint4*)(wl + (kt*32 + lane)*4);
        ah[0]=a4.x; ah[1]=a4.y; ah[2]=a4.z; ah[3]=a4.w;
        al[0]=c4.x; al[1]=c4.y; al[2]=c4.z; al[3]=c4.w;
#pragma unroll
        for (int ng = 0; ng < 8; ++ng) {
            uint32_t bh[2], bl[2];
            uint2 u = *(const uint2*)(Bsh + ((kt*8 + ng)*32 + lane)*2);
            uint2 v = *(const uint2*)(Bsl + ((kt*8 + ng)*32 + lane)*2);
            bh[0]=u.x; bh[1]=u.y; bl[0]=v.x; bl[1]=v.y;
            mma16816(acc[ng], ah, bh);
            mma16816(acc[ng], al, bh);
            mma16816(acc[ng], ah, bl);
        }
    }
}
__device__ __forceinline__ void bfrag_store(uint32_t* Bsh, uint32_t* Bsl,
                                            int c, int n, float v0, float v1) {
    uint32_t h, l; split_pack(v0, v1, h, l);
    int kt = c >> 4, kk = c & 15;
    int ng = n >> 3;
    int reg  = (kk & 8) ? 1 : 0;
    int lane = (n & 7)*4 + ((kk & 7) >> 1);
    int idx = ((kt*8 + ng)*32 + lane)*2 + reg;
    Bsh[idx] = h; Bsl[idx] = l;
}
__device__ __forceinline__ void dfrag_to_cs(float* Cs, const float acc[8][4],
                                            int w, int lane) {
    int g = lane >> 2, tig = lane & 3;
#pragma unroll
    for (int ng = 0; ng < 8; ++ng) {
        float* r0 = Cs + (w*16 + g)*65 + ng*8 + tig*2;
        float* r1 = Cs + (w*16 + 8 + g)*65 + ng*8 + tig*2;
        r0[0] = acc[ng][0]; r0[1] = acc[ng][1];
        r1[0] = acc[ng][2]; r1[1] = acc[ng][3];
    }
}

#define GSM_ ((4096 + 4096)*4 + 128*65*4)    // 66048 B

// ============ stage1: [0,200) Q-GEMM, [200,250) SR conv =========================
__global__ __launch_bounds__(256, 2) void k_stage1(const float* __restrict__ x,
                                                   const float* __restrict__ qb,
                                                   const float* __restrict__ srb,
                                                   const float* __restrict__ bng,
                                                   const float* __restrict__ bnb,
                                                   const float* __restrict__ bnm,
                                                   const float* __restrict__ bnv) {
    extern __shared__ char smraw[];
    uint32_t* Bsh = (uint32_t*)smraw;
    uint32_t* Bsl = Bsh + 4096;
    float*    Cs  = (float*)(Bsl + 4096);
    const int tid = threadIdx.x;
    const int w   = tid >> 5, lane = tid & 31;
    const int bx  = blockIdx.x;
    const int tr = tid >> 4, tc = tid & 15;

    float acc[8][4];
#pragma unroll
    for (int i = 0; i < 8; ++i)
#pragma unroll
        for (int j = 0; j < 4; ++j) acc[i][j] = 0.f;

    if (bx < 200) {
        const int b  = bx / 100;
        const int N0 = (bx % 100) * 64;
        for (int idx = tid; idx < 64*64; idx += 256) {
            int cp = idx >> 6, n = idx & 63;
            int c = 2*cp;
            float v0 = x[(b*128 + c)*N_ + N0 + n];
            float v1 = x[(b*128 + c + 1)*N_ + N0 + n];
            bfrag_store(Bsh, Bsl, c, n, v0, v1);
        }
        __syncthreads();
        hmma_tile(g_Wq[0] + w*1024, g_Wq[1] + w*1024, Bsh, Bsl, acc, lane);
        dfrag_to_cs(Cs, acc, w, lane);
        __syncthreads();
#pragma unroll
        for (int i = 0; i < 8; i += 2) {
            int o0 = tr*8 + i;
            float b0 = qb[o0], b1 = qb[o0+1];
            int dp = (o0 & 15) >> 1;
            int bh = b*8 + (o0 >> 4);
            int tig = dp & 3;
            int reglo = (dp < 4) ? 0 : 2;
#pragma unroll
            for (int j = 0; j < 2; ++j)
#pragma unroll
                for (int e = 0; e < 2; ++e) {
                    int nn = tc*4 + 2*j + e;
                    float va = Cs[o0*65 + nn] + b0;
                    float vb = Cs[(o0+1)*65 + nn] + b1;
                    int n  = N0 + nn;
                    int qt = n >> 4, r = n & 15;
                    int reg = reglo + (r >> 3);
                    int ln = (r & 7)*4 + tig;
                    long idx = (((long)bh*400 + qt)*32 + ln)*4 + reg;
                    g_Qh[idx] = pack_f16(va*SL2E_, vb*SL2E_);
                }
        }
    } else {
        const int sidx = bx - 200;
        const int b  = sidx / 25;
        const int P0 = (sidx % 25) * 64;
        for (int kc = 0; kc < 4; ++kc) {
            __syncthreads();
            for (int idx = tid; idx < 64*64; idx += 256) {
                int cp = idx >> 6, n = idx & 63;
                int cl = 2*cp;
                int kb = kc*128 + cl;
                int c  = kb >> 2;
                int ii = (kb >> 1) & 1;
                int p  = P0 + n;
                int hp = p / 40, wp = p % 40;
                const float* base = x + ((b*128 + c)*80 + 2*hp + ii)*80 + 2*wp;
                bfrag_store(Bsh, Bsl, cl, n, base[0], base[1]);
            }
            __syncthreads();
            hmma_tile(g_Wsr[0] + (w*32 + kc*8)*128, g_Wsr[1] + (w*32 + kc*8)*128,
                      Bsh, Bsl, acc, lane);
        }
        dfrag_to_cs(Cs, acc, w, lane);
        __syncthreads();
#pragma unroll
        for (int i = 0; i < 8; ++i) {
            int o = tr*8 + i;
            float inv = bng[o] * rsqrtf(bnv[o] + 1e-5f);
            float sh  = srb[o]*inv + bnb[o] - bnm[o]*inv;
#pragma unroll
            for (int j = 0; j < 4; ++j) {
                int nn = tc*4 + j;
                float v = Cs[o*65 + nn]*inv + sh;
                g_xkv[(b*128 + o)*NKV_ + P0 + nn] = fmaxf(v, 0.f);
            }
        }
    }
}

// ============ K/V GEMM (HMMA) -> fp16 single-term fragment arrays ===============
__global__ __launch_bounds__(256, 2) void k_kv(const float* __restrict__ kb,
                                               const float* __restrict__ vb) {
    extern __shared__ char smraw[];
    uint32_t* Bsh = (uint32_t*)smraw;
    uint32_t* Bsl = Bsh + 4096;
    float*    Cs  = (float*)(Bsl + 4096);
    const int tid = threadIdx.x;
    const int w   = tid >> 5, lane = tid & 31;
    const int b  = blockIdx.y;
    const int zz = blockIdx.z;
    const int M0 = blockIdx.x * 64;
    const float* bg = zz ? vb : kb;
    const uint32_t* wh = (zz ? g_Wv[0] : g_Wk[0]) + w*1024;
    const uint32_t* wl = (zz ? g_Wv[1] : g_Wk[1]) + w*1024;

    for (int idx = tid; idx < 64*64; idx += 256) {
        int cp = idx >> 6, n = idx & 63;
        int c = 2*cp;
        float v0 = g_xkv[(b*128 + c)*NKV_ + M0 + n];
        float v1 = g_xkv[(b*128 + c + 1)*NKV_ + M0 + n];
        bfrag_store(Bsh, Bsl, c, n, v0, v1);
    }
    __syncthreads();

    float acc[8][4];
#pragma unroll
    for (int i = 0; i < 8; ++i)
#pragma unroll
        for (int j = 0; j < 4; ++j) acc[i][j] = 0.f;
    hmma_tile(wh, wl, Bsh, Bsl, acc, lane);
    dfrag_to_cs(Cs, acc, w, lane);
    __syncthreads();

    const int tr = tid >> 4, tc = tid & 15;
    if (!zz) {
#pragma unroll
        for (int i = 0; i < 8; i += 2) {
            int o0 = tr*8 + i;
            float b0 = bg[o0], b1 = bg[o0+1];
            int dp = (o0 & 15) >> 1;
            int bh = b*8 + (o0 >> 4);
            int tig = dp & 3;
            int reg = (dp < 4) ? 0 : 1;
#pragma unroll
            for (int j = 0; j < 2; ++j)
#pragma unroll
                for (int e = 0; e < 2; ++e) {
                    int nn = tc*4 + 2*j + e;
                    float va = Cs[o0*65 + nn] + b0;
                    float vb = Cs[(o0+1)*65 + nn] + b1;
                    int m = M0 + nn;
                    int kt = m >> 3;
                    int ln = (m & 7)*4 + tig;
                    long idx = (((long)bh*200 + kt)*32 + ln)*2 + reg;
                    g_Kh[idx] = pack_f16(va, vb);
                }
        }
    } else {
#pragma unroll
        for (int i = 0; i < 8; ++i) {
            int o = tr*8 + i;
            float bias = bg[o];
            int d = o & 15;
            int bh = b*8 + (o >> 4);
            int dh = d >> 3;
#pragma unroll
            for (int j = 0; j < 2; ++j) {
                int nn = tc*4 + 2*j;
                float v0 = Cs[o*65 + nn] + bias;
                float v1 = Cs[o*65 + nn + 1] + bias;
                int m0 = M0 + nn;
                int ml = m0 & 15;
                int reg  = (ml < 8) ? 0 : 1;
                int tigv = (ml & 7) >> 1;
                int vt = m0 >> 4;
                int ln = (d & 7)*4 + tigv;
                long idx = ((((long)bh*100 + vt)*2 + dh)*32 + ln)*2 + reg;
                g_Vh[idx] = pack_f16(v0, v1);
            }
        }
    }
}

// ============ fp16 HMMA flash attention: f16x2 exp + ones-MMA row sums ==========
__global__ __launch_bounds__(256, 3) void k_attn() {
    __shared__ uint32_t smK[2][1024];
    __shared__ uint32_t smV[2][1024];
    const int tid  = threadIdx.x;
    const int w    = tid >> 5;
    const int lane = tid & 31;
    const int g    = lane >> 2, tig = lane & 3;
    const int bh   = blockIdx.y;
    const int blk  = blockIdx.x;
    const uint32_t ones[2] = {0x3C003C00u, 0x3C003C00u};   // f16 1.0 x4

    uint32_t qh[2][4];
    int qt[2] = {blk*16 + w, blk*16 + 8 + w};
#pragma unroll
    for (int t = 0; t < 2; ++t) {
        const uint4 a = *(const uint4*)(g_Qh + (((long)bh*400 + qt[t])*32 + lane)*4);
        qh[t][0]=a.x; qh[t][1]=a.y; qh[t][2]=a.z; qh[t][3]=a.w;
    }
    float acc[2][2][4];
    float lacc[2][4];
#pragma unroll
    for (int t = 0; t < 2; ++t) {
#pragma unroll
        for (int d = 0; d < 2; ++d)
#pragma unroll
            for (int r = 0; r < 4; ++r) acc[t][d][r] = 0.f;
#pragma unroll
        for (int r = 0; r < 4; ++r) lacc[t][r] = 0.f;
    }

    auto copy_chunk = [&](int buf, int c) {
        const int nq = (c == 12) ? 128 : 256;
        const uint4* kh = (const uint4*)(g_Kh + ((long)bh*200 + c*16)*64);
        const uint4* vh = (const uint4*)(g_Vh + ((long)bh*100 + c*8)*128);
        uint4* dkh = (uint4*)smK[buf];
        uint4* dvh = (uint4*)smV[buf];
        for (int i = tid; i < nq; i += 256) {
            dkh[i] = kh[i]; dvh[i] = vh[i];
        }
    };

    copy_chunk(0, 0);
    __syncthreads();

    for (int c = 0; c < 13; ++c) {
        const int buf = c & 1;
        if (c < 12) copy_chunk(buf ^ 1, c + 1);
        const int ngrp = (c == 12) ? 4 : 8;
        const uint32_t* Ksh = smK[buf];
        const uint32_t* Vsh = smV[buf];

        for (int gg = 0; gg < ngrp; ++gg) {
            uint32_t k0[2], k1[2];
            {
                uint2 x0 = *(const uint2*)(Ksh + (gg*2)*64 + lane*2);
                uint2 x1 = *(const uint2*)(Ksh + (gg*2+1)*64 + lane*2);
                k0[0]=x0.x; k0[1]=x0.y; k1[0]=x1.x; k1[1]=x1.y;
            }
            uint32_t vh0[2], vh1[2];
            {
                uint2 x0 = *(const uint2*)(Vsh + (gg*2)*64 + lane*2);
                uint2 x1 = *(const uint2*)(Vsh + (gg*2+1)*64 + lane*2);
                vh0[0]=x0.x; vh0[1]=x0.y; vh1[0]=x1.x; vh1[1]=x1.y;
            }
#pragma unroll
            for (int t = 0; t < 2; ++t) {
                float d0[4] = {-SHIFT_,-SHIFT_,-SHIFT_,-SHIFT_};
                float d1[4] = {-SHIFT_,-SHIFT_,-SHIFT_,-SHIFT_};
                mma16816f(d0, qh[t], k0);
                mma16816f(d1, qh[t], k1);
                uint32_t p[4];
                p[0] = ex2h2(pack_f16(d0[0], d0[1]));
                p[1] = ex2h2(pack_f16(d0[2], d0[3]));
                p[2] = ex2h2(pack_f16(d1[0], d1[1]));
                p[3] = ex2h2(pack_f16(d1[2], d1[3]));
                mma16816f(lacc[t], p, ones);
                mma16816f(acc[t][0], p, vh0);
                mma16816f(acc[t][1], p, vh1);
            }
        }
        __syncthreads();
    }

    const int b = bh >> 3, h = bh & 7;
#pragma unroll
    for (int t = 0; t < 2; ++t) {
        float ia = 1.0f / lacc[t][0];    // full row sum (rows g)
        float ib = 1.0f / lacc[t][2];    // full row sum (rows g+8)
        int q = qt[t]*16 + g;
        float* oA = g_attn + ((long)b*N_ + q)*128 + h*16 + tig*2;
        float* oB = g_attn + ((long)b*N_ + q + 8)*128 + h*16 + tig*2;
        *(float2*)(oA)     = make_float2(acc[t][0][0]*ia, acc[t][0][1]*ia);
        *(float2*)(oA + 8) = make_float2(acc[t][1][0]*ia, acc[t][1][1]*ia);
        *(float2*)(oB)     = make_float2(acc[t][0][2]*ib, acc[t][0][3]*ib);
        *(float2*)(oB + 8) = make_float2(acc[t][1][2]*ib, acc[t][1][3]*ib);
    }
}

// ============ proj (HMMA) =======================================================
__global__ __launch_bounds__(256, 2) void k_proj(const float* __restrict__ pb,
                                                 float* __restrict__ out) {
    extern __shared__ char smraw[];
    uint32_t* Bsh = (uint32_t*)smraw;
    uint32_t* Bsl = Bsh + 4096;
    float*    Cs  = (float*)(Bsl + 4096);
    const int tid = threadIdx.x;
    const int w   = tid >> 5, lane = tid & 31;
    const int b  = blockIdx.y;
    const int P0 = blockIdx.x * 64;
    const float* gA = g_attn + (long)b*N_*128;

    for (int idx = tid; idx < 64*64; idx += 256) {
        int cp = idx >> 6, n = idx & 63;
        int c = 2*cp;
        long f = (long)c*N_ + P0 + n;
        float v0 = gA[f];
        float v1 = gA[f + N_];
        bfrag_store(Bsh, Bsl, c, n, v0, v1);
    }
    __syncthreads();

    float acc[8][4];
#pragma unroll
    for (int i = 0; i < 8; ++i)
#pragma unroll
        for (int j = 0; j < 4; ++j) acc[i][j] = 0.f;
    hmma_tile(g_Wp[0] + w*1024, g_Wp[1] + w*1024, Bsh, Bsl, acc, lane);
    dfrag_to_cs(Cs, acc, w, lane);
    __syncthreads();

    const int tr = tid >> 4, tc = tid & 15;
#pragma unroll
    for (int i = 0; i < 8; ++i) {
        int o = tr*8 + i;
        float bias = pb[o];
        long rowbase = ((long)b*128 + o)*N_ + P0 + tc*4;
#pragma unroll
        for (int j = 0; j < 2; ++j) {
            float v0 = Cs[o*65 + tc*4 + 2*j]     + bias;
            float v1 = Cs[o*65 + tc*4 + 2*j + 1] + bias;
            *(float2*)(out + rowbase + 2*j) = make_float2(v0, v1);
        }
    }
}

// ---------------- launch ----------------
extern "C" void kernel_launch(void* const* d_in, const int* in_sizes, int n_in,
                              void* d_out, int out_size) {
    const float* x    = (const float*)d_in[0];
    const float* q_w  = (const float*)d_in[1];
    const float* q_b  = (const float*)d_in[2];
    const float* k_w  = (const float*)d_in[3];
    const float* k_b  = (const float*)d_in[4];
    const float* v_w  = (const float*)d_in[5];
    const float* v_b  = (const float*)d_in[6];
    const float* sr_w = (const float*)d_in[7];
    const float* sr_b = (const float*)d_in[8];
    const float* bn_g = (const float*)d_in[9];
    const float* bn_b = (const float*)d_in[10];
    const float* bn_m = (const float*)d_in[11];
    const float* bn_v = (const float*)d_in[12];
    const float* p_w  = (const float*)d_in[13];
    const float* p_b  = (const float*)d_in[14];
    float* out = (float*)d_out;

    cudaFuncSetAttribute(k_stage1, cudaFuncAttributeMaxDynamicSharedMemorySize, GSM_);
    cudaFuncSetAttribute(k_kv,     cudaFuncAttributeMaxDynamicSharedMemorySize, GSM_);
    cudaFuncSetAttribute(k_proj,   cudaFuncAttributeMaxDynamicSharedMemorySize, GSM_);

    k_prep  <<<32, 256>>>(q_w, k_w, v_w, p_w, sr_w);
    k_stage1<<<250, 256, GSM_>>>(x, q_b, sr_b, bn_g, bn_b, bn_m, bn_v);
    k_kv    <<<dim3(25, B_, 2), 256, GSM_>>>(k_b, v_b);
    k_attn  <<<dim3(25, 16), 256>>>();
    k_proj  <<<dim3(100, B_), 256, GSM_>>>(p_b, out);
}

// round 11
// speedup vs baseline: 7.3436x; 1.0473x over previous
#include <cuda_runtime.h>
#include <cuda_bf16.h>
#include <cstdint>

#define B_    2
#define DIM_  128
#define N_    6400
#define NKV_  1600
#define SL2E_ 0.3606737602f   // 0.25 * log2(e)
#define SHIFT_ 16.0f

typedef unsigned long long u64;

// ---------------- helpers ----------------
// bf16 split (weights / GEMM stages): a -> low half, b -> high half
__device__ __forceinline__ void split_pack(float a, float b, uint32_t& hi, uint32_t& lo) {
    uint32_t h; asm("cvt.rn.bf16x2.f32 %0, %1, %2;" : "=r"(h) : "f"(b), "f"(a));
    float fa = __uint_as_float(h << 16);
    float fb = __uint_as_float(h & 0xFFFF0000u);
    float ra = a - fa, rb = b - fb;
    uint32_t l_; asm("cvt.rn.bf16x2.f32 %0, %1, %2;" : "=r"(l_) : "f"(rb), "f"(ra));
    hi = h; lo = l_;
}
// fp16 pack: a -> low half, b -> high half
__device__ __forceinline__ uint32_t pack_f16(float a, float b) {
    uint32_t h; asm("cvt.rn.f16x2.f32 %0, %1, %2;" : "=r"(h) : "f"(b), "f"(a));
    return h;
}
// packed 2-way fp16 exp2
__device__ __forceinline__ uint32_t ex2h2(uint32_t x) {
    uint32_t y; asm("ex2.approx.f16x2 %0, %1;" : "=r"(y) : "r"(x));
    return y;
}
// ---------------- HMMA m16n8k16 ----------------
__device__ __forceinline__ void mma16816(float d[4], const uint32_t a[4], const uint32_t b[2]) {
    asm("mma.sync.aligned.m16n8k16.row.col.f32.bf16.bf16.f32 "
        "{%0,%1,%2,%3}, {%4,%5,%6,%7}, {%8,%9}, {%0,%1,%2,%3};"
        : "+f"(d[0]), "+f"(d[1]), "+f"(d[2]), "+f"(d[3])
        : "r"(a[0]), "r"(a[1]), "r"(a[2]), "r"(a[3]), "r"(b[0]), "r"(b[1]));
}
__device__ __forceinline__ void mma16816f(float d[4], const uint32_t a[4], const uint32_t b[2]) {
    asm("mma.sync.aligned.m16n8k16.row.col.f32.f16.f16.f32 "
        "{%0,%1,%2,%3}, {%4,%5,%6,%7}, {%8,%9}, {%0,%1,%2,%3};"
        : "+f"(d[0]), "+f"(d[1]), "+f"(d[2]), "+f"(d[3])
        : "r"(a[0]), "r"(a[1]), "r"(a[2]), "r"(a[3]), "r"(b[0]), "r"(b[1]));
}

// ---------------- scratch ----------------
__device__ uint32_t g_Qh[16*400*32*4];          // fp16 single-term Q (pre-scaled)
__device__ uint32_t g_Kh[16*200*32*2];          // fp16 single-term K
__device__ uint32_t g_Vh[16*100*2*32*2];        // fp16 single-term V
__device__ float g_xkvp[4][B_*DIM_*NKV_];       // SR conv raw partials (split-K x4)
__device__ float g_attn[B_*N_*DIM_];
// weight fragments (bf16 2-term): [split][(mt*KT+kt)*32 + lane][4]
__device__ uint32_t g_Wq[2][8*8*32*4];
__device__ uint32_t g_Wk[2][8*8*32*4];
__device__ uint32_t g_Wv[2][8*8*32*4];
__device__ uint32_t g_Wp[2][8*8*32*4];
__device__ uint32_t g_Wsr[2][8*32*32*4];

// ============ weight prep ======================================================
__global__ __launch_bounds__(256) void k_prep(const float* __restrict__ qw,
                                              const float* __restrict__ kw,
                                              const float* __restrict__ vw,
                                              const float* __restrict__ pw,
                                              const float* __restrict__ srw) {
    int bx = blockIdx.x, tid = threadIdx.x;
    const float* src; uint32_t *dh, *dl; int K, b0;
    if (bx < 4)       { src = qw;  dh = g_Wq[0];  dl = g_Wq[1];  K = 128; b0 = bx; }
    else if (bx < 8)  { src = kw;  dh = g_Wk[0];  dl = g_Wk[1];  K = 128; b0 = bx - 4; }
    else if (bx < 12) { src = vw;  dh = g_Wv[0];  dl = g_Wv[1];  K = 128; b0 = bx - 8; }
    else if (bx < 16) { src = pw;  dh = g_Wp[0];  dl = g_Wp[1];  K = 128; b0 = bx - 12; }
    else              { src = srw; dh = g_Wsr[0]; dl = g_Wsr[1]; K = 512; b0 = bx - 16; }
    const int KT = K >> 4;
    const int KP = K >> 1;
    for (int p = b0*2048 + tid; p < (b0 + 1)*2048; p += 256) {
        int o = p / KP, cp = p % KP;
        int c = cp * 2;
        float v0 = src[o*K + c], v1 = src[o*K + c + 1];
        uint32_t h, l; split_pack(v0, v1, h, l);
        int mt = o >> 4, r = o & 15;
        int kt = c >> 4, kk = c & 15;
        int reg  = ((kk & 8) ? 2 : 0) + (r >> 3);
        int lane = (r & 7)*4 + ((kk & 7) >> 1);
        long idx = (((long)mt*KT + kt)*32 + lane)*4 + reg;
        dh[idx] = h; dl[idx] = l;
    }
}

// ---------------- common HMMA mainloop (bf16, GEMM stages) ----------------------
__device__ __forceinline__ void hmma_tile(const uint32_t* __restrict__ wh,
                                          const uint32_t* __restrict__ wl,
                                          const uint32_t* __restrict__ Bsh,
                                          const uint32_t* __restrict__ Bsl,
                                          float acc[8][4], int lane) {
#pragma unroll
    for (int kt = 0; kt < 8; ++kt) {
        uint32_t ah[4], al[4];
        const uint4 a4 = *(const uint4*)(wh + (kt*32 + lane)*4);
        const uint4 c4 = *(const uint4*)(wl + (kt*32 + lane)*4);
        ah[0]=a4.x; ah[1]=a4.y; ah[2]=a4.z; ah[3]=a4.w;
        al[0]=c4.x; al[1]=c4.y; al[2]=c4.z; al[3]=c4.w;
#pragma unroll
        for (int ng = 0; ng < 8; ++ng) {
            uint32_t bh[2], bl[2];
            uint2 u = *(const uint2*)(Bsh + ((kt*8 + ng)*32 + lane)*2);
            uint2 v = *(const uint2*)(Bsl + ((kt*8 + ng)*32 + lane)*2);
            bh[0]=u.x; bh[1]=u.y; bl[0]=v.x; bl[1]=v.y;
            mma16816(acc[ng], ah, bh);
            mma16816(acc[ng], al, bh);
            mma16816(acc[ng], ah, bl);
        }
    }
}
__device__ __forceinline__ void bfrag_store(uint32_t* Bsh, uint32_t* Bsl,
                                            int c, int n, float v0, float v1) {
    uint32_t h, l; split_pack(v0, v1, h, l);
    int kt = c >> 4, kk = c & 15;
    int ng = n >> 3;
    int reg  = (kk & 8) ? 1 : 0;
    int lane = (n & 7)*4 + ((kk & 7) >> 1);
    int idx = ((kt*8 + ng)*32 + lane)*2 + reg;
    Bsh[idx] = h; Bsl[idx] = l;
}
__device__ __forceinline__ void dfrag_to_cs(float* Cs, const float acc[8][4],
                                            int w, int lane) {
    int g = lane >> 2, tig = lane & 3;
#pragma unroll
    for (int ng = 0; ng < 8; ++ng) {
        float* r0 = Cs + (w*16 + g)*65 + ng*8 + tig*2;
        float* r1 = Cs + (w*16 + 8 + g)*65 + ng*8 + tig*2;
        r0[0] = acc[ng][0]; r0[1] = acc[ng][1];
        r1[0] = acc[ng][2]; r1[1] = acc[ng][3];
    }
}

#define GSM_ ((4096 + 4096)*4 + 128*65*4)    // 66048 B
#define KVS_ (GSM_ + 1024)

// ============ stage1: [0,200) Q-GEMM, [200,400) SR conv split-K x4 ==============
__global__ __launch_bounds__(256, 2) void k_stage1(const float* __restrict__ x,
                                                   const float* __restrict__ qb) {
    extern __shared__ char smraw[];
    uint32_t* Bsh = (uint32_t*)smraw;
    uint32_t* Bsl = Bsh + 4096;
    float*    Cs  = (float*)(Bsl + 4096);
    const int tid = threadIdx.x;
    const int w   = tid >> 5, lane = tid & 31;
    const int bx  = blockIdx.x;
    const int tr = tid >> 4, tc = tid & 15;

    float acc[8][4];
#pragma unroll
    for (int i = 0; i < 8; ++i)
#pragma unroll
        for (int j = 0; j < 4; ++j) acc[i][j] = 0.f;

    if (bx < 200) {
        const int b  = bx / 100;
        const int N0 = (bx % 100) * 64;
        for (int idx = tid; idx < 64*64; idx += 256) {
            int cp = idx >> 6, n = idx & 63;
            int c = 2*cp;
            float v0 = x[(b*128 + c)*N_ + N0 + n];
            float v1 = x[(b*128 + c + 1)*N_ + N0 + n];
            bfrag_store(Bsh, Bsl, c, n, v0, v1);
        }
        __syncthreads();
        hmma_tile(g_Wq[0] + w*1024, g_Wq[1] + w*1024, Bsh, Bsl, acc, lane);
        dfrag_to_cs(Cs, acc, w, lane);
        __syncthreads();
#pragma unroll
        for (int i = 0; i < 8; i += 2) {
            int o0 = tr*8 + i;
            float b0 = qb[o0], b1 = qb[o0+1];
            int dp = (o0 & 15) >> 1;
            int bh = b*8 + (o0 >> 4);
            int tig = dp & 3;
            int reglo = (dp < 4) ? 0 : 2;
#pragma unroll
            for (int j = 0; j < 2; ++j)
#pragma unroll
                for (int e = 0; e < 2; ++e) {
                    int nn = tc*4 + 2*j + e;
                    float va = Cs[o0*65 + nn] + b0;
                    float vb = Cs[(o0+1)*65 + nn] + b1;
                    int n  = N0 + nn;
                    int qt = n >> 4, r = n & 15;
                    int reg = reglo + (r >> 3);
                    int ln = (r & 7)*4 + tig;
                    long idx = (((long)bh*400 + qt)*32 + ln)*4 + reg;
                    g_Qh[idx] = pack_f16(va*SL2E_, vb*SL2E_);
                }
        }
    } else {
        const int sidx = bx - 200;                 // [0,200)
        const int z  = sidx / 50;                  // K-chunk 0..3
        const int r  = sidx % 50;
        const int b  = r / 25;
        const int P0 = (r % 25) * 64;
        for (int idx = tid; idx < 64*64; idx += 256) {
            int cp = idx >> 6, n = idx & 63;
            int cl = 2*cp;
            int kb = z*128 + cl;
            int c  = kb >> 2;
            int ii = (kb >> 1) & 1;
            int p  = P0 + n;
            int hp = p / 40, wp = p % 40;
            const float* base = x + ((b*128 + c)*80 + 2*hp + ii)*80 + 2*wp;
            bfrag_store(Bsh, Bsl, cl, n, base[0], base[1]);   // jj = 0,1
        }
        __syncthreads();
        hmma_tile(g_Wsr[0] + (w*32 + z*8)*128, g_Wsr[1] + (w*32 + z*8)*128,
                  Bsh, Bsl, acc, lane);
        dfrag_to_cs(Cs, acc, w, lane);
        __syncthreads();
        float* dst = g_xkvp[z];
#pragma unroll
        for (int i = 0; i < 8; ++i) {
            int o = tr*8 + i;
#pragma unroll
            for (int j = 0; j < 4; ++j) {
                int nn = tc*4 + j;
                dst[(b*128 + o)*NKV_ + P0 + nn] = Cs[o*65 + nn];
            }
        }
    }
}

// ============ K/V GEMM: sum SR partials + BN + ReLU fused in producer ===========
__global__ __launch_bounds__(256, 2) void k_kv(const float* __restrict__ kb,
                                               const float* __restrict__ vb,
                                               const float* __restrict__ srb,
                                               const float* __restrict__ bng,
                                               const float* __restrict__ bnb,
                                               const float* __restrict__ bnm,
                                               const float* __restrict__ bnv) {
    extern __shared__ char smraw[];
    float*    s_inv = (float*)smraw;               // [128]
    float*    s_sh  = s_inv + 128;                 // [128]
    uint32_t* Bsh = (uint32_t*)(s_sh + 128);
    uint32_t* Bsl = Bsh + 4096;
    float*    Cs  = (float*)(Bsl + 4096);
    const int tid = threadIdx.x;
    const int w   = tid >> 5, lane = tid & 31;
    const int b  = blockIdx.y;
    const int zz = blockIdx.z;
    const int M0 = blockIdx.x * 64;
    const float* bg = zz ? vb : kb;
    const uint32_t* wh = (zz ? g_Wv[0] : g_Wk[0]) + w*1024;
    const uint32_t* wl = (zz ? g_Wv[1] : g_Wk[1]) + w*1024;

    if (tid < 128) {
        float inv = bng[tid] * rsqrtf(bnv[tid] + 1e-5f);
        s_inv[tid] = inv;
        s_sh[tid]  = srb[tid]*inv + bnb[tid] - bnm[tid]*inv;
    }
    __syncthreads();
    for (int idx = tid; idx < 64*64; idx += 256) {
        int cp = idx >> 6, n = idx & 63;
        int c = 2*cp;
        long f0 = (long)(b*128 + c)*NKV_ + M0 + n;
        long f1 = f0 + NKV_;
        float r0 = g_xkvp[0][f0] + g_xkvp[1][f0] + g_xkvp[2][f0] + g_xkvp[3][f0];
        float r1 = g_xkvp[0][f1] + g_xkvp[1][f1] + g_xkvp[2][f1] + g_xkvp[3][f1];
        float v0 = fmaxf(r0 * s_inv[c]   + s_sh[c],   0.f);
        float v1 = fmaxf(r1 * s_inv[c+1] + s_sh[c+1], 0.f);
        bfrag_store(Bsh, Bsl, c, n, v0, v1);
    }
    __syncthreads();

    float acc[8][4];
#pragma unroll
    for (int i = 0; i < 8; ++i)
#pragma unroll
        for (int j = 0; j < 4; ++j) acc[i][j] = 0.f;
    hmma_tile(wh, wl, Bsh, Bsl, acc, lane);
    dfrag_to_cs(Cs, acc, w, lane);
    __syncthreads();

    const int tr = tid >> 4, tc = tid & 15;
    if (!zz) {
#pragma unroll
        for (int i = 0; i < 8; i += 2) {
            int o0 = tr*8 + i;
            float b0 = bg[o0], b1 = bg[o0+1];
            int dp = (o0 & 15) >> 1;
            int bh = b*8 + (o0 >> 4);
            int tig = dp & 3;
            int reg = (dp < 4) ? 0 : 1;
#pragma unroll
            for (int j = 0; j < 2; ++j)
#pragma unroll
                for (int e = 0; e < 2; ++e) {
                    int nn = tc*4 + 2*j + e;
                    float va = Cs[o0*65 + nn] + b0;
                    float vb = Cs[(o0+1)*65 + nn] + b1;
                    int m = M0 + nn;
                    int kt = m >> 3;
                    int ln = (m & 7)*4 + tig;
                    long idx = (((long)bh*200 + kt)*32 + ln)*2 + reg;
                    g_Kh[idx] = pack_f16(va, vb);
                }
        }
    } else {
#pragma unroll
        for (int i = 0; i < 8; ++i) {
            int o = tr*8 + i;
            float bias = bg[o];
            int d = o & 15;
            int bh = b*8 + (o >> 4);
            int dh = d >> 3;
#pragma unroll
            for (int j = 0; j < 2; ++j) {
                int nn = tc*4 + 2*j;
                float v0 = Cs[o*65 + nn] + bias;
                float v1 = Cs[o*65 + nn + 1] + bias;
                int m0 = M0 + nn;
                int ml = m0 & 15;
                int reg  = (ml < 8) ? 0 : 1;
                int tigv = (ml & 7) >> 1;
                int vt = m0 >> 4;
                int ln = (d & 7)*4 + tigv;
                long idx = ((((long)bh*100 + vt)*2 + dh)*32 + ln)*2 + reg;
                g_Vh[idx] = pack_f16(v0, v1);
            }
        }
    }
}

// ============ fp16 HMMA flash attention: 256-key chunks, unrolled ==============
__global__ __launch_bounds__(256, 3) void k_attn() {
    __shared__ uint32_t smK[2][2048];
    __shared__ uint32_t smV[2][2048];
    const int tid  = threadIdx.x;
    const int w    = tid >> 5;
    const int lane = tid & 31;
    const int g    = lane >> 2, tig = lane & 3;
    const int bh   = blockIdx.y;
    const int blk  = blockIdx.x;
    const uint32_t ones[2] = {0x3C003C00u, 0x3C003C00u};   // f16 1.0 x4

    uint32_t qh[2][4];
    int qt[2] = {blk*16 + w, blk*16 + 8 + w};
#pragma unroll
    for (int t = 0; t < 2; ++t) {
        const uint4 a = *(const uint4*)(g_Qh + (((long)bh*400 + qt[t])*32 + lane)*4);
        qh[t][0]=a.x; qh[t][1]=a.y; qh[t][2]=a.z; qh[t][3]=a.w;
    }
    float acc[2][2][4];
    float lacc[2][4];
#pragma unroll
    for (int t = 0; t < 2; ++t) {
#pragma unroll
        for (int d = 0; d < 2; ++d)
#pragma unroll
            for (int r = 0; r < 4; ++r) acc[t][d][r] = 0.f;
#pragma unroll
        for (int r = 0; r < 4; ++r) lacc[t][r] = 0.f;
    }

    auto copy_chunk = [&](int buf, int c) {
        const int nq = (c == 6) ? 128 : 512;
        const uint4* kh = (const uint4*)(g_Kh + ((long)bh*200 + c*32)*64);
        const uint4* vh = (const uint4*)(g_Vh + ((long)bh*100 + c*16)*128);
        uint4* dkh = (uint4*)smK[buf];
        uint4* dvh = (uint4*)smV[buf];
        for (int i = tid; i < nq; i += 256) {
            dkh[i] = kh[i]; dvh[i] = vh[i];
        }
    };

    auto step = [&](const uint32_t* Ksh, const uint32_t* Vsh, int gg) {
        uint32_t k0[2], k1[2];
        {
            uint2 x0 = *(const uint2*)(Ksh + (gg*2)*64 + lane*2);
            uint2 x1 = *(const uint2*)(Ksh + (gg*2+1)*64 + lane*2);
            k0[0]=x0.x; k0[1]=x0.y; k1[0]=x1.x; k1[1]=x1.y;
        }
        uint32_t vh0[2], vh1[2];
        {
            uint2 x0 = *(const uint2*)(Vsh + (gg*2)*64 + lane*2);
            uint2 x1 = *(const uint2*)(Vsh + (gg*2+1)*64 + lane*2);
            vh0[0]=x0.x; vh0[1]=x0.y; vh1[0]=x1.x; vh1[1]=x1.y;
        }
#pragma unroll
        for (int t = 0; t < 2; ++t) {
            float d0[4] = {-SHIFT_,-SHIFT_,-SHIFT_,-SHIFT_};
            float d1[4] = {-SHIFT_,-SHIFT_,-SHIFT_,-SHIFT_};
            mma16816f(d0, qh[t], k0);
            mma16816f(d1, qh[t], k1);
            uint32_t p[4];
            p[0] = ex2h2(pack_f16(d0[0], d0[1]));
            p[1] = ex2h2(pack_f16(d0[2], d0[3]));
            p[2] = ex2h2(pack_f16(d1[0], d1[1]));
            p[3] = ex2h2(pack_f16(d1[2], d1[3]));
            mma16816f(lacc[t], p, ones);
            mma16816f(acc[t][0], p, vh0);
            mma16816f(acc[t][1], p, vh1);
        }
    };

    copy_chunk(0, 0);
    __syncthreads();

    for (int c = 0; c < 7; ++c) {
        const int buf = c & 1;
        if (c < 6) copy_chunk(buf ^ 1, c + 1);
        const uint32_t* Ksh = smK[buf];
        const uint32_t* Vsh = smV[buf];
        if (c < 6) {
#pragma unroll
            for (int gg = 0; gg < 16; ++gg) step(Ksh, Vsh, gg);
        } else {
#pragma unroll
            for (int gg = 0; gg < 4; ++gg) step(Ksh, Vsh, gg);
        }
        __syncthreads();
    }

    const int b = bh >> 3, h = bh & 7;
#pragma unroll
    for (int t = 0; t < 2; ++t) {
        float ia = 1.0f / lacc[t][0];
        float ib = 1.0f / lacc[t][2];
        int q = qt[t]*16 + g;
        float* oA = g_attn + ((long)b*N_ + q)*128 + h*16 + tig*2;
        float* oB = g_attn + ((long)b*N_ + q + 8)*128 + h*16 + tig*2;
        *(float2*)(oA)     = make_float2(acc[t][0][0]*ia, acc[t][0][1]*ia);
        *(float2*)(oA + 8) = make_float2(acc[t][1][0]*ia, acc[t][1][1]*ia);
        *(float2*)(oB)     = make_float2(acc[t][0][2]*ib, acc[t][0][3]*ib);
        *(float2*)(oB + 8) = make_float2(acc[t][1][2]*ib, acc[t][1][3]*ib);
    }
}

// ============ proj (HMMA) =======================================================
__global__ __launch_bounds__(256, 2) void k_proj(const float* __restrict__ pb,
                                                 float* __restrict__ out) {
    extern __shared__ char smraw[];
    uint32_t* Bsh = (uint32_t*)smraw;
    uint32_t* Bsl = Bsh + 4096;
    float*    Cs  = (float*)(Bsl + 4096);
    const int tid = threadIdx.x;
    const int w   = tid >> 5, lane = tid & 31;
    const int b  = blockIdx.y;
    const int P0 = blockIdx.x * 64;
    const float* gA = g_attn + (long)b*N_*128;

    for (int idx = tid; idx < 64*64; idx += 256) {
        int cp = idx >> 6, n = idx & 63;
        int c = 2*cp;
        long f = (long)c*N_ + P0 + n;
        float v0 = gA[f];
        float v1 = gA[f + N_];
        bfrag_store(Bsh, Bsl, c, n, v0, v1);
    }
    __syncthreads();

    float acc[8][4];
#pragma unroll
    for (int i = 0; i < 8; ++i)
#pragma unroll
        for (int j = 0; j < 4; ++j) acc[i][j] = 0.f;
    hmma_tile(g_Wp[0] + w*1024, g_Wp[1] + w*1024, Bsh, Bsl, acc, lane);
    dfrag_to_cs(Cs, acc, w, lane);
    __syncthreads();

    const int tr = tid >> 4, tc = tid & 15;
#pragma unroll
    for (int i = 0; i < 8; ++i) {
        int o = tr*8 + i;
        float bias = pb[o];
        long rowbase = ((long)b*128 + o)*N_ + P0 + tc*4;
#pragma unroll
        for (int j = 0; j < 2; ++j) {
            float v0 = Cs[o*65 + tc*4 + 2*j]     + bias;
            float v1 = Cs[o*65 + tc*4 + 2*j + 1] + bias;
            *(float2*)(out + rowbase + 2*j) = make_float2(v0, v1);
        }
    }
}

// ---------------- launch ----------------
extern "C" void kernel_launch(void* const* d_in, const int* in_sizes, int n_in,
                              void* d_out, int out_size) {
    const float* x    = (const float*)d_in[0];
    const float* q_w  = (const float*)d_in[1];
    const float* q_b  = (const float*)d_in[2];
    const float* k_w  = (const float*)d_in[3];
    const float* k_b  = (const float*)d_in[4];
    const float* v_w  = (const float*)d_in[5];
    const float* v_b  = (const float*)d_in[6];
    const float* sr_w = (const float*)d_in[7];
    const float* sr_b = (const float*)d_in[8];
    const float* bn_g = (const float*)d_in[9];
    const float* bn_b = (const float*)d_in[10];
    const float* bn_m = (const float*)d_in[11];
    const float* bn_v = (const float*)d_in[12];
    const float* p_w  = (const float*)d_in[13];
    const float* p_b  = (const float*)d_in[14];
    float* out = (float*)d_out;

    cudaFuncSetAttribute(k_stage1, cudaFuncAttributeMaxDynamicSharedMemorySize, GSM_);
    cudaFuncSetAttribute(k_kv,     cudaFuncAttributeMaxDynamicSharedMemorySize, KVS_);
    cudaFuncSetAttribute(k_proj,   cudaFuncAttributeMaxDynamicSharedMemorySize, GSM_);

    k_prep  <<<32, 256>>>(q_w, k_w, v_w, p_w, sr_w);
    k_stage1<<<400, 256, GSM_>>>(x, q_b);
    k_kv    <<<dim3(25, B_, 2), 256, KVS_>>>(k_b, v_b, sr_b, bn_g, bn_b, bn_m, bn_v);
    k_attn  <<<dim3(25, 16), 256>>>();
    k_proj  <<<dim3(100, B_), 256, GSM_>>>(p_b, out);
}

// round 12
// speedup vs baseline: 7.3463x; 1.0004x over previous
#include <cuda_runtime.h>
#include <cuda_bf16.h>
#include <cstdint>

#define B_    2
#define DIM_  128
#define N_    6400
#define NKV_  1600
#define SL2E_ 0.3606737602f   // 0.25 * log2(e)
#define SHIFT_ 16.0f

typedef unsigned long long u64;

// ---------------- helpers ----------------
// bf16 split (weights / GEMM stages): a -> low half, b -> high half
__device__ __forceinline__ void split_pack(float a, float b, uint32_t& hi, uint32_t& lo) {
    uint32_t h; asm("cvt.rn.bf16x2.f32 %0, %1, %2;" : "=r"(h) : "f"(b), "f"(a));
    float fa = __uint_as_float(h << 16);
    float fb = __uint_as_float(h & 0xFFFF0000u);
    float ra = a - fa, rb = b - fb;
    uint32_t l_; asm("cvt.rn.bf16x2.f32 %0, %1, %2;" : "=r"(l_) : "f"(rb), "f"(ra));
    hi = h; lo = l_;
}
// fp16 pack: a -> low half, b -> high half
__device__ __forceinline__ uint32_t pack_f16(float a, float b) {
    uint32_t h; asm("cvt.rn.f16x2.f32 %0, %1, %2;" : "=r"(h) : "f"(b), "f"(a));
    return h;
}
// packed 2-way fp16 exp2
__device__ __forceinline__ uint32_t ex2h2(uint32_t x) {
    uint32_t y; asm("ex2.approx.f16x2 %0, %1;" : "=r"(y) : "r"(x));
    return y;
}
// ---------------- HMMA m16n8k16 ----------------
__device__ __forceinline__ void mma16816(float d[4], const uint32_t a[4], const uint32_t b[2]) {
    asm("mma.sync.aligned.m16n8k16.row.col.f32.bf16.bf16.f32 "
        "{%0,%1,%2,%3}, {%4,%5,%6,%7}, {%8,%9}, {%0,%1,%2,%3};"
        : "+f"(d[0]), "+f"(d[1]), "+f"(d[2]), "+f"(d[3])
        : "r"(a[0]), "r"(a[1]), "r"(a[2]), "r"(a[3]), "r"(b[0]), "r"(b[1]));
}
__device__ __forceinline__ void mma16816f(float d[4], const uint32_t a[4], const uint32_t b[2]) {
    asm("mma.sync.aligned.m16n8k16.row.col.f32.f16.f16.f32 "
        "{%0,%1,%2,%3}, {%4,%5,%6,%7}, {%8,%9}, {%0,%1,%2,%3};"
        : "+f"(d[0]), "+f"(d[1]), "+f"(d[2]), "+f"(d[3])
        : "r"(a[0]), "r"(a[1]), "r"(a[2]), "r"(a[3]), "r"(b[0]), "r"(b[1]));
}

// ---------------- scratch ----------------
__device__ uint32_t g_Qh[16*400*32*4];          // fp16 single-term Q (pre-scaled)
__device__ uint32_t g_Kh[16*200*32*2];          // fp16 single-term K
__device__ uint32_t g_Vh[16*100*2*32*2];        // fp16 single-term V
__device__ float g_xkvp[4][B_*DIM_*NKV_];       // SR conv raw partials (split-K x4)
__device__ float g_attn[B_*N_*DIM_];
// weight fragments (bf16 2-term): [split][(mt*KT+kt)*32 + lane][4]
__device__ uint32_t g_Wq[2][8*8*32*4];
__device__ uint32_t g_Wk[2][8*8*32*4];
__device__ uint32_t g_Wv[2][8*8*32*4];
__device__ uint32_t g_Wp[2][8*8*32*4];
__device__ uint32_t g_Wsr[2][8*32*32*4];

// ============ weight prep ======================================================
__global__ __launch_bounds__(256) void k_prep(const float* __restrict__ qw,
                                              const float* __restrict__ kw,
                                              const float* __restrict__ vw,
                                              const float* __restrict__ pw,
                                              const float* __restrict__ srw) {
    int bx = blockIdx.x, tid = threadIdx.x;
    const float* src; uint32_t *dh, *dl; int K, b0;
    if (bx < 4)       { src = qw;  dh = g_Wq[0];  dl = g_Wq[1];  K = 128; b0 = bx; }
    else if (bx < 8)  { src = kw;  dh = g_Wk[0];  dl = g_Wk[1];  K = 128; b0 = bx - 4; }
    else if (bx < 12) { src = vw;  dh = g_Wv[0];  dl = g_Wv[1];  K = 128; b0 = bx - 8; }
    else if (bx < 16) { src = pw;  dh = g_Wp[0];  dl = g_Wp[1];  K = 128; b0 = bx - 12; }
    else              { src = srw; dh = g_Wsr[0]; dl = g_Wsr[1]; K = 512; b0 = bx - 16; }
    const int KT = K >> 4;
    const int KP = K >> 1;
    for (int p = b0*2048 + tid; p < (b0 + 1)*2048; p += 256) {
        int o = p / KP, cp = p % KP;
        int c = cp * 2;
        float v0 = src[o*K + c], v1 = src[o*K + c + 1];
        uint32_t h, l; split_pack(v0, v1, h, l);
        int mt = o >> 4, r = o & 15;
        int kt = c >> 4, kk = c & 15;
        int reg  = ((kk & 8) ? 2 : 0) + (r >> 3);
        int lane = (r & 7)*4 + ((kk & 7) >> 1);
        long idx = (((long)mt*KT + kt)*32 + lane)*4 + reg;
        dh[idx] = h; dl[idx] = l;
    }
}

// ---------------- common HMMA mainloop (bf16, GEMM stages) ----------------------
__device__ __forceinline__ void hmma_tile(const uint32_t* __restrict__ wh,
                                          const uint32_t* __restrict__ wl,
                                          const uint32_t* __restrict__ Bsh,
                                          const uint32_t* __restrict__ Bsl,
                                          float acc[8][4], int lane) {
#pragma unroll
    for (int kt = 0; kt < 8; ++kt) {
        uint32_t ah[4], al[4];
        const uint4 a4 = *(const uint4*)(wh + (kt*32 + lane)*4);
        const uint4 c4 = *(const uint4*)(wl + (kt*32 + lane)*4);
        ah[0]=a4.x; ah[1]=a4.y; ah[2]=a4.z; ah[3]=a4.w;
        al[0]=c4.x; al[1]=c4.y; al[2]=c4.z; al[3]=c4.w;
#pragma unroll
        for (int ng = 0; ng < 8; ++ng) {
            uint32_t bh[2], bl[2];
            uint2 u = *(const uint2*)(Bsh + ((kt*8 + ng)*32 + lane)*2);
            uint2 v = *(const uint2*)(Bsl + ((kt*8 + ng)*32 + lane)*2);
            bh[0]=u.x; bh[1]=u.y; bl[0]=v.x; bl[1]=v.y;
            mma16816(acc[ng], ah, bh);
            mma16816(acc[ng], al, bh);
            mma16816(acc[ng], ah, bl);
        }
    }
}
__device__ __forceinline__ void bfrag_store(uint32_t* Bsh, uint32_t* Bsl,
                                            int c, int n, float v0, float v1) {
    uint32_t h, l; split_pack(v0, v1, h, l);
    int kt = c >> 4, kk = c & 15;
    int ng = n >> 3;
    int reg  = (kk & 8) ? 1 : 0;
    int lane = (n & 7)*4 + ((kk & 7) >> 1);
    int idx = ((kt*8 + ng)*32 + lane)*2 + reg;
    Bsh[idx] = h; Bsl[idx] = l;
}
__device__ __forceinline__ void dfrag_to_cs(float* Cs, const float acc[8][4],
                                            int w, int lane) {
    int g = lane >> 2, tig = lane & 3;
#pragma unroll
    for (int ng = 0; ng < 8; ++ng) {
        float* r0 = Cs + (w*16 + g)*65 + ng*8 + tig*2;
        float* r1 = Cs + (w*16 + 8 + g)*65 + ng*8 + tig*2;
        r0[0] = acc[ng][0]; r0[1] = acc[ng][1];
        r1[0] = acc[ng][2]; r1[1] = acc[ng][3];
    }
}

#define GSM_ ((4096 + 4096)*4 + 128*65*4)    // 66048 B
#define KVS_ (GSM_ + 1024)

// ============ stage1: [0,200) Q-GEMM, [200,400) SR conv split-K x4 ==============
__global__ __launch_bounds__(256, 2) void k_stage1(const float* __restrict__ x,
                                                   const float* __restrict__ qb) {
    extern __shared__ char smraw[];
    uint32_t* Bsh = (uint32_t*)smraw;
    uint32_t* Bsl = Bsh + 4096;
    float*    Cs  = (float*)(Bsl + 4096);
    const int tid = threadIdx.x;
    const int w   = tid >> 5, lane = tid & 31;
    const int bx  = blockIdx.x;
    const int tr = tid >> 4, tc = tid & 15;

    float acc[8][4];
#pragma unroll
    for (int i = 0; i < 8; ++i)
#pragma unroll
        for (int j = 0; j < 4; ++j) acc[i][j] = 0.f;

    if (bx < 200) {
        const int b  = bx / 100;
        const int N0 = (bx % 100) * 64;
        for (int idx = tid; idx < 64*64; idx += 256) {
            int cp = idx >> 6, n = idx & 63;
            int c = 2*cp;
            float v0 = x[(b*128 + c)*N_ + N0 + n];
            float v1 = x[(b*128 + c + 1)*N_ + N0 + n];
            bfrag_store(Bsh, Bsl, c, n, v0, v1);
        }
        __syncthreads();
        hmma_tile(g_Wq[0] + w*1024, g_Wq[1] + w*1024, Bsh, Bsl, acc, lane);
        dfrag_to_cs(Cs, acc, w, lane);
        __syncthreads();
#pragma unroll
        for (int i = 0; i < 8; i += 2) {
            int o0 = tr*8 + i;
            float b0 = qb[o0], b1 = qb[o0+1];
            int dp = (o0 & 15) >> 1;
            int bh = b*8 + (o0 >> 4);
            int tig = dp & 3;
            int reglo = (dp < 4) ? 0 : 2;
#pragma unroll
            for (int j = 0; j < 2; ++j)
#pragma unroll
                for (int e = 0; e < 2; ++e) {
                    int nn = tc*4 + 2*j + e;
                    float va = Cs[o0*65 + nn] + b0;
                    float vb = Cs[(o0+1)*65 + nn] + b1;
                    int n  = N0 + nn;
                    int qt = n >> 4, r = n & 15;
                    int reg = reglo + (r >> 3);
                    int ln = (r & 7)*4 + tig;
                    long idx = (((long)bh*400 + qt)*32 + ln)*4 + reg;
                    g_Qh[idx] = pack_f16(va*SL2E_, vb*SL2E_);
                }
        }
    } else {
        const int sidx = bx - 200;                 // [0,200)
        const int z  = sidx / 50;                  // K-chunk 0..3
        const int r  = sidx % 50;
        const int b  = r / 25;
        const int P0 = (r % 25) * 64;
        for (int idx = tid; idx < 64*64; idx += 256) {
            int cp = idx >> 6, n = idx & 63;
            int cl = 2*cp;
            int kb = z*128 + cl;
            int c  = kb >> 2;
            int ii = (kb >> 1) & 1;
            int p  = P0 + n;
            int hp = p / 40, wp = p % 40;
            const float* base = x + ((b*128 + c)*80 + 2*hp + ii)*80 + 2*wp;
            bfrag_store(Bsh, Bsl, cl, n, base[0], base[1]);   // jj = 0,1
        }
        __syncthreads();
        hmma_tile(g_Wsr[0] + (w*32 + z*8)*128, g_Wsr[1] + (w*32 + z*8)*128,
                  Bsh, Bsl, acc, lane);
        dfrag_to_cs(Cs, acc, w, lane);
        __syncthreads();
        float* dst = g_xkvp[z];
#pragma unroll
        for (int i = 0; i < 8; ++i) {
            int o = tr*8 + i;
#pragma unroll
            for (int j = 0; j < 4; ++j) {
                int nn = tc*4 + j;
                dst[(b*128 + o)*NKV_ + P0 + nn] = Cs[o*65 + nn];
            }
        }
    }
}

// ============ K/V GEMM: sum SR partials + BN + ReLU fused in producer ===========
__global__ __launch_bounds__(256, 2) void k_kv(const float* __restrict__ kb,
                                               const float* __restrict__ vb,
                                               const float* __restrict__ srb,
                                               const float* __restrict__ bng,
                                               const float* __restrict__ bnb,
                                               const float* __restrict__ bnm,
                                               const float* __restrict__ bnv) {
    extern __shared__ char smraw[];
    float*    s_inv = (float*)smraw;               // [128]
    float*    s_sh  = s_inv + 128;                 // [128]
    uint32_t* Bsh = (uint32_t*)(s_sh + 128);
    uint32_t* Bsl = Bsh + 4096;
    float*    Cs  = (float*)(Bsl + 4096);
    const int tid = threadIdx.x;
    const int w   = tid >> 5, lane = tid & 31;
    const int b  = blockIdx.y;
    const int zz = blockIdx.z;
    const int M0 = blockIdx.x * 64;
    const float* bg = zz ? vb : kb;
    const uint32_t* wh = (zz ? g_Wv[0] : g_Wk[0]) + w*1024;
    const uint32_t* wl = (zz ? g_Wv[1] : g_Wk[1]) + w*1024;

    if (tid < 128) {
        float inv = bng[tid] * rsqrtf(bnv[tid] + 1e-5f);
        s_inv[tid] = inv;
        s_sh[tid]  = srb[tid]*inv + bnb[tid] - bnm[tid]*inv;
    }
    __syncthreads();
    for (int idx = tid; idx < 64*64; idx += 256) {
        int cp = idx >> 6, n = idx & 63;
        int c = 2*cp;
        long f0 = (long)(b*128 + c)*NKV_ + M0 + n;
        long f1 = f0 + NKV_;
        float r0 = g_xkvp[0][f0] + g_xkvp[1][f0] + g_xkvp[2][f0] + g_xkvp[3][f0];
        float r1 = g_xkvp[0][f1] + g_xkvp[1][f1] + g_xkvp[2][f1] + g_xkvp[3][f1];
        float v0 = fmaxf(r0 * s_inv[c]   + s_sh[c],   0.f);
        float v1 = fmaxf(r1 * s_inv[c+1] + s_sh[c+1], 0.f);
        bfrag_store(Bsh, Bsl, c, n, v0, v1);
    }
    __syncthreads();

    float acc[8][4];
#pragma unroll
    for (int i = 0; i < 8; ++i)
#pragma unroll
        for (int j = 0; j < 4; ++j) acc[i][j] = 0.f;
    hmma_tile(wh, wl, Bsh, Bsl, acc, lane);
    dfrag_to_cs(Cs, acc, w, lane);
    __syncthreads();

    const int tr = tid >> 4, tc = tid & 15;
    if (!zz) {
#pragma unroll
        for (int i = 0; i < 8; i += 2) {
            int o0 = tr*8 + i;
            float b0 = bg[o0], b1 = bg[o0+1];
            int dp = (o0 & 15) >> 1;
            int bh = b*8 + (o0 >> 4);
            int tig = dp & 3;
            int reg = (dp < 4) ? 0 : 1;
#pragma unroll
            for (int j = 0; j < 2; ++j)
#pragma unroll
                for (int e = 0; e < 2; ++e) {
                    int nn = tc*4 + 2*j + e;
                    float va = Cs[o0*65 + nn] + b0;
                    float vb = Cs[(o0+1)*65 + nn] + b1;
                    int m = M0 + nn;
                    int kt = m >> 3;
                    int ln = (m & 7)*4 + tig;
                    long idx = (((long)bh*200 + kt)*32 + ln)*2 + reg;
                    g_Kh[idx] = pack_f16(va, vb);
                }
        }
    } else {
#pragma unroll
        for (int i = 0; i < 8; ++i) {
            int o = tr*8 + i;
            float bias = bg[o];
            int d = o & 15;
            int bh = b*8 + (o >> 4);
            int dh = d >> 3;
#pragma unroll
            for (int j = 0; j < 2; ++j) {
                int nn = tc*4 + 2*j;
                float v0 = Cs[o*65 + nn] + bias;
                float v1 = Cs[o*65 + nn + 1] + bias;
                int m0 = M0 + nn;
                int ml = m0 & 15;
                int reg  = (ml < 8) ? 0 : 1;
                int tigv = (ml & 7) >> 1;
                int vt = m0 >> 4;
                int ln = (d & 7)*4 + tigv;
                long idx = ((((long)bh*100 + vt)*2 + dh)*32 + ln)*2 + reg;
                g_Vh[idx] = pack_f16(v0, v1);
            }
        }
    }
}

// ============ fp16 HMMA flash attention: 256-key chunks, unrolled ==============
__global__ __launch_bounds__(256, 3) void k_attn() {
    __shared__ uint32_t smK[2][2048];
    __shared__ uint32_t smV[2][2048];
    const int tid  = threadIdx.x;
    const int w    = tid >> 5;
    const int lane = tid & 31;
    const int g    = lane >> 2, tig = lane & 3;
    const int bh   = blockIdx.y;
    const int blk  = blockIdx.x;
    const uint32_t ones[2] = {0x3C003C00u, 0x3C003C00u};   // f16 1.0 x4

    uint32_t qh[2][4];
    int qt[2] = {blk*16 + w, blk*16 + 8 + w};
#pragma unroll
    for (int t = 0; t < 2; ++t) {
        const uint4 a = *(const uint4*)(g_Qh + (((long)bh*400 + qt[t])*32 + lane)*4);
        qh[t][0]=a.x; qh[t][1]=a.y; qh[t][2]=a.z; qh[t][3]=a.w;
    }
    float acc[2][2][4];
    float lacc[2][4];
#pragma unroll
    for (int t = 0; t < 2; ++t) {
#pragma unroll
        for (int d = 0; d < 2; ++d)
#pragma unroll
            for (int r = 0; r < 4; ++r) acc[t][d][r] = 0.f;
#pragma unroll
        for (int r = 0; r < 4; ++r) lacc[t][r] = 0.f;
    }

    auto copy_chunk = [&](int buf, int c) {
        const int nq = (c == 6) ? 128 : 512;
        const uint4* kh = (const uint4*)(g_Kh + ((long)bh*200 + c*32)*64);
        const uint4* vh = (const uint4*)(g_Vh + ((long)bh*100 + c*16)*128);
        uint4* dkh = (uint4*)smK[buf];
        uint4* dvh = (uint4*)smV[buf];
        for (int i = tid; i < nq; i += 256) {
            dkh[i] = kh[i]; dvh[i] = vh[i];
        }
    };

    auto step = [&](const uint32_t* Ksh, const uint32_t* Vsh, int gg) {
        uint32_t k0[2], k1[2];
        {
            uint2 x0 = *(const uint2*)(Ksh + (gg*2)*64 + lane*2);
            uint2 x1 = *(const uint2*)(Ksh + (gg*2+1)*64 + lane*2);
            k0[0]=x0.x; k0[1]=x0.y; k1[0]=x1.x; k1[1]=x1.y;
        }
        uint32_t vh0[2], vh1[2];
        {
            uint2 x0 = *(const uint2*)(Vsh + (gg*2)*64 + lane*2);
            uint2 x1 = *(const uint2*)(Vsh + (gg*2+1)*64 + lane*2);
            vh0[0]=x0.x; vh0[1]=x0.y; vh1[0]=x1.x; vh1[1]=x1.y;
        }
#pragma unroll
        for (int t = 0; t < 2; ++t) {
            float d0[4] = {-SHIFT_,-SHIFT_,-SHIFT_,-SHIFT_};
            float d1[4] = {-SHIFT_,-SHIFT_,-SHIFT_,-SHIFT_};
            mma16816f(d0, qh[t], k0);
            mma16816f(d1, qh[t], k1);
            uint32_t p[4];
            p[0] = ex2h2(pack_f16(d0[0], d0[1]));
            p[1] = ex2h2(pack_f16(d0[2], d0[3]));
            p[2] = ex2h2(pack_f16(d1[0], d1[1]));
            p[3] = ex2h2(pack_f16(d1[2], d1[3]));
            mma16816f(lacc[t], p, ones);
            mma16816f(acc[t][0], p, vh0);
            mma16816f(acc[t][1], p, vh1);
        }
    };

    copy_chunk(0, 0);
    __syncthreads();

    for (int c = 0; c < 7; ++c) {
        const int buf = c & 1;
        if (c < 6) copy_chunk(buf ^ 1, c + 1);
        const uint32_t* Ksh = smK[buf];
        const uint32_t* Vsh = smV[buf];
        if (c < 6) {
#pragma unroll
            for (int gg = 0; gg < 16; ++gg) step(Ksh, Vsh, gg);
        } else {
#pragma unroll
            for (int gg = 0; gg < 4; ++gg) step(Ksh, Vsh, gg);
        }
        __syncthreads();
    }

    const int b = bh >> 3, h = bh & 7;
#pragma unroll
    for (int t = 0; t < 2; ++t) {
        float ia = 1.0f / lacc[t][0];
        float ib = 1.0f / lacc[t][2];
        int q = qt[t]*16 + g;
        float* oA = g_attn + ((long)b*N_ + q)*128 + h*16 + tig*2;
        float* oB = g_attn + ((long)b*N_ + q + 8)*128 + h*16 + tig*2;
        *(float2*)(oA)     = make_float2(acc[t][0][0]*ia, acc[t][0][1]*ia);
        *(float2*)(oA + 8) = make_float2(acc[t][1][0]*ia, acc[t][1][1]*ia);
        *(float2*)(oB)     = make_float2(acc[t][0][2]*ib, acc[t][0][3]*ib);
        *(float2*)(oB + 8) = make_float2(acc[t][1][2]*ib, acc[t][1][3]*ib);
    }
}

// ============ proj (HMMA) =======================================================
__global__ __launch_bounds__(256, 2) void k_proj(const float* __restrict__ pb,
                                                 float* __restrict__ out) {
    extern __shared__ char smraw[];
    uint32_t* Bsh = (uint32_t*)smraw;
    uint32_t* Bsl = Bsh + 4096;
    float*    Cs  = (float*)(Bsl + 4096);
    const int tid = threadIdx.x;
    const int w   = tid >> 5, lane = tid & 31;
    const int b  = blockIdx.y;
    const int P0 = blockIdx.x * 64;
    const float* gA = g_attn + (long)b*N_*128;

    for (int idx = tid; idx < 64*64; idx += 256) {
        int cp = idx >> 6, n = idx & 63;
        int c = 2*cp;
        long f = (long)c*N_ + P0 + n;
        float v0 = gA[f];
        float v1 = gA[f + N_];
        bfrag_store(Bsh, Bsl, c, n, v0, v1);
    }
    __syncthreads();

    float acc[8][4];
#pragma unroll
    for (int i = 0; i < 8; ++i)
#pragma unroll
        for (int j = 0; j < 4; ++j) acc[i][j] = 0.f;
    hmma_tile(g_Wp[0] + w*1024, g_Wp[1] + w*1024, Bsh, Bsl, acc, lane);
    dfrag_to_cs(Cs, acc, w, lane);
    __syncthreads();

    const int tr = tid >> 4, tc = tid & 15;
#pragma unroll
    for (int i = 0; i < 8; ++i) {
        int o = tr*8 + i;
        float bias = pb[o];
        long rowbase = ((long)b*128 + o)*N_ + P0 + tc*4;
#pragma unroll
        for (int j = 0; j < 2; ++j) {
            float v0 = Cs[o*65 + tc*4 + 2*j]     + bias;
            float v1 = Cs[o*65 + tc*4 + 2*j + 1] + bias;
            *(float2*)(out + rowbase + 2*j) = make_float2(v0, v1);
        }
    }
}

// ---------------- launch ----------------
extern "C" void kernel_launch(void* const* d_in, const int* in_sizes, int n_in,
                              void* d_out, int out_size) {
    const float* x    = (const float*)d_in[0];
    const float* q_w  = (const float*)d_in[1];
    const float* q_b  = (const float*)d_in[2];
    const float* k_w  = (const float*)d_in[3];
    const float* k_b  = (const float*)d_in[4];
    const float* v_w  = (const float*)d_in[5];
    const float* v_b  = (const float*)d_in[6];
    const float* sr_w = (const float*)d_in[7];
    const float* sr_b = (const float*)d_in[8];
    const float* bn_g = (const float*)d_in[9];
    const float* bn_b = (const float*)d_in[10];
    const float* bn_m = (const float*)d_in[11];
    const float* bn_v = (const float*)d_in[12];
    const float* p_w  = (const float*)d_in[13];
    const float* p_b  = (const float*)d_in[14];
    float* out = (float*)d_out;

    cudaFuncSetAttribute(k_stage1, cudaFuncAttributeMaxDynamicSharedMemorySize, GSM_);
    cudaFuncSetAttribute(k_kv,     cudaFuncAttributeMaxDynamicSharedMemorySize, KVS_);
    cudaFuncSetAttribute(k_proj,   cudaFuncAttributeMaxDynamicSharedMemorySize, GSM_);

    k_prep  <<<32, 256>>>(q_w, k_w, v_w, p_w, sr_w);
    k_stage1<<<400, 256, GSM_>>>(x, q_b);
    k_kv    <<<dim3(25, B_, 2), 256, KVS_>>>(k_b, v_b, sr_b, bn_g, bn_b, bn_m, bn_v);
    k_attn  <<<dim3(25, 16), 256>>>();
    k_proj  <<<dim3(100, B_), 256, GSM_>>>(p_b, out);
}